// round 1
// baseline (speedup 1.0000x reference)
#include <cuda_runtime.h>
#include <math.h>

// Problem constants
#define BB 2
#define TT 2048
#define DD 2048
#define HH 16
#define HD 128
#define MROWS (BB*TT)     // 4096
#define NBATCH (BB*HH)    // 32

// Scratch (device globals: allocation-free rule)
__device__ float g_q[(size_t)MROWS*DD];
__device__ float g_k[(size_t)MROWS*DD];
__device__ float g_v[(size_t)MROWS*DD];
__device__ float g_attn[(size_t)MROWS*DD];
__device__ float g_out[(size_t)MROWS*DD];
__device__ float g_scores[(size_t)NBATCH*TT*TT];   // 512 MB

// ---------------------------------------------------------------------------
// Generic C = A[M,K] @ W[K,N] + bias, optional gated epilogue:
//   if mulsrc != null:  C = mulsrc * sigmoid(A@W + bias)
// Tiling: 128x128x16, 256 threads, 8x8 per-thread microtile. All dims assumed
// multiples of 128/16 (true for this problem).
// ---------------------------------------------------------------------------
__global__ __launch_bounds__(256) void sgemm_nn_bias(
    const float* __restrict__ A, const float* __restrict__ W,
    const float* __restrict__ bias, const float* __restrict__ mulsrc,
    float* __restrict__ C, int M, int N, int K)
{
    __shared__ float As[16][128];
    __shared__ float Bs[16][128];
    const int tid = threadIdx.x;
    const int m0 = blockIdx.y * 128;
    const int n0 = blockIdx.x * 128;
    const int tx = tid & 15, ty = tid >> 4;
    const int ar = tid >> 2;          // 0..63
    const int ak = (tid & 3) * 4;     // 0,4,8,12
    const int br = tid >> 5;          // 0..7
    const int bc = (tid & 31) * 4;    // 0..124

    float acc[8][8];
    #pragma unroll
    for (int i = 0; i < 8; i++)
        #pragma unroll
        for (int j = 0; j < 8; j++) acc[i][j] = 0.f;

    for (int k0 = 0; k0 < K; k0 += 16) {
        #pragma unroll
        for (int rr = 0; rr < 128; rr += 64) {
            float4 va = *reinterpret_cast<const float4*>(&A[(size_t)(m0+ar+rr)*K + k0 + ak]);
            As[ak+0][ar+rr] = va.x; As[ak+1][ar+rr] = va.y;
            As[ak+2][ar+rr] = va.z; As[ak+3][ar+rr] = va.w;
        }
        #pragma unroll
        for (int rr = 0; rr < 16; rr += 8) {
            float4 vb = *reinterpret_cast<const float4*>(&W[(size_t)(k0+br+rr)*N + n0 + bc]);
            *reinterpret_cast<float4*>(&Bs[br+rr][bc]) = vb;
        }
        __syncthreads();
        #pragma unroll
        for (int kk = 0; kk < 16; kk++) {
            float a[8], b[8];
            *reinterpret_cast<float4*>(a)   = *reinterpret_cast<const float4*>(&As[kk][ty*8]);
            *reinterpret_cast<float4*>(a+4) = *reinterpret_cast<const float4*>(&As[kk][ty*8+4]);
            *reinterpret_cast<float4*>(b)   = *reinterpret_cast<const float4*>(&Bs[kk][tx*8]);
            *reinterpret_cast<float4*>(b+4) = *reinterpret_cast<const float4*>(&Bs[kk][tx*8+4]);
            #pragma unroll
            for (int i = 0; i < 8; i++)
                #pragma unroll
                for (int j = 0; j < 8; j++) acc[i][j] += a[i]*b[j];
        }
        __syncthreads();
    }

    #pragma unroll
    for (int i = 0; i < 8; i++) {
        const int r = m0 + ty*8 + i;
        #pragma unroll
        for (int j = 0; j < 8; j++) {
            const int c = n0 + tx*8 + j;
            float v = acc[i][j] + bias[c];
            if (mulsrc) {
                float s = 1.0f / (1.0f + __expf(-v));
                v = mulsrc[(size_t)r*N + c] * s;
            }
            C[(size_t)r*N + c] = v;
        }
    }
}

// ---------------------------------------------------------------------------
// Batched QK^T: scores[z, i, j] = scale * sum_d q[b,i,h,d]*k[b,j,h,d], z=b*H+h
// ---------------------------------------------------------------------------
__global__ __launch_bounds__(256) void sgemm_qk()
{
    __shared__ float As[16][128];
    __shared__ float Bs[16][128];
    const int tid = threadIdx.x;
    const int z = blockIdx.z;
    const int b = z >> 4, h = z & 15;
    const float* A  = g_q + (size_t)b*TT*DD + h*HD;
    const float* Bm = g_k + (size_t)b*TT*DD + h*HD;
    float* C = g_scores + (size_t)z*TT*TT;
    const int m0 = blockIdx.y * 128, n0 = blockIdx.x * 128;
    const int tx = tid & 15, ty = tid >> 4;
    const int ar = tid >> 2, ak = (tid & 3) * 4;

    float acc[8][8];
    #pragma unroll
    for (int i = 0; i < 8; i++)
        #pragma unroll
        for (int j = 0; j < 8; j++) acc[i][j] = 0.f;

    for (int k0 = 0; k0 < HD; k0 += 16) {
        #pragma unroll
        for (int rr = 0; rr < 128; rr += 64) {
            float4 va = *reinterpret_cast<const float4*>(&A [(size_t)(m0+ar+rr)*DD + k0 + ak]);
            As[ak+0][ar+rr] = va.x; As[ak+1][ar+rr] = va.y;
            As[ak+2][ar+rr] = va.z; As[ak+3][ar+rr] = va.w;
            float4 vb = *reinterpret_cast<const float4*>(&Bm[(size_t)(n0+ar+rr)*DD + k0 + ak]);
            Bs[ak+0][ar+rr] = vb.x; Bs[ak+1][ar+rr] = vb.y;
            Bs[ak+2][ar+rr] = vb.z; Bs[ak+3][ar+rr] = vb.w;
        }
        __syncthreads();
        #pragma unroll
        for (int kk = 0; kk < 16; kk++) {
            float a[8], bf[8];
            *reinterpret_cast<float4*>(a)    = *reinterpret_cast<const float4*>(&As[kk][ty*8]);
            *reinterpret_cast<float4*>(a+4)  = *reinterpret_cast<const float4*>(&As[kk][ty*8+4]);
            *reinterpret_cast<float4*>(bf)   = *reinterpret_cast<const float4*>(&Bs[kk][tx*8]);
            *reinterpret_cast<float4*>(bf+4) = *reinterpret_cast<const float4*>(&Bs[kk][tx*8+4]);
            #pragma unroll
            for (int i = 0; i < 8; i++)
                #pragma unroll
                for (int j = 0; j < 8; j++) acc[i][j] += a[i]*bf[j];
        }
        __syncthreads();
    }
    const float scale = 0.08838834764831845f;  // 128^-0.5
    #pragma unroll
    for (int i = 0; i < 8; i++)
        #pragma unroll
        for (int j = 0; j < 8; j++)
            C[(size_t)(m0+ty*8+i)*TT + n0+tx*8+j] = acc[i][j] * scale;
}

// ---------------------------------------------------------------------------
// Batched PV: attn[b,i,h,:] = sum_j P[z,i,j] * v[b,j,h,:]
// ---------------------------------------------------------------------------
__global__ __launch_bounds__(256) void sgemm_pv()
{
    __shared__ float As[16][128];
    __shared__ float Bs[16][128];
    const int tid = threadIdx.x;
    const int z = blockIdx.z;
    const int b = z >> 4, h = z & 15;
    const float* A  = g_scores + (size_t)z*TT*TT;
    const float* Bm = g_v    + (size_t)b*TT*DD + h*HD;
    float* C        = g_attn + (size_t)b*TT*DD + h*HD;
    const int m0 = blockIdx.y * 128;
    const int tx = tid & 15, ty = tid >> 4;
    const int ar = tid >> 2, ak = (tid & 3) * 4;
    const int br = tid >> 5, bc = (tid & 31) * 4;

    float acc[8][8];
    #pragma unroll
    for (int i = 0; i < 8; i++)
        #pragma unroll
        for (int j = 0; j < 8; j++) acc[i][j] = 0.f;

    for (int k0 = 0; k0 < TT; k0 += 16) {
        #pragma unroll
        for (int rr = 0; rr < 128; rr += 64) {
            float4 va = *reinterpret_cast<const float4*>(&A[(size_t)(m0+ar+rr)*TT + k0 + ak]);
            As[ak+0][ar+rr] = va.x; As[ak+1][ar+rr] = va.y;
            As[ak+2][ar+rr] = va.z; As[ak+3][ar+rr] = va.w;
        }
        #pragma unroll
        for (int rr = 0; rr < 16; rr += 8) {
            float4 vb = *reinterpret_cast<const float4*>(&Bm[(size_t)(k0+br+rr)*DD + bc]);
            *reinterpret_cast<float4*>(&Bs[br+rr][bc]) = vb;
        }
        __syncthreads();
        #pragma unroll
        for (int kk = 0; kk < 16; kk++) {
            float a[8], bf[8];
            *reinterpret_cast<float4*>(a)    = *reinterpret_cast<const float4*>(&As[kk][ty*8]);
            *reinterpret_cast<float4*>(a+4)  = *reinterpret_cast<const float4*>(&As[kk][ty*8+4]);
            *reinterpret_cast<float4*>(bf)   = *reinterpret_cast<const float4*>(&Bs[kk][tx*8]);
            *reinterpret_cast<float4*>(bf+4) = *reinterpret_cast<const float4*>(&Bs[kk][tx*8+4]);
            #pragma unroll
            for (int i = 0; i < 8; i++)
                #pragma unroll
                for (int j = 0; j < 8; j++) acc[i][j] += a[i]*bf[j];
        }
        __syncthreads();
    }
    #pragma unroll
    for (int i = 0; i < 8; i++)
        #pragma unroll
        for (int j = 0; j < 8; j++)
            C[(size_t)(m0+ty*8+i)*DD + tx*8+j] = acc[i][j];
}

// ---------------------------------------------------------------------------
// Fused RMSNorm (over full D=2048) + per-head rotary. In-place on buf.
// One block per row (b,t). cos/sin are [T, 64].
// ---------------------------------------------------------------------------
__global__ __launch_bounds__(256) void rmsnorm_rope(
    float* __restrict__ buf, const float* __restrict__ g,
    const float* __restrict__ cosp, const float* __restrict__ sinp)
{
    __shared__ float s[DD];
    __shared__ float red[8];
    const int row = blockIdx.x;
    const int t = row & (TT - 1);
    float* p = buf + (size_t)row * DD;
    const int tid = threadIdx.x;

    float ss = 0.f;
    for (int c = tid; c < DD; c += 256) { float x = p[c]; s[c] = x; ss += x*x; }
    #pragma unroll
    for (int o = 16; o > 0; o >>= 1) ss += __shfl_xor_sync(0xffffffffu, ss, o);
    if ((tid & 31) == 0) red[tid >> 5] = ss;
    __syncthreads();
    float tot = red[0]+red[1]+red[2]+red[3]+red[4]+red[5]+red[6]+red[7];
    const float inv = rsqrtf(tot * (1.0f / (float)DD) + 1e-6f);

    for (int c = tid; c < DD; c += 256) {
        const int pidx = c & 127;
        const int base = c - pidx;
        float o;
        if (pidx < 64) {
            float x1 = s[c] * inv * g[c];
            float x2 = s[base + 64 + pidx] * inv * g[base + 64 + pidx];
            o = x1 * cosp[t*64 + pidx] - sinp[t*64 + pidx] * x2;
        } else {
            const int pp = pidx - 64;
            float x2 = s[c] * inv * g[c];
            float x1 = s[base + pp] * inv * g[base + pp];
            o = x2 * cosp[t*64 + pp] + sinp[t*64 + pp] * x1;
        }
        p[c] = o;
    }
}

// ---------------------------------------------------------------------------
// Row softmax over g_scores rows (NBATCH*T rows of length T). In-place.
// Row fits in registers (8 floats/thread).
// ---------------------------------------------------------------------------
__global__ __launch_bounds__(256) void softmax_rows()
{
    float* p = g_scores + (size_t)blockIdx.x * TT;
    const int tid = threadIdx.x;
    __shared__ float red[8];

    float v[8];
    float mx = -1e30f;
    #pragma unroll
    for (int i = 0; i < 8; i++) { v[i] = p[tid + i*256]; mx = fmaxf(mx, v[i]); }
    #pragma unroll
    for (int o = 16; o > 0; o >>= 1) mx = fmaxf(mx, __shfl_xor_sync(0xffffffffu, mx, o));
    if ((tid & 31) == 0) red[tid >> 5] = mx;
    __syncthreads();
    mx = fmaxf(fmaxf(fmaxf(red[0],red[1]),fmaxf(red[2],red[3])),
               fmaxf(fmaxf(red[4],red[5]),fmaxf(red[6],red[7])));
    __syncthreads();

    float sum = 0.f;
    #pragma unroll
    for (int i = 0; i < 8; i++) { v[i] = __expf(v[i] - mx); sum += v[i]; }
    #pragma unroll
    for (int o = 16; o > 0; o >>= 1) sum += __shfl_xor_sync(0xffffffffu, sum, o);
    if ((tid & 31) == 0) red[tid >> 5] = sum;
    __syncthreads();
    float tot = red[0]+red[1]+red[2]+red[3]+red[4]+red[5]+red[6]+red[7];
    const float r = 1.0f / tot;
    #pragma unroll
    for (int i = 0; i < 8; i++) p[tid + i*256] = v[i] * r;
}

// ---------------------------------------------------------------------------
extern "C" void kernel_launch(void* const* d_in, const int* in_sizes, int n_in,
                              void* d_out, int out_size)
{
    const float* x    = (const float*)d_in[0];
    const float* cosp = (const float*)d_in[1];
    const float* sinp = (const float*)d_in[2];
    const float* wq = (const float*)d_in[3];  const float* bq = (const float*)d_in[4];
    const float* wk = (const float*)d_in[5];  const float* bk = (const float*)d_in[6];
    const float* wv = (const float*)d_in[7];  const float* bv = (const float*)d_in[8];
    const float* gq = (const float*)d_in[9];  const float* gk = (const float*)d_in[10];
    const float* wo = (const float*)d_in[11]; const float* bo = (const float*)d_in[12];
    const float* wg = (const float*)d_in[13]; const float* bg = (const float*)d_in[14];
    float* out = (float*)d_out;

    float *q, *k, *v, *attn, *o;
    cudaGetSymbolAddress((void**)&q,    g_q);
    cudaGetSymbolAddress((void**)&k,    g_k);
    cudaGetSymbolAddress((void**)&v,    g_v);
    cudaGetSymbolAddress((void**)&attn, g_attn);
    cudaGetSymbolAddress((void**)&o,    g_out);

    dim3 blk(256);
    dim3 gproj(DD/128, MROWS/128);   // (16, 32)

    sgemm_nn_bias<<<gproj, blk>>>(x, wq, bq, nullptr, q, MROWS, DD, DD);
    sgemm_nn_bias<<<gproj, blk>>>(x, wk, bk, nullptr, k, MROWS, DD, DD);
    sgemm_nn_bias<<<gproj, blk>>>(x, wv, bv, nullptr, v, MROWS, DD, DD);

    rmsnorm_rope<<<MROWS, blk>>>(q, gq, cosp, sinp);
    rmsnorm_rope<<<MROWS, blk>>>(k, gk, cosp, sinp);

    sgemm_qk<<<dim3(TT/128, TT/128, NBATCH), blk>>>();
    softmax_rows<<<NBATCH*TT, blk>>>();
    sgemm_pv<<<dim3(1, TT/128, NBATCH), blk>>>();

    sgemm_nn_bias<<<gproj, blk>>>(attn, wo, bo, nullptr, o, MROWS, DD, DD);
    sgemm_nn_bias<<<gproj, blk>>>(o, wg, bg, o, out, MROWS, DD, DD);
}

// round 3
// speedup vs baseline: 2.8584x; 2.8584x over previous
#include <cuda_runtime.h>
#include <cuda_bf16.h>
#include <cstdint>
#include <math.h>

#define BB 2
#define TT 2048
#define DD 2048
#define HH 16
#define HD 128
#define MROWS (BB*TT)     // 4096
#define NB (BB*HH)        // 32

typedef __nv_bfloat16 bf16;

// ---------------- scratch (device globals; allocation-free rule) ----------
__device__ bf16  g_xh[(size_t)MROWS*DD], g_xl[(size_t)MROWS*DD];
__device__ bf16  g_wth[5ULL*DD*DD],      g_wtl[5ULL*DD*DD];      // transposed weights
__device__ float g_tmp[(size_t)MROWS*DD];                        // fp32 proj out
__device__ bf16  g_qh[(size_t)MROWS*DD], g_ql[(size_t)MROWS*DD];
__device__ bf16  g_kh[(size_t)MROWS*DD], g_kl[(size_t)MROWS*DD];
__device__ bf16  g_vth[(size_t)NB*HD*TT], g_vtl[(size_t)NB*HD*TT]; // v^T [b,h,d,t]
__device__ float g_sc[(size_t)NB*TT*TT];                         // scores fp32 512MB
__device__ bf16  g_ph[(size_t)NB*TT*TT], g_pl[(size_t)NB*TT*TT]; // probs hi/lo
__device__ bf16  g_ah[(size_t)MROWS*DD], g_al[(size_t)MROWS*DD]; // attn hi/lo
__device__ float g_of[(size_t)MROWS*DD];
__device__ bf16  g_oh[(size_t)MROWS*DD], g_ol[(size_t)MROWS*DD];

// ---------------- PTX helpers (all plain sm_80+ PTX, no arch-variant) -----
__device__ __forceinline__ uint32_t smem_u32(const void* p) {
    uint32_t a;
    asm("{ .reg .u64 t; cvta.to.shared.u64 t, %1; cvt.u32.u64 %0, t; }" : "=r"(a) : "l"(p));
    return a;
}
__device__ __forceinline__ void cpa16(uint32_t s, const void* g) {
    asm volatile("cp.async.cg.shared.global [%0], [%1], 16;" :: "r"(s), "l"(g));
}
#define CP_COMMIT()  asm volatile("cp.async.commit_group;" ::: "memory")

__device__ __forceinline__ void ldsm4(uint32_t* r, uint32_t a) {
    asm volatile("ldmatrix.sync.aligned.m8n8.x4.shared.b16 {%0,%1,%2,%3}, [%4];"
        : "=r"(r[0]), "=r"(r[1]), "=r"(r[2]), "=r"(r[3]) : "r"(a));
}
__device__ __forceinline__ void mma16816(float* c, const uint32_t* a, const uint32_t* b) {
    asm volatile("mma.sync.aligned.m16n8k16.row.col.f32.bf16.bf16.f32 "
        "{%0,%1,%2,%3}, {%4,%5,%6,%7}, {%8,%9}, {%0,%1,%2,%3};"
        : "+f"(c[0]), "+f"(c[1]), "+f"(c[2]), "+f"(c[3])
        : "r"(a[0]), "r"(a[1]), "r"(a[2]), "r"(a[3]), "r"(b[0]), "r"(b[1]));
}

__device__ __forceinline__ uint32_t sw_addr(uint32_t base, int row, int ch) {
    uint32_t off = (uint32_t)(row*128 + ch*16);
    return base + (off ^ ((off >> 3) & 0x70u));
}

// ---------------- stage loader (4 x 16KB sub-tiles, SW128, BK=64) ---------
__device__ __forceinline__ void ld_stage(uint32_t sb,
    const bf16* Ah, const bf16* Al, long lda,
    const bf16* Bh, const bf16* Bl, long ldb,
    int m0, int n0, int k0, int tid)
{
    #pragma unroll
    for (int t = 0; t < 4; t++) {
        int ch = tid + t*256;           // 0..1023
        int r  = ch >> 3;
        int kc = ch & 7;
        uint32_t off = (uint32_t)(r*128 + kc*16);
        uint32_t sw  = off ^ ((off >> 3) & 0x70u);
        size_t ga = (size_t)(m0 + r)*lda + k0 + kc*8;
        cpa16(sb         + sw, Ah + ga);
        cpa16(sb + 16384 + sw, Al + ga);
        size_t gb = (size_t)(n0 + r)*ldb + k0 + kc*8;
        cpa16(sb + 32768 + sw, Bh + gb);
        cpa16(sb + 49152 + sw, Bl + gb);
    }
    CP_COMMIT();
}

// ---------------- GEMM: C = (Ah+Al)@(Bh+Bl)^T (3-term split-bf16) ---------
// epi: 0 = fp32 (+bias), 1 = split bf16, 2 = fp32 + split, 3 = gate
__global__ __launch_bounds__(256, 1) void gemm_t3(
    const bf16* __restrict__ Ah, const bf16* __restrict__ Al, long lda, long azb, long azh,
    const bf16* __restrict__ Bh, const bf16* __restrict__ Bl, long ldb, long bzb, long bzh,
    const float* __restrict__ bias, const float* __restrict__ mul,
    float* __restrict__ Cf, bf16* __restrict__ Ch, bf16* __restrict__ Cl,
    long ldc, long czb, long czh, int K, int epi)
{
    extern __shared__ __align__(16) uint8_t dyns[];
    const int tid = threadIdx.x;
    uint32_t raw = smem_u32(dyns);
    uint32_t sb0 = (raw + 1023u) & ~1023u;
    uint32_t pad = sb0 - raw;

    const int z  = blockIdx.z;
    const int zb = z >> 4, zh = z & 15;
    const bf16* pAh = Ah + (size_t)zb*azb + (size_t)zh*azh;
    const bf16* pAl = Al + (size_t)zb*azb + (size_t)zh*azh;
    const bf16* pBh = Bh + (size_t)zb*bzb + (size_t)zh*bzh;
    const bf16* pBl = Bl + (size_t)zb*bzb + (size_t)zh*bzh;
    const size_t czoff = (size_t)zb*czb + (size_t)zh*czh;
    const int m0 = blockIdx.y * 128, n0 = blockIdx.x * 128;

    const int lane = tid & 31, wid = tid >> 5;
    const int wm = wid >> 1, wn = wid & 1;          // 4 x 2 warp grid
    const int g8 = lane & 7, q = lane >> 3;

    float c[2][8][4];
    #pragma unroll
    for (int i = 0; i < 2; i++)
        #pragma unroll
        for (int j = 0; j < 8; j++)
            #pragma unroll
            for (int e = 0; e < 4; e++) c[i][j][e] = 0.f;

    const int nch = K >> 6;
    ld_stage(sb0, pAh, pAl, lda, pBh, pBl, ldb, m0, n0, 0, tid);

    for (int cc = 0; cc < nch; cc++) {
        const int s = cc & 1;
        const uint32_t sbs = sb0 + s*65536;
        if (cc + 1 < nch) {
            ld_stage(sb0 + (s^1)*65536, pAh, pAl, lda, pBh, pBl, ldb, m0, n0, (cc+1)*64, tid);
            asm volatile("cp.async.wait_group 1;" ::: "memory");
        } else {
            asm volatile("cp.async.wait_group 0;" ::: "memory");
        }
        __syncthreads();

        const uint32_t sAh = sbs, sBh = sbs + 32768;
        #pragma unroll
        for (int k16 = 0; k16 < 4; k16++) {
            uint32_t ah[2][4], al[2][4], bh[8][2], bl[8][2];
            #pragma unroll
            for (int mi = 0; mi < 2; mi++) {
                int row = wm*32 + mi*16 + g8 + ((q & 1) << 3);
                int ch  = k16*2 + (q >> 1);
                uint32_t a = sw_addr(sAh, row, ch);
                ldsm4(ah[mi], a);
                ldsm4(al[mi], a + 16384);
            }
            #pragma unroll
            for (int nj = 0; nj < 4; nj++) {
                int row = wn*64 + nj*16 + g8 + ((q >> 1) << 3);
                int ch  = k16*2 + (q & 1);
                uint32_t b = sw_addr(sBh, row, ch);
                uint32_t r[4];
                ldsm4(r, b);
                bh[2*nj][0] = r[0]; bh[2*nj][1] = r[1];
                bh[2*nj+1][0] = r[2]; bh[2*nj+1][1] = r[3];
                ldsm4(r, b + 16384);
                bl[2*nj][0] = r[0]; bl[2*nj][1] = r[1];
                bl[2*nj+1][0] = r[2]; bl[2*nj+1][1] = r[3];
            }
            #pragma unroll
            for (int mi = 0; mi < 2; mi++)
                #pragma unroll
                for (int ni = 0; ni < 8; ni++) {
                    mma16816(c[mi][ni], ah[mi], bh[ni]);
                    mma16816(c[mi][ni], al[mi], bh[ni]);
                    mma16816(c[mi][ni], ah[mi], bl[ni]);
                }
        }
        __syncthreads();
    }

    // ---- epilogue: frags -> padded fp32 smem -> coalesced gmem ----
    float* smemf = (float*)(dyns + pad);   // [128][132]
    {
        const int gid = lane >> 2, tig = lane & 3;
        #pragma unroll
        for (int mi = 0; mi < 2; mi++)
            #pragma unroll
            for (int ni = 0; ni < 8; ni++) {
                int r0 = wm*32 + mi*16 + gid;
                int col = wn*64 + ni*8 + tig*2;
                *(float2*)&smemf[r0*132 + col]     = make_float2(c[mi][ni][0], c[mi][ni][1]);
                *(float2*)&smemf[(r0+8)*132 + col] = make_float2(c[mi][ni][2], c[mi][ni][3]);
            }
    }
    __syncthreads();

    for (int v = tid; v < 4096; v += 256) {
        const int row = v >> 5, c4 = (v & 31) << 2;
        float4 val = *(const float4*)&smemf[row*132 + c4];
        const int gc = n0 + c4;
        const size_t go = czoff + (size_t)(m0 + row)*ldc + gc;
        if (bias) {
            val.x += bias[gc]; val.y += bias[gc+1]; val.z += bias[gc+2]; val.w += bias[gc+3];
        }
        if (epi == 0) {
            *(float4*)&Cf[go] = val;
        } else if (epi <= 2) {
            if (epi == 2) *(float4*)&Cf[go] = val;
            bf16 h0 = __float2bfloat16(val.x), h1 = __float2bfloat16(val.y);
            bf16 h2 = __float2bfloat16(val.z), h3 = __float2bfloat16(val.w);
            bf16 l0 = __float2bfloat16(val.x - __bfloat162float(h0));
            bf16 l1 = __float2bfloat16(val.y - __bfloat162float(h1));
            bf16 l2 = __float2bfloat16(val.z - __bfloat162float(h2));
            bf16 l3 = __float2bfloat16(val.w - __bfloat162float(h3));
            *(__nv_bfloat162*)&Ch[go]   = __nv_bfloat162(h0, h1);
            *(__nv_bfloat162*)&Ch[go+2] = __nv_bfloat162(h2, h3);
            *(__nv_bfloat162*)&Cl[go]   = __nv_bfloat162(l0, l1);
            *(__nv_bfloat162*)&Cl[go+2] = __nv_bfloat162(l2, l3);
        } else {  // gate
            const float4 m = *(const float4*)&mul[go];
            float4 o;
            o.x = m.x / (1.0f + __expf(-val.x));
            o.y = m.y / (1.0f + __expf(-val.y));
            o.z = m.z / (1.0f + __expf(-val.z));
            o.w = m.w / (1.0f + __expf(-val.w));
            *(float4*)&Cf[go] = o;
        }
    }
}

// ---------------- elementwise split: fp32 -> bf16 hi/lo -------------------
__global__ __launch_bounds__(256) void split4(const float* __restrict__ in,
    bf16* __restrict__ oh, bf16* __restrict__ ol, int n4)
{
    int i = blockIdx.x*256 + threadIdx.x;
    if (i >= n4) return;
    float4 v = ((const float4*)in)[i];
    bf16 h0 = __float2bfloat16(v.x), h1 = __float2bfloat16(v.y);
    bf16 h2 = __float2bfloat16(v.z), h3 = __float2bfloat16(v.w);
    bf16 l0 = __float2bfloat16(v.x - __bfloat162float(h0));
    bf16 l1 = __float2bfloat16(v.y - __bfloat162float(h1));
    bf16 l2 = __float2bfloat16(v.z - __bfloat162float(h2));
    bf16 l3 = __float2bfloat16(v.w - __bfloat162float(h3));
    ((__nv_bfloat162*)oh)[i*2]   = __nv_bfloat162(h0, h1);
    ((__nv_bfloat162*)oh)[i*2+1] = __nv_bfloat162(h2, h3);
    ((__nv_bfloat162*)ol)[i*2]   = __nv_bfloat162(l0, l1);
    ((__nv_bfloat162*)ol)[i*2+1] = __nv_bfloat162(l2, l3);
}

// ---------------- transpose + split ---------------------------------------
__global__ void transpose_split(const float* __restrict__ in, long izb, long izh, long ldin,
                                bf16* __restrict__ oh, bf16* __restrict__ ol,
                                long ozb, long ozh, long ldout)
{
    __shared__ float t[32][33];
    const int z = blockIdx.z, zb = z >> 4, zh = z & 15;
    const float* pin = in + (size_t)zb*izb + (size_t)zh*izh;
    bf16* poh = oh + (size_t)zb*ozb + (size_t)zh*ozh;
    bf16* pol = ol + (size_t)zb*ozb + (size_t)zh*ozh;
    const int r0 = blockIdx.y*32, c0 = blockIdx.x*32;
    const int tx = threadIdx.x, ty = threadIdx.y;
    #pragma unroll
    for (int i = 0; i < 32; i += 8)
        t[ty+i][tx] = pin[(size_t)(r0+ty+i)*ldin + c0+tx];
    __syncthreads();
    #pragma unroll
    for (int i = 0; i < 32; i += 8) {
        float vv = t[tx][ty+i];
        size_t o = (size_t)(c0+ty+i)*ldout + r0 + tx;
        bf16 h = __float2bfloat16(vv);
        poh[o] = h;
        pol[o] = __float2bfloat16(vv - __bfloat162float(h));
    }
}

// ---------------- fused rmsnorm + rope -> split bf16 -----------------------
__global__ __launch_bounds__(256) void rmsnorm_rope_split(
    const float* __restrict__ in, const float* __restrict__ g,
    const float* __restrict__ cosp, const float* __restrict__ sinp,
    float scale, bf16* __restrict__ oh, bf16* __restrict__ ol)
{
    __shared__ float s[DD];
    __shared__ float red[8];
    const int row = blockIdx.x;
    const int t = row & (TT - 1);
    const float* p = in + (size_t)row * DD;
    const int tid = threadIdx.x;

    float ss = 0.f;
    for (int c = tid; c < DD; c += 256) { float x = p[c]; s[c] = x; ss += x*x; }
    #pragma unroll
    for (int o = 16; o > 0; o >>= 1) ss += __shfl_xor_sync(0xffffffffu, ss, o);
    if ((tid & 31) == 0) red[tid >> 5] = ss;
    __syncthreads();
    float tot = red[0]+red[1]+red[2]+red[3]+red[4]+red[5]+red[6]+red[7];
    const float inv = rsqrtf(tot * (1.0f / (float)DD) + 1e-6f);

    for (int c = tid; c < DD; c += 256) {
        const int pidx = c & 127;
        const int base = c - pidx;
        float o;
        if (pidx < 64) {
            float x1 = s[c] * inv * g[c];
            float x2 = s[base + 64 + pidx] * inv * g[base + 64 + pidx];
            o = x1 * cosp[t*64 + pidx] - sinp[t*64 + pidx] * x2;
        } else {
            const int pp = pidx - 64;
            float x2 = s[c] * inv * g[c];
            float x1 = s[base + pp] * inv * g[base + pp];
            o = x2 * cosp[t*64 + pp] + sinp[t*64 + pp] * x1;
        }
        o *= scale;
        bf16 h = __float2bfloat16(o);
        oh[(size_t)row*DD + c] = h;
        ol[(size_t)row*DD + c] = __float2bfloat16(o - __bfloat162float(h));
    }
}

// ---------------- softmax -> split bf16 probs ------------------------------
__global__ __launch_bounds__(256) void softmax_split(
    const float* __restrict__ sc, bf16* __restrict__ ph, bf16* __restrict__ pl)
{
    const float* p = sc + (size_t)blockIdx.x * TT;
    bf16* oh = ph + (size_t)blockIdx.x * TT;
    bf16* ol = pl + (size_t)blockIdx.x * TT;
    const int tid = threadIdx.x;
    __shared__ float red[8];

    float v[8];
    float mx = -1e30f;
    #pragma unroll
    for (int i = 0; i < 8; i++) { v[i] = p[tid + i*256]; mx = fmaxf(mx, v[i]); }
    #pragma unroll
    for (int o = 16; o > 0; o >>= 1) mx = fmaxf(mx, __shfl_xor_sync(0xffffffffu, mx, o));
    if ((tid & 31) == 0) red[tid >> 5] = mx;
    __syncthreads();
    mx = fmaxf(fmaxf(fmaxf(red[0],red[1]),fmaxf(red[2],red[3])),
               fmaxf(fmaxf(red[4],red[5]),fmaxf(red[6],red[7])));
    __syncthreads();

    float sum = 0.f;
    #pragma unroll
    for (int i = 0; i < 8; i++) { v[i] = __expf(v[i] - mx); sum += v[i]; }
    #pragma unroll
    for (int o = 16; o > 0; o >>= 1) sum += __shfl_xor_sync(0xffffffffu, sum, o);
    if ((tid & 31) == 0) red[tid >> 5] = sum;
    __syncthreads();
    float tot = red[0]+red[1]+red[2]+red[3]+red[4]+red[5]+red[6]+red[7];
    const float r = 1.0f / tot;
    #pragma unroll
    for (int i = 0; i < 8; i++) {
        float e = v[i] * r;
        bf16 h = __float2bfloat16(e);
        oh[tid + i*256] = h;
        ol[tid + i*256] = __float2bfloat16(e - __bfloat162float(h));
    }
}

// ---------------------------------------------------------------------------
extern "C" void kernel_launch(void* const* d_in, const int* in_sizes, int n_in,
                              void* d_out, int out_size)
{
    const float* x    = (const float*)d_in[0];
    const float* cosp = (const float*)d_in[1];
    const float* sinp = (const float*)d_in[2];
    const float* w[5] = { (const float*)d_in[3], (const float*)d_in[5],
                          (const float*)d_in[7], (const float*)d_in[11],
                          (const float*)d_in[13] };
    const float* bq = (const float*)d_in[4];
    const float* bk = (const float*)d_in[6];
    const float* bv = (const float*)d_in[8];
    const float* gq = (const float*)d_in[9];
    const float* gk = (const float*)d_in[10];
    const float* bo = (const float*)d_in[12];
    const float* bg = (const float*)d_in[14];
    float* out = (float*)d_out;

    bf16 *xh, *xl, *wth, *wtl, *qh, *ql, *kh, *kl, *vth, *vtl, *ph, *pl, *ah, *al, *oh, *ol;
    float *tmp, *sc, *of;
    cudaGetSymbolAddress((void**)&xh, g_xh);   cudaGetSymbolAddress((void**)&xl, g_xl);
    cudaGetSymbolAddress((void**)&wth, g_wth); cudaGetSymbolAddress((void**)&wtl, g_wtl);
    cudaGetSymbolAddress((void**)&tmp, g_tmp);
    cudaGetSymbolAddress((void**)&qh, g_qh);   cudaGetSymbolAddress((void**)&ql, g_ql);
    cudaGetSymbolAddress((void**)&kh, g_kh);   cudaGetSymbolAddress((void**)&kl, g_kl);
    cudaGetSymbolAddress((void**)&vth, g_vth); cudaGetSymbolAddress((void**)&vtl, g_vtl);
    cudaGetSymbolAddress((void**)&sc, g_sc);
    cudaGetSymbolAddress((void**)&ph, g_ph);   cudaGetSymbolAddress((void**)&pl, g_pl);
    cudaGetSymbolAddress((void**)&ah, g_ah);   cudaGetSymbolAddress((void**)&al, g_al);
    cudaGetSymbolAddress((void**)&of, g_of);
    cudaGetSymbolAddress((void**)&oh, g_oh);   cudaGetSymbolAddress((void**)&ol, g_ol);

    const int SMEMSZ = 2*65536 + 1024;   // double-buffered stages + align pad
    static int attr_set = 0;
    if (!attr_set) {
        cudaFuncSetAttribute(gemm_t3, cudaFuncAttributeMaxDynamicSharedMemorySize, SMEMSZ);
        attr_set = 1;
    }

    dim3 blk(256), tb(32, 8);
    const long DDl = DD, TTl = TT;

    // input + weight prep
    split4<<<(MROWS*DD/4 + 255)/256, blk>>>(x, xh, xl, MROWS*DD/4);
    for (int i = 0; i < 5; i++)
        transpose_split<<<dim3(64,64,1), tb>>>(w[i], 0, 0, DDl,
            wth + (size_t)i*DD*DD, wtl + (size_t)i*DD*DD, 0, 0, DDl);

    dim3 gproj(DD/128, MROWS/128, 1);   // (16, 32)

    // Q
    gemm_t3<<<gproj, blk, SMEMSZ>>>(xh, xl, DDl,0,0, wth, wtl, DDl,0,0,
        bq, nullptr, tmp, nullptr, nullptr, DDl,0,0, DD, 0);
    rmsnorm_rope_split<<<MROWS, blk>>>(tmp, gq, cosp, sinp, 0.08838834764831845f, qh, ql);
    // K
    gemm_t3<<<gproj, blk, SMEMSZ>>>(xh, xl, DDl,0,0, wth + (size_t)DD*DD, wtl + (size_t)DD*DD, DDl,0,0,
        bk, nullptr, tmp, nullptr, nullptr, DDl,0,0, DD, 0);
    rmsnorm_rope_split<<<MROWS, blk>>>(tmp, gk, cosp, sinp, 1.0f, kh, kl);
    // V (+ transpose to [b,h,d,t])
    gemm_t3<<<gproj, blk, SMEMSZ>>>(xh, xl, DDl,0,0, wth + 2ULL*DD*DD, wtl + 2ULL*DD*DD, DDl,0,0,
        bv, nullptr, tmp, nullptr, nullptr, DDl,0,0, DD, 0);
    transpose_split<<<dim3(4,64,NB), tb>>>(tmp, (long)TT*DD, (long)HD, DDl,
        vth, vtl, 16L*HD*TT, (long)HD*TT, TTl);

    // scores = q @ k^T (scale folded into q)
    gemm_t3<<<dim3(16,16,NB), blk, SMEMSZ>>>(
        qh, ql, DDl, (long)TT*DD, (long)HD,
        kh, kl, DDl, (long)TT*DD, (long)HD,
        nullptr, nullptr, sc, nullptr, nullptr,
        TTl, 16L*TT*TT, (long)TT*TT, HD, 0);
    softmax_split<<<NB*TT, blk>>>(sc, ph, pl);
    // attn = P @ v
    gemm_t3<<<dim3(1,16,NB), blk, SMEMSZ>>>(
        ph, pl, TTl, 16L*TT*TT, (long)TT*TT,
        vth, vtl, TTl, 16L*HD*TT, (long)HD*TT,
        nullptr, nullptr, nullptr, ah, al,
        DDl, (long)TT*DD, (long)HD, TT, 1);
    // out proj (fp32 + split)
    gemm_t3<<<gproj, blk, SMEMSZ>>>(ah, al, DDl,0,0, wth + 3ULL*DD*DD, wtl + 3ULL*DD*DD, DDl,0,0,
        bo, nullptr, of, oh, ol, DDl,0,0, DD, 2);
    // gate: out = of * sigmoid(o @ wg + bg)
    gemm_t3<<<gproj, blk, SMEMSZ>>>(oh, ol, DDl,0,0, wth + 4ULL*DD*DD, wtl + 4ULL*DD*DD, DDl,0,0,
        bg, of, out, nullptr, nullptr, DDl,0,0, DD, 3);
}

// round 4
// speedup vs baseline: 3.2348x; 1.1317x over previous
#include <cuda_runtime.h>
#include <cuda_bf16.h>
#include <cstdint>
#include <math.h>

#define BB 2
#define TT 2048
#define DD 2048
#define HH 16
#define HD 128
#define MROWS (BB*TT)     // 4096
#define NB (BB*HH)        // 32

typedef __nv_bfloat16 bf16;

// ---------------- scratch (device globals; allocation-free rule) ----------
__device__ bf16  g_xh[(size_t)MROWS*DD], g_xl[(size_t)MROWS*DD];
__device__ bf16  g_wth[5ULL*DD*DD],      g_wtl[5ULL*DD*DD];      // transposed weights
__device__ float g_tmp[(size_t)MROWS*DD];                        // fp32 proj out
__device__ bf16  g_qh[(size_t)MROWS*DD], g_ql[(size_t)MROWS*DD];
__device__ bf16  g_kh[(size_t)MROWS*DD], g_kl[(size_t)MROWS*DD];
__device__ bf16  g_vth[(size_t)NB*HD*TT], g_vtl[(size_t)NB*HD*TT]; // v^T [b,h,d,t]
__device__ bf16  g_ah[(size_t)MROWS*DD], g_al[(size_t)MROWS*DD]; // attn hi/lo
__device__ float g_of[(size_t)MROWS*DD];
__device__ bf16  g_oh[(size_t)MROWS*DD], g_ol[(size_t)MROWS*DD];

// ---------------- PTX helpers (plain sm_80+ PTX only) ---------------------
__device__ __forceinline__ uint32_t smem_u32(const void* p) {
    uint32_t a;
    asm("{ .reg .u64 t; cvta.to.shared.u64 t, %1; cvt.u32.u64 %0, t; }" : "=r"(a) : "l"(p));
    return a;
}
__device__ __forceinline__ void cpa16(uint32_t s, const void* g) {
    asm volatile("cp.async.cg.shared.global [%0], [%1], 16;" :: "r"(s), "l"(g));
}
#define CP_COMMIT()  asm volatile("cp.async.commit_group;" ::: "memory")

__device__ __forceinline__ void ldsm4(uint32_t* r, uint32_t a) {
    asm volatile("ldmatrix.sync.aligned.m8n8.x4.shared.b16 {%0,%1,%2,%3}, [%4];"
        : "=r"(r[0]), "=r"(r[1]), "=r"(r[2]), "=r"(r[3]) : "r"(a));
}
__device__ __forceinline__ void mma16816(float* c, const uint32_t* a, const uint32_t* b) {
    asm volatile("mma.sync.aligned.m16n8k16.row.col.f32.bf16.bf16.f32 "
        "{%0,%1,%2,%3}, {%4,%5,%6,%7}, {%8,%9}, {%0,%1,%2,%3};"
        : "+f"(c[0]), "+f"(c[1]), "+f"(c[2]), "+f"(c[3])
        : "r"(a[0]), "r"(a[1]), "r"(a[2]), "r"(a[3]), "r"(b[0]), "r"(b[1]));
}
__device__ __forceinline__ uint32_t sw_addr(uint32_t base, int row, int ch) {
    uint32_t off = (uint32_t)(row*128 + ch*16);
    return base + (off ^ ((off >> 3) & 0x70u));
}
__device__ __forceinline__ uint32_t packsplit(float a, float b, uint32_t& lo) {
    bf16 ha = __float2bfloat16(a), hb = __float2bfloat16(b);
    bf16 la = __float2bfloat16(a - __bfloat162float(ha));
    bf16 lb = __float2bfloat16(b - __bfloat162float(hb));
    __nv_bfloat162 H(ha, hb), L(la, lb);
    lo = *(uint32_t*)&L;
    return *(uint32_t*)&H;
}

// ---------------- stage loader for gemm_t3 (SW128, BK=64) -----------------
__device__ __forceinline__ void ld_stage(uint32_t sb,
    const bf16* Ah, const bf16* Al, long lda,
    const bf16* Bh, const bf16* Bl, long ldb,
    int m0, int n0, int k0, int tid)
{
    #pragma unroll
    for (int t = 0; t < 4; t++) {
        int ch = tid + t*256;
        int r  = ch >> 3;
        int kc = ch & 7;
        uint32_t off = (uint32_t)(r*128 + kc*16);
        uint32_t sw  = off ^ ((off >> 3) & 0x70u);
        size_t ga = (size_t)(m0 + r)*lda + k0 + kc*8;
        cpa16(sb         + sw, Ah + ga);
        cpa16(sb + 16384 + sw, Al + ga);
        size_t gb = (size_t)(n0 + r)*ldb + k0 + kc*8;
        cpa16(sb + 32768 + sw, Bh + gb);
        cpa16(sb + 49152 + sw, Bl + gb);
    }
    CP_COMMIT();
}

// ---------------- GEMM: C = (Ah+Al)@(Bh+Bl)^T (3-term split-bf16) ---------
// epi: 0 = fp32 (+bias), 1 = split bf16, 2 = fp32 + split, 3 = gate
__global__ __launch_bounds__(256, 1) void gemm_t3(
    const bf16* __restrict__ Ah, const bf16* __restrict__ Al, long lda,
    const bf16* __restrict__ Bh, const bf16* __restrict__ Bl, long ldb,
    const float* __restrict__ bias, const float* __restrict__ mul,
    float* __restrict__ Cf, bf16* __restrict__ Ch, bf16* __restrict__ Cl,
    long ldc, int K, int epi)
{
    extern __shared__ __align__(16) uint8_t dyns[];
    const int tid = threadIdx.x;
    uint32_t raw = smem_u32(dyns);
    uint32_t sb0 = (raw + 1023u) & ~1023u;
    uint32_t pad = sb0 - raw;

    const int m0 = blockIdx.y * 128, n0 = blockIdx.x * 128;
    const int lane = tid & 31, wid = tid >> 5;
    const int wm = wid >> 1, wn = wid & 1;
    const int g8 = lane & 7, q = lane >> 3;

    float c[2][8][4];
    #pragma unroll
    for (int i = 0; i < 2; i++)
        #pragma unroll
        for (int j = 0; j < 8; j++)
            #pragma unroll
            for (int e = 0; e < 4; e++) c[i][j][e] = 0.f;

    const int nch = K >> 6;
    ld_stage(sb0, Ah, Al, lda, Bh, Bl, ldb, m0, n0, 0, tid);

    for (int cc = 0; cc < nch; cc++) {
        const int s = cc & 1;
        const uint32_t sbs = sb0 + s*65536;
        if (cc + 1 < nch) {
            ld_stage(sb0 + (s^1)*65536, Ah, Al, lda, Bh, Bl, ldb, m0, n0, (cc+1)*64, tid);
            asm volatile("cp.async.wait_group 1;" ::: "memory");
        } else {
            asm volatile("cp.async.wait_group 0;" ::: "memory");
        }
        __syncthreads();

        const uint32_t sAh = sbs, sBh = sbs + 32768;
        #pragma unroll
        for (int k16 = 0; k16 < 4; k16++) {
            uint32_t ah[2][4], al[2][4], bh[8][2], bl[8][2];
            #pragma unroll
            for (int mi = 0; mi < 2; mi++) {
                int row = wm*32 + mi*16 + g8 + ((q & 1) << 3);
                int ch  = k16*2 + (q >> 1);
                uint32_t a = sw_addr(sAh, row, ch);
                ldsm4(ah[mi], a);
                ldsm4(al[mi], a + 16384);
            }
            #pragma unroll
            for (int nj = 0; nj < 4; nj++) {
                int row = wn*64 + nj*16 + g8 + ((q >> 1) << 3);
                int ch  = k16*2 + (q & 1);
                uint32_t b = sw_addr(sBh, row, ch);
                uint32_t r[4];
                ldsm4(r, b);
                bh[2*nj][0] = r[0]; bh[2*nj][1] = r[1];
                bh[2*nj+1][0] = r[2]; bh[2*nj+1][1] = r[3];
                ldsm4(r, b + 16384);
                bl[2*nj][0] = r[0]; bl[2*nj][1] = r[1];
                bl[2*nj+1][0] = r[2]; bl[2*nj+1][1] = r[3];
            }
            #pragma unroll
            for (int mi = 0; mi < 2; mi++)
                #pragma unroll
                for (int ni = 0; ni < 8; ni++) {
                    mma16816(c[mi][ni], ah[mi], bh[ni]);
                    mma16816(c[mi][ni], al[mi], bh[ni]);
                    mma16816(c[mi][ni], ah[mi], bl[ni]);
                }
        }
        __syncthreads();
    }

    // ---- epilogue: frags -> padded fp32 smem -> coalesced gmem ----
    float* smemf = (float*)(dyns + pad);   // [128][132]
    {
        const int gid = lane >> 2, tig = lane & 3;
        #pragma unroll
        for (int mi = 0; mi < 2; mi++)
            #pragma unroll
            for (int ni = 0; ni < 8; ni++) {
                int r0 = wm*32 + mi*16 + gid;
                int col = wn*64 + ni*8 + tig*2;
                *(float2*)&smemf[r0*132 + col]     = make_float2(c[mi][ni][0], c[mi][ni][1]);
                *(float2*)&smemf[(r0+8)*132 + col] = make_float2(c[mi][ni][2], c[mi][ni][3]);
            }
    }
    __syncthreads();

    for (int v = tid; v < 4096; v += 256) {
        const int row = v >> 5, c4 = (v & 31) << 2;
        float4 val = *(const float4*)&smemf[row*132 + c4];
        const int gc = n0 + c4;
        const size_t go = (size_t)(m0 + row)*ldc + gc;
        if (bias) {
            val.x += bias[gc]; val.y += bias[gc+1]; val.z += bias[gc+2]; val.w += bias[gc+3];
        }
        if (epi == 0) {
            *(float4*)&Cf[go] = val;
        } else if (epi <= 2) {
            if (epi == 2) *(float4*)&Cf[go] = val;
            uint32_t l0, l1;
            uint32_t h0 = packsplit(val.x, val.y, l0);
            uint32_t h1 = packsplit(val.z, val.w, l1);
            *(uint32_t*)&Ch[go]   = h0; *(uint32_t*)&Ch[go+2] = h1;
            *(uint32_t*)&Cl[go]   = l0; *(uint32_t*)&Cl[go+2] = l1;
        } else {  // gate
            const float4 m = *(const float4*)&mul[go];
            float4 o;
            o.x = m.x / (1.0f + __expf(-val.x));
            o.y = m.y / (1.0f + __expf(-val.y));
            o.z = m.z / (1.0f + __expf(-val.z));
            o.w = m.w / (1.0f + __expf(-val.w));
            *(float4*)&Cf[go] = o;
        }
    }
}

// ---------------- flash attention KV stage loader --------------------------
// stage layout (64KB): Kh[2 panels 8KB] Kl[2 panels] | Vh 16KB | Vl 16KB
__device__ __forceinline__ void flash_ldkv(uint32_t stg, int kc0,
    const bf16* Kh, const bf16* Kl, const bf16* Vh, const bf16* Vl, int tid)
{
    #pragma unroll
    for (int t = 0; t < 16; t++) {
        int i = tid + t*256;
        if (i < 2048) {
            int p = i >> 9, j = i & 511;
            int r = j >> 3, ch = j & 7;
            uint32_t off = (uint32_t)(r*128 + ch*16);
            uint32_t sw = off ^ ((off >> 3) & 0x70u);
            const bf16* src = ((p < 2) ? Kh : Kl) + (size_t)(kc0 + r)*DD + (p & 1)*64 + ch*8;
            cpa16(stg + (p >> 1)*16384 + (p & 1)*8192 + sw, src);
        } else {
            int ii = i - 2048;
            int hi = ii >> 10, j = ii & 1023;
            int r = j >> 3, ch = j & 7;
            uint32_t off = (uint32_t)(r*128 + ch*16);
            uint32_t sw = off ^ ((off >> 3) & 0x70u);
            const bf16* src = (hi ? Vl : Vh) + (size_t)r*TT + kc0 + ch*8;
            cpa16(stg + 32768 + hi*16384 + sw, src);
        }
    }
    CP_COMMIT();
}

// ---------------- fused flash attention ------------------------------------
// grid (16 qtiles, 32 bh); 256 thr; 8 warps x 16 q-rows; kc tile = 64
__global__ __launch_bounds__(256, 1) void flash_attn(
    const bf16* __restrict__ qh, const bf16* __restrict__ ql,
    const bf16* __restrict__ kh, const bf16* __restrict__ kl,
    const bf16* __restrict__ vth, const bf16* __restrict__ vtl,
    bf16* __restrict__ ah, bf16* __restrict__ al)
{
    extern __shared__ __align__(16) uint8_t dyns[];
    const int tid = threadIdx.x;
    uint32_t raw = smem_u32(dyns);
    uint32_t sb0 = (raw + 1023u) & ~1023u;
    uint32_t pad = sb0 - raw;

    const int qt = blockIdx.x;
    const int bh = blockIdx.y;
    const int b = bh >> 4, h = bh & 15;

    const bf16* Qh = qh + ((size_t)(b*TT) + qt*128)*DD + h*HD;
    const bf16* Ql = ql + ((size_t)(b*TT) + qt*128)*DD + h*HD;
    const bf16* Kh = kh + (size_t)(b*TT)*DD + h*HD;
    const bf16* Kl = kl + (size_t)(b*TT)*DD + h*HD;
    const bf16* Vh = vth + (size_t)bh*HD*TT;
    const bf16* Vl = vtl + (size_t)bh*HD*TT;

    const int lane = tid & 31, wid = tid >> 5;
    const int g8 = lane & 7, q2 = lane >> 3;
    const int gid = lane >> 2, tig = lane & 3;

    // Q: 4 panels of 16KB (Qh p0, Qh p1 | Ql p0, Ql p1) at sb0..64KB  (group 0)
    #pragma unroll
    for (int t = 0; t < 16; t++) {
        int i = tid + t*256;
        int half = i >> 11, j = i & 2047;
        int pd = j >> 10, jj = j & 1023;
        int r = jj >> 3, ch = jj & 7;
        uint32_t off = (uint32_t)(r*128 + ch*16);
        uint32_t sw = off ^ ((off >> 3) & 0x70u);
        const bf16* src = (half ? Ql : Qh) + (size_t)r*DD + pd*64 + ch*8;
        cpa16(sb0 + half*32768 + pd*16384 + sw, src);
    }
    CP_COMMIT();
    flash_ldkv(sb0 + 65536,  0, Kh, Kl, Vh, Vl, tid);    // group 1
    flash_ldkv(sb0 + 131072, 64, Kh, Kl, Vh, Vl, tid);   // group 2

    float c_o[16][4];
    #pragma unroll
    for (int i = 0; i < 16; i++)
        #pragma unroll
        for (int e = 0; e < 4; e++) c_o[i][e] = 0.f;
    float m0 = -1e30f, m1 = -1e30f, l0 = 0.f, l1 = 0.f;

    for (int t = 0; t < 32; t++) {
        if (t < 31) asm volatile("cp.async.wait_group 1;" ::: "memory");
        else        asm volatile("cp.async.wait_group 0;" ::: "memory");
        __syncthreads();
        const uint32_t stg = sb0 + 65536 + (t & 1)*65536;

        // ---- S = Q @ K^T  (128 x 64, split-3) ----
        float c_s[8][4];
        #pragma unroll
        for (int i = 0; i < 8; i++)
            #pragma unroll
            for (int e = 0; e < 4; e++) c_s[i][e] = 0.f;

        #pragma unroll
        for (int k16 = 0; k16 < 8; k16++) {
            const int pd = k16 >> 2;
            uint32_t qa = sw_addr(sb0 + pd*16384, wid*16 + g8 + ((q2 & 1) << 3),
                                  (k16 & 3)*2 + (q2 >> 1));
            uint32_t qah[4], qal[4];
            ldsm4(qah, qa);
            ldsm4(qal, qa + 32768);
            uint32_t kbh[8][2], kbl[8][2];
            #pragma unroll
            for (int nj = 0; nj < 4; nj++) {
                uint32_t ka = sw_addr(stg + pd*8192, nj*16 + g8 + ((q2 >> 1) << 3),
                                      (k16 & 3)*2 + (q2 & 1));
                uint32_t r4[4];
                ldsm4(r4, ka);
                kbh[2*nj][0] = r4[0]; kbh[2*nj][1] = r4[1];
                kbh[2*nj+1][0] = r4[2]; kbh[2*nj+1][1] = r4[3];
                ldsm4(r4, ka + 16384);
                kbl[2*nj][0] = r4[0]; kbl[2*nj][1] = r4[1];
                kbl[2*nj+1][0] = r4[2]; kbl[2*nj+1][1] = r4[3];
            }
            #pragma unroll
            for (int nj = 0; nj < 8; nj++) {
                mma16816(c_s[nj], qah, kbh[nj]);
                mma16816(c_s[nj], qal, kbh[nj]);
                mma16816(c_s[nj], qah, kbl[nj]);
            }
        }

        // ---- online softmax (rows gid / gid+8 of this warp's 16) ----
        float tm0 = -1e30f, tm1 = -1e30f;
        #pragma unroll
        for (int nj = 0; nj < 8; nj++) {
            tm0 = fmaxf(tm0, fmaxf(c_s[nj][0], c_s[nj][1]));
            tm1 = fmaxf(tm1, fmaxf(c_s[nj][2], c_s[nj][3]));
        }
        tm0 = fmaxf(tm0, __shfl_xor_sync(0xffffffffu, tm0, 1));
        tm0 = fmaxf(tm0, __shfl_xor_sync(0xffffffffu, tm0, 2));
        tm1 = fmaxf(tm1, __shfl_xor_sync(0xffffffffu, tm1, 1));
        tm1 = fmaxf(tm1, __shfl_xor_sync(0xffffffffu, tm1, 2));
        const float mn0 = fmaxf(m0, tm0), mn1 = fmaxf(m1, tm1);
        const float a0 = __expf(m0 - mn0), a1 = __expf(m1 - mn1);
        float rs0 = 0.f, rs1 = 0.f;
        #pragma unroll
        for (int nj = 0; nj < 8; nj++) {
            c_s[nj][0] = __expf(c_s[nj][0] - mn0);
            c_s[nj][1] = __expf(c_s[nj][1] - mn0);
            c_s[nj][2] = __expf(c_s[nj][2] - mn1);
            c_s[nj][3] = __expf(c_s[nj][3] - mn1);
            rs0 += c_s[nj][0] + c_s[nj][1];
            rs1 += c_s[nj][2] + c_s[nj][3];
        }
        rs0 += __shfl_xor_sync(0xffffffffu, rs0, 1);
        rs0 += __shfl_xor_sync(0xffffffffu, rs0, 2);
        rs1 += __shfl_xor_sync(0xffffffffu, rs1, 1);
        rs1 += __shfl_xor_sync(0xffffffffu, rs1, 2);
        l0 = l0*a0 + rs0;  l1 = l1*a1 + rs1;
        m0 = mn0;          m1 = mn1;
        #pragma unroll
        for (int nb = 0; nb < 16; nb++) {
            c_o[nb][0] *= a0; c_o[nb][1] *= a0;
            c_o[nb][2] *= a1; c_o[nb][3] *= a1;
        }

        // ---- O += P @ V  (P A-frags built in registers, split-3) ----
        #pragma unroll
        for (int kb = 0; kb < 4; kb++) {
            uint32_t pah[4], pal[4];
            pah[0] = packsplit(c_s[2*kb][0],   c_s[2*kb][1],   pal[0]);
            pah[1] = packsplit(c_s[2*kb][2],   c_s[2*kb][3],   pal[1]);
            pah[2] = packsplit(c_s[2*kb+1][0], c_s[2*kb+1][1], pal[2]);
            pah[3] = packsplit(c_s[2*kb+1][2], c_s[2*kb+1][3], pal[3]);
            #pragma unroll
            for (int nj2 = 0; nj2 < 8; nj2++) {
                uint32_t va = sw_addr(stg + 32768, nj2*16 + g8 + ((q2 >> 1) << 3),
                                      kb*2 + (q2 & 1));
                uint32_t vh4[4], vl4[4];
                ldsm4(vh4, va);
                ldsm4(vl4, va + 16384);
                uint32_t b0[2] = {vh4[0], vh4[1]}, b1[2] = {vh4[2], vh4[3]};
                uint32_t c0[2] = {vl4[0], vl4[1]}, c1[2] = {vl4[2], vl4[3]};
                mma16816(c_o[2*nj2],   pah, b0);
                mma16816(c_o[2*nj2],   pal, b0);
                mma16816(c_o[2*nj2],   pah, c0);
                mma16816(c_o[2*nj2+1], pah, b1);
                mma16816(c_o[2*nj2+1], pal, b1);
                mma16816(c_o[2*nj2+1], pah, c1);
            }
        }

        __syncthreads();
        if (t + 2 < 32)
            flash_ldkv(sb0 + 65536 + (t & 1)*65536, (t+2)*64, Kh, Kl, Vh, Vl, tid);
    }

    // ---- epilogue: O/l -> padded fp32 smem -> coalesced split write ----
    float* smemf = (float*)(dyns + pad + 65536);   // reuse stage region, [128][132]
    {
        const float r0i = 1.0f / l0, r1i = 1.0f / l1;
        const int row0 = wid*16 + gid, row1 = row0 + 8;
        #pragma unroll
        for (int nb = 0; nb < 16; nb++) {
            const int col = nb*8 + tig*2;
            smemf[row0*132 + col]     = c_o[nb][0]*r0i;
            smemf[row0*132 + col + 1] = c_o[nb][1]*r0i;
            smemf[row1*132 + col]     = c_o[nb][2]*r1i;
            smemf[row1*132 + col + 1] = c_o[nb][3]*r1i;
        }
    }
    __syncthreads();
    for (int v = tid; v < 4096; v += 256) {
        const int row = v >> 5, c4 = (v & 31) << 2;
        float4 val = *(const float4*)&smemf[row*132 + c4];
        const size_t go = ((size_t)(b*TT) + qt*128 + row)*DD + h*HD + c4;
        uint32_t lo0, lo1;
        uint32_t hi0 = packsplit(val.x, val.y, lo0);
        uint32_t hi1 = packsplit(val.z, val.w, lo1);
        *(uint32_t*)&ah[go]   = hi0; *(uint32_t*)&ah[go+2] = hi1;
        *(uint32_t*)&al[go]   = lo0; *(uint32_t*)&al[go+2] = lo1;
    }
}

// ---------------- elementwise split: fp32 -> bf16 hi/lo -------------------
__global__ __launch_bounds__(256) void split4(const float* __restrict__ in,
    bf16* __restrict__ oh, bf16* __restrict__ ol, int n4)
{
    int i = blockIdx.x*256 + threadIdx.x;
    if (i >= n4) return;
    float4 v = ((const float4*)in)[i];
    uint32_t l0, l1;
    uint32_t h0 = packsplit(v.x, v.y, l0);
    uint32_t h1 = packsplit(v.z, v.w, l1);
    ((uint32_t*)oh)[i*2]   = h0; ((uint32_t*)oh)[i*2+1] = h1;
    ((uint32_t*)ol)[i*2]   = l0; ((uint32_t*)ol)[i*2+1] = l1;
}

// ---------------- transpose + split ---------------------------------------
__global__ void transpose_split(const float* __restrict__ in, long izb, long izh, long ldin,
                                bf16* __restrict__ oh, bf16* __restrict__ ol,
                                long ozb, long ozh, long ldout)
{
    __shared__ float t[32][33];
    const int z = blockIdx.z, zb = z >> 4, zh = z & 15;
    const float* pin = in + (size_t)zb*izb + (size_t)zh*izh;
    bf16* poh = oh + (size_t)zb*ozb + (size_t)zh*ozh;
    bf16* pol = ol + (size_t)zb*ozb + (size_t)zh*ozh;
    const int r0 = blockIdx.y*32, c0 = blockIdx.x*32;
    const int tx = threadIdx.x, ty = threadIdx.y;
    #pragma unroll
    for (int i = 0; i < 32; i += 8)
        t[ty+i][tx] = pin[(size_t)(r0+ty+i)*ldin + c0+tx];
    __syncthreads();
    #pragma unroll
    for (int i = 0; i < 32; i += 8) {
        float vv = t[tx][ty+i];
        size_t o = (size_t)(c0+ty+i)*ldout + r0 + tx;
        bf16 h = __float2bfloat16(vv);
        poh[o] = h;
        pol[o] = __float2bfloat16(vv - __bfloat162float(h));
    }
}

// ---------------- fused rmsnorm + rope -> split bf16 -----------------------
__global__ __launch_bounds__(256) void rmsnorm_rope_split(
    const float* __restrict__ in, const float* __restrict__ g,
    const float* __restrict__ cosp, const float* __restrict__ sinp,
    float scale, bf16* __restrict__ oh, bf16* __restrict__ ol)
{
    __shared__ float s[DD];
    __shared__ float red[8];
    const int row = blockIdx.x;
    const int t = row & (TT - 1);
    const float* p = in + (size_t)row * DD;
    const int tid = threadIdx.x;

    float ss = 0.f;
    for (int c = tid; c < DD; c += 256) { float x = p[c]; s[c] = x; ss += x*x; }
    #pragma unroll
    for (int o = 16; o > 0; o >>= 1) ss += __shfl_xor_sync(0xffffffffu, ss, o);
    if ((tid & 31) == 0) red[tid >> 5] = ss;
    __syncthreads();
    float tot = red[0]+red[1]+red[2]+red[3]+red[4]+red[5]+red[6]+red[7];
    const float inv = rsqrtf(tot * (1.0f / (float)DD) + 1e-6f);

    for (int c = tid; c < DD; c += 256) {
        const int pidx = c & 127;
        const int base = c - pidx;
        float o;
        if (pidx < 64) {
            float x1 = s[c] * inv * g[c];
            float x2 = s[base + 64 + pidx] * inv * g[base + 64 + pidx];
            o = x1 * cosp[t*64 + pidx] - sinp[t*64 + pidx] * x2;
        } else {
            const int pp = pidx - 64;
            float x2 = s[c] * inv * g[c];
            float x1 = s[base + pp] * inv * g[base + pp];
            o = x2 * cosp[t*64 + pp] + sinp[t*64 + pp] * x1;
        }
        o *= scale;
        bf16 h = __float2bfloat16(o);
        oh[(size_t)row*DD + c] = h;
        ol[(size_t)row*DD + c] = __float2bfloat16(o - __bfloat162float(h));
    }
}

// ---------------------------------------------------------------------------
extern "C" void kernel_launch(void* const* d_in, const int* in_sizes, int n_in,
                              void* d_out, int out_size)
{
    const float* x    = (const float*)d_in[0];
    const float* cosp = (const float*)d_in[1];
    const float* sinp = (const float*)d_in[2];
    const float* w[5] = { (const float*)d_in[3], (const float*)d_in[5],
                          (const float*)d_in[7], (const float*)d_in[11],
                          (const float*)d_in[13] };
    const float* bq = (const float*)d_in[4];
    const float* bk = (const float*)d_in[6];
    const float* bv = (const float*)d_in[8];
    const float* gq = (const float*)d_in[9];
    const float* gk = (const float*)d_in[10];
    const float* bo = (const float*)d_in[12];
    const float* bg = (const float*)d_in[14];
    float* out = (float*)d_out;

    bf16 *xh, *xl, *wth, *wtl, *qh, *ql, *kh, *kl, *vth, *vtl, *ah, *al, *oh, *ol;
    float *tmp, *of;
    cudaGetSymbolAddress((void**)&xh, g_xh);   cudaGetSymbolAddress((void**)&xl, g_xl);
    cudaGetSymbolAddress((void**)&wth, g_wth); cudaGetSymbolAddress((void**)&wtl, g_wtl);
    cudaGetSymbolAddress((void**)&tmp, g_tmp);
    cudaGetSymbolAddress((void**)&qh, g_qh);   cudaGetSymbolAddress((void**)&ql, g_ql);
    cudaGetSymbolAddress((void**)&kh, g_kh);   cudaGetSymbolAddress((void**)&kl, g_kl);
    cudaGetSymbolAddress((void**)&vth, g_vth); cudaGetSymbolAddress((void**)&vtl, g_vtl);
    cudaGetSymbolAddress((void**)&ah, g_ah);   cudaGetSymbolAddress((void**)&al, g_al);
    cudaGetSymbolAddress((void**)&of, g_of);
    cudaGetSymbolAddress((void**)&oh, g_oh);   cudaGetSymbolAddress((void**)&ol, g_ol);

    const int SMEMSZ  = 2*65536 + 1024;           // gemm_t3
    const int SMEMF   = 3*65536 + 1024;           // flash
    cudaFuncSetAttribute(gemm_t3, cudaFuncAttributeMaxDynamicSharedMemorySize, SMEMSZ);
    cudaFuncSetAttribute(flash_attn, cudaFuncAttributeMaxDynamicSharedMemorySize, SMEMF);

    dim3 blk(256), tb(32, 8);
    const long DDl = DD;

    // input + weight prep
    split4<<<(MROWS*DD/4 + 255)/256, blk>>>(x, xh, xl, MROWS*DD/4);
    for (int i = 0; i < 5; i++)
        transpose_split<<<dim3(64,64,1), tb>>>(w[i], 0, 0, DDl,
            wth + (size_t)i*DD*DD, wtl + (size_t)i*DD*DD, 0, 0, DDl);

    dim3 gproj(DD/128, MROWS/128, 1);   // (16, 32)

    // Q
    gemm_t3<<<gproj, blk, SMEMSZ>>>(xh, xl, DDl, wth, wtl, DDl,
        bq, nullptr, tmp, nullptr, nullptr, DDl, DD, 0);
    rmsnorm_rope_split<<<MROWS, blk>>>(tmp, gq, cosp, sinp, 0.08838834764831845f, qh, ql);
    // K
    gemm_t3<<<gproj, blk, SMEMSZ>>>(xh, xl, DDl, wth + (size_t)DD*DD, wtl + (size_t)DD*DD, DDl,
        bk, nullptr, tmp, nullptr, nullptr, DDl, DD, 0);
    rmsnorm_rope_split<<<MROWS, blk>>>(tmp, gk, cosp, sinp, 1.0f, kh, kl);
    // V (+ transpose to [b,h,d,t])
    gemm_t3<<<gproj, blk, SMEMSZ>>>(xh, xl, DDl, wth + 2ULL*DD*DD, wtl + 2ULL*DD*DD, DDl,
        bv, nullptr, tmp, nullptr, nullptr, DDl, DD, 0);
    transpose_split<<<dim3(4,64,NB), tb>>>(tmp, (long)TT*DD, (long)HD, DDl,
        vth, vtl, 16L*HD*TT, (long)HD*TT, (long)TT);

    // fused attention (scale folded into q)
    flash_attn<<<dim3(16, 32), blk, SMEMF>>>(qh, ql, kh, kl, vth, vtl, ah, al);

    // out proj (fp32 + split)
    gemm_t3<<<gproj, blk, SMEMSZ>>>(ah, al, DDl, wth + 3ULL*DD*DD, wtl + 3ULL*DD*DD, DDl,
        bo, nullptr, of, oh, ol, DDl, DD, 2);
    // gate: out = of * sigmoid(o @ wg + bg)
    gemm_t3<<<gproj, blk, SMEMSZ>>>(oh, ol, DDl, wth + 4ULL*DD*DD, wtl + 4ULL*DD*DD, DDl,
        bg, of, out, nullptr, nullptr, DDl, DD, 3);
}

// round 7
// speedup vs baseline: 3.3442x; 1.0338x over previous
#include <cuda_runtime.h>
#include <cuda_bf16.h>
#include <cstdint>
#include <math.h>

#define BB 2
#define TT 2048
#define DD 2048
#define HH 16
#define HD 128
#define MROWS (BB*TT)     // 4096
#define NB (BB*HH)        // 32

typedef __nv_bfloat16 bf16;

// ---------------- scratch (device globals; allocation-free rule) ----------
__device__ bf16  g_xh[(size_t)MROWS*DD], g_xl[(size_t)MROWS*DD];
__device__ bf16  g_wth[5ULL*DD*DD],      g_wtl[5ULL*DD*DD];      // transposed weights
__device__ float g_tmp[(size_t)MROWS*DD];                        // fp32 proj out
__device__ bf16  g_qh[(size_t)MROWS*DD], g_ql[(size_t)MROWS*DD];
__device__ bf16  g_kh[(size_t)MROWS*DD], g_kl[(size_t)MROWS*DD];
__device__ bf16  g_vth[(size_t)NB*HD*TT], g_vtl[(size_t)NB*HD*TT]; // v^T [b,h,d,t]
__device__ bf16  g_ah[(size_t)MROWS*DD], g_al[(size_t)MROWS*DD]; // attn hi/lo
__device__ float g_of[(size_t)MROWS*DD];
__device__ bf16  g_oh[(size_t)MROWS*DD], g_ol[(size_t)MROWS*DD];

// ---------------- PTX helpers (plain sm_80+ PTX only) ---------------------
__device__ __forceinline__ uint32_t smem_u32(const void* p) {
    uint32_t a;
    asm("{ .reg .u64 t; cvta.to.shared.u64 t, %1; cvt.u32.u64 %0, t; }" : "=r"(a) : "l"(p));
    return a;
}
__device__ __forceinline__ void cpa16(uint32_t s, const void* g) {
    asm volatile("cp.async.cg.shared.global [%0], [%1], 16;" :: "r"(s), "l"(g));
}
#define CP_COMMIT()  asm volatile("cp.async.commit_group;" ::: "memory")

__device__ __forceinline__ void ldsm4(uint32_t* r, uint32_t a) {
    asm volatile("ldmatrix.sync.aligned.m8n8.x4.shared.b16 {%0,%1,%2,%3}, [%4];"
        : "=r"(r[0]), "=r"(r[1]), "=r"(r[2]), "=r"(r[3]) : "r"(a));
}
__device__ __forceinline__ void mma16816(float* c, const uint32_t* a, const uint32_t* b) {
    asm volatile("mma.sync.aligned.m16n8k16.row.col.f32.bf16.bf16.f32 "
        "{%0,%1,%2,%3}, {%4,%5,%6,%7}, {%8,%9}, {%0,%1,%2,%3};"
        : "+f"(c[0]), "+f"(c[1]), "+f"(c[2]), "+f"(c[3])
        : "r"(a[0]), "r"(a[1]), "r"(a[2]), "r"(a[3]), "r"(b[0]), "r"(b[1]));
}
__device__ __forceinline__ uint32_t sw_addr(uint32_t base, int row, int ch) {
    uint32_t off = (uint32_t)(row*128 + ch*16);
    return base + (off ^ ((off >> 3) & 0x70u));
}
__device__ __forceinline__ uint32_t packsplit(float a, float b, uint32_t& lo) {
    bf16 ha = __float2bfloat16(a), hb = __float2bfloat16(b);
    bf16 la = __float2bfloat16(a - __bfloat162float(ha));
    bf16 lb = __float2bfloat16(b - __bfloat162float(hb));
    __nv_bfloat162 H(ha, hb), L(la, lb);
    lo = *(uint32_t*)&L;
    return *(uint32_t*)&H;
}

// ============ 256x128x64 GEMM (split-3 bf16) ================================
// stage layout (96KB): Ah 32KB | Al 32KB | Bh 16KB | Bl 16KB
#define STG_SZ 98304

__device__ __forceinline__ void ld_stage256(uint32_t sb,
    const bf16* Ah, const bf16* Al, long lda,
    const bf16* Bh, const bf16* Bl, long ldb,
    int m0, int n0, int k0, int tid)
{
    #pragma unroll
    for (int t = 0; t < 24; t++) {
        int i = tid + t*256;
        if (i < 4096) {                       // A hi/lo: 256 rows x 128B each
            int half = i >> 11, j = i & 2047;
            int r = j >> 3, ch = j & 7;
            uint32_t off = (uint32_t)(r*128 + ch*16);
            uint32_t sw = off ^ ((off >> 3) & 0x70u);
            const bf16* src = (half ? Al : Ah) + (size_t)(m0 + r)*lda + k0 + ch*8;
            cpa16(sb + half*32768 + sw, src);
        } else {                              // B hi/lo: 128 rows x 128B each
            int ii = i - 4096;
            int half = ii >> 10, j = ii & 1023;
            int r = j >> 3, ch = j & 7;
            uint32_t off = (uint32_t)(r*128 + ch*16);
            uint32_t sw = off ^ ((off >> 3) & 0x70u);
            const bf16* src = (half ? Bl : Bh) + (size_t)(n0 + r)*ldb + k0 + ch*8;
            cpa16(sb + 65536 + half*16384 + sw, src);
        }
    }
    CP_COMMIT();
}

// epi: 0 = fp32 (+bias), 1 = split bf16, 2 = fp32 + split, 3 = gate
__global__ __launch_bounds__(256, 1) void gemm_t3(
    const bf16* __restrict__ Ah, const bf16* __restrict__ Al, long lda,
    const bf16* __restrict__ Bh, const bf16* __restrict__ Bl, long ldb,
    const float* __restrict__ bias, const float* __restrict__ mul,
    float* __restrict__ Cf, bf16* __restrict__ Ch, bf16* __restrict__ Cl,
    long ldc, int K, int epi)
{
    extern __shared__ __align__(16) uint8_t dyns[];
    const int tid = threadIdx.x;
    uint32_t raw = smem_u32(dyns);
    uint32_t sb0 = (raw + 1023u) & ~1023u;
    uint32_t pad = sb0 - raw;

    const int m0 = blockIdx.y * 256, n0 = blockIdx.x * 128;
    const int lane = tid & 31, wid = tid >> 5;
    const int wm = wid >> 1, wn = wid & 1;       // 4 x 2 warps, each 64x64
    const int g8 = lane & 7, q = lane >> 3;

    float c[4][8][4];
    #pragma unroll
    for (int i = 0; i < 4; i++)
        #pragma unroll
        for (int j = 0; j < 8; j++)
            #pragma unroll
            for (int e = 0; e < 4; e++) c[i][j][e] = 0.f;

    const int nch = K >> 6;
    ld_stage256(sb0, Ah, Al, lda, Bh, Bl, ldb, m0, n0, 0, tid);

    for (int cc = 0; cc < nch; cc++) {
        const int s = cc & 1;
        const uint32_t sbs = sb0 + s*STG_SZ;
        if (cc + 1 < nch) {
            ld_stage256(sb0 + (s^1)*STG_SZ, Ah, Al, lda, Bh, Bl, ldb, m0, n0, (cc+1)*64, tid);
            asm volatile("cp.async.wait_group 1;" ::: "memory");
        } else {
            asm volatile("cp.async.wait_group 0;" ::: "memory");
        }
        __syncthreads();

        #pragma unroll
        for (int k16 = 0; k16 < 4; k16++) {
            uint32_t bh[8][2], bl[8][2];
            #pragma unroll
            for (int nj = 0; nj < 4; nj++) {
                int row = wn*64 + nj*16 + g8 + ((q >> 1) << 3);
                int ch  = k16*2 + (q & 1);
                uint32_t b = sw_addr(sbs + 65536, row, ch);
                uint32_t r4[4];
                ldsm4(r4, b);
                bh[2*nj][0] = r4[0]; bh[2*nj][1] = r4[1];
                bh[2*nj+1][0] = r4[2]; bh[2*nj+1][1] = r4[3];
                ldsm4(r4, b + 16384);
                bl[2*nj][0] = r4[0]; bl[2*nj][1] = r4[1];
                bl[2*nj+1][0] = r4[2]; bl[2*nj+1][1] = r4[3];
            }
            #pragma unroll
            for (int mi = 0; mi < 4; mi++) {
                int row = wm*64 + mi*16 + g8 + ((q & 1) << 3);
                int ch  = k16*2 + (q >> 1);
                uint32_t a = sw_addr(sbs, row, ch);
                uint32_t ah4[4], al4[4];
                ldsm4(ah4, a);
                ldsm4(al4, a + 32768);
                #pragma unroll
                for (int ni = 0; ni < 8; ni++) {
                    mma16816(c[mi][ni], ah4, bh[ni]);
                    mma16816(c[mi][ni], al4, bh[ni]);
                    mma16816(c[mi][ni], ah4, bl[ni]);
                }
            }
        }
        __syncthreads();
    }

    // ---- epilogue: frags -> padded fp32 smem [256][132] -> coalesced gmem ----
    float* smemf = (float*)(dyns + pad);
    {
        const int gid = lane >> 2, tig = lane & 3;
        #pragma unroll
        for (int mi = 0; mi < 4; mi++)
            #pragma unroll
            for (int ni = 0; ni < 8; ni++) {
                int r0 = wm*64 + mi*16 + gid;
                int col = wn*64 + ni*8 + tig*2;
                *(float2*)&smemf[r0*132 + col]     = make_float2(c[mi][ni][0], c[mi][ni][1]);
                *(float2*)&smemf[(r0+8)*132 + col] = make_float2(c[mi][ni][2], c[mi][ni][3]);
            }
    }
    __syncthreads();

    for (int v = tid; v < 8192; v += 256) {
        const int row = v >> 5, c4 = (v & 31) << 2;
        float4 val = *(const float4*)&smemf[row*132 + c4];
        const int gc = n0 + c4;
        const size_t go = (size_t)(m0 + row)*ldc + gc;
        if (bias) {
            val.x += bias[gc]; val.y += bias[gc+1]; val.z += bias[gc+2]; val.w += bias[gc+3];
        }
        if (epi == 0) {
            *(float4*)&Cf[go] = val;
        } else if (epi <= 2) {
            if (epi == 2) *(float4*)&Cf[go] = val;
            uint32_t l0, l1;
            uint32_t h0 = packsplit(val.x, val.y, l0);
            uint32_t h1 = packsplit(val.z, val.w, l1);
            *(uint32_t*)&Ch[go]   = h0; *(uint32_t*)&Ch[go+2] = h1;
            *(uint32_t*)&Cl[go]   = l0; *(uint32_t*)&Cl[go+2] = l1;
        } else {  // gate
            const float4 m = *(const float4*)&mul[go];
            float4 o;
            o.x = m.x / (1.0f + __expf(-val.x));
            o.y = m.y / (1.0f + __expf(-val.y));
            o.z = m.z / (1.0f + __expf(-val.z));
            o.w = m.w / (1.0f + __expf(-val.w));
            *(float4*)&Cf[go] = o;
        }
    }
}

// ---------------- flash attention KV stage loader --------------------------
__device__ __forceinline__ void flash_ldkv(uint32_t stg, int kc0,
    const bf16* Kh, const bf16* Kl, const bf16* Vh, const bf16* Vl, int tid)
{
    #pragma unroll
    for (int t = 0; t < 16; t++) {
        int i = tid + t*256;
        if (i < 2048) {
            int p = i >> 9, j = i & 511;
            int r = j >> 3, ch = j & 7;
            uint32_t off = (uint32_t)(r*128 + ch*16);
            uint32_t sw = off ^ ((off >> 3) & 0x70u);
            const bf16* src = ((p < 2) ? Kh : Kl) + (size_t)(kc0 + r)*DD + (p & 1)*64 + ch*8;
            cpa16(stg + (p >> 1)*16384 + (p & 1)*8192 + sw, src);
        } else {
            int ii = i - 2048;
            int hi = ii >> 10, j = ii & 1023;
            int r = j >> 3, ch = j & 7;
            uint32_t off = (uint32_t)(r*128 + ch*16);
            uint32_t sw = off ^ ((off >> 3) & 0x70u);
            const bf16* src = (hi ? Vl : Vh) + (size_t)r*TT + kc0 + ch*8;
            cpa16(stg + 32768 + hi*16384 + sw, src);
        }
    }
    CP_COMMIT();
}

// ---------------- fused flash attention ------------------------------------
__global__ __launch_bounds__(256, 1) void flash_attn(
    const bf16* __restrict__ qh, const bf16* __restrict__ ql,
    const bf16* __restrict__ kh, const bf16* __restrict__ kl,
    const bf16* __restrict__ vth, const bf16* __restrict__ vtl,
    bf16* __restrict__ ah, bf16* __restrict__ al)
{
    extern __shared__ __align__(16) uint8_t dyns[];
    const int tid = threadIdx.x;
    uint32_t raw = smem_u32(dyns);
    uint32_t sb0 = (raw + 1023u) & ~1023u;
    uint32_t pad = sb0 - raw;

    const int qt = blockIdx.x;
    const int bh = blockIdx.y;
    const int b = bh >> 4, h = bh & 15;

    const bf16* Qh = qh + ((size_t)(b*TT) + qt*128)*DD + h*HD;
    const bf16* Ql = ql + ((size_t)(b*TT) + qt*128)*DD + h*HD;
    const bf16* Kh = kh + (size_t)(b*TT)*DD + h*HD;
    const bf16* Kl = kl + (size_t)(b*TT)*DD + h*HD;
    const bf16* Vh = vth + (size_t)bh*HD*TT;
    const bf16* Vl = vtl + (size_t)bh*HD*TT;

    const int lane = tid & 31, wid = tid >> 5;
    const int g8 = lane & 7, q2 = lane >> 3;
    const int gid = lane >> 2, tig = lane & 3;

    #pragma unroll
    for (int t = 0; t < 16; t++) {
        int i = tid + t*256;
        int half = i >> 11, j = i & 2047;
        int pd = j >> 10, jj = j & 1023;
        int r = jj >> 3, ch = jj & 7;
        uint32_t off = (uint32_t)(r*128 + ch*16);
        uint32_t sw = off ^ ((off >> 3) & 0x70u);
        const bf16* src = (half ? Ql : Qh) + (size_t)r*DD + pd*64 + ch*8;
        cpa16(sb0 + half*32768 + pd*16384 + sw, src);
    }
    CP_COMMIT();
    flash_ldkv(sb0 + 65536,  0, Kh, Kl, Vh, Vl, tid);
    flash_ldkv(sb0 + 131072, 64, Kh, Kl, Vh, Vl, tid);

    float c_o[16][4];
    #pragma unroll
    for (int i = 0; i < 16; i++)
        #pragma unroll
        for (int e = 0; e < 4; e++) c_o[i][e] = 0.f;
    float m0 = -1e30f, m1 = -1e30f, l0 = 0.f, l1 = 0.f;

    for (int t = 0; t < 32; t++) {
        if (t < 31) asm volatile("cp.async.wait_group 1;" ::: "memory");
        else        asm volatile("cp.async.wait_group 0;" ::: "memory");
        __syncthreads();
        const uint32_t stg = sb0 + 65536 + (t & 1)*65536;

        float c_s[8][4];
        #pragma unroll
        for (int i = 0; i < 8; i++)
            #pragma unroll
            for (int e = 0; e < 4; e++) c_s[i][e] = 0.f;

        #pragma unroll
        for (int k16 = 0; k16 < 8; k16++) {
            const int pd = k16 >> 2;
            uint32_t qa = sw_addr(sb0 + pd*16384, wid*16 + g8 + ((q2 & 1) << 3),
                                  (k16 & 3)*2 + (q2 >> 1));
            uint32_t qah[4], qal[4];
            ldsm4(qah, qa);
            ldsm4(qal, qa + 32768);
            uint32_t kbh[8][2], kbl[8][2];
            #pragma unroll
            for (int nj = 0; nj < 4; nj++) {
                uint32_t ka = sw_addr(stg + pd*8192, nj*16 + g8 + ((q2 >> 1) << 3),
                                      (k16 & 3)*2 + (q2 & 1));
                uint32_t r4[4];
                ldsm4(r4, ka);
                kbh[2*nj][0] = r4[0]; kbh[2*nj][1] = r4[1];
                kbh[2*nj+1][0] = r4[2]; kbh[2*nj+1][1] = r4[3];
                ldsm4(r4, ka + 16384);
                kbl[2*nj][0] = r4[0]; kbl[2*nj][1] = r4[1];
                kbl[2*nj+1][0] = r4[2]; kbl[2*nj+1][1] = r4[3];
            }
            #pragma unroll
            for (int nj = 0; nj < 8; nj++) {
                mma16816(c_s[nj], qah, kbh[nj]);
                mma16816(c_s[nj], qal, kbh[nj]);
                mma16816(c_s[nj], qah, kbl[nj]);
            }
        }

        float tm0 = -1e30f, tm1 = -1e30f;
        #pragma unroll
        for (int nj = 0; nj < 8; nj++) {
            tm0 = fmaxf(tm0, fmaxf(c_s[nj][0], c_s[nj][1]));
            tm1 = fmaxf(tm1, fmaxf(c_s[nj][2], c_s[nj][3]));
        }
        tm0 = fmaxf(tm0, __shfl_xor_sync(0xffffffffu, tm0, 1));
        tm0 = fmaxf(tm0, __shfl_xor_sync(0xffffffffu, tm0, 2));
        tm1 = fmaxf(tm1, __shfl_xor_sync(0xffffffffu, tm1, 1));
        tm1 = fmaxf(tm1, __shfl_xor_sync(0xffffffffu, tm1, 2));
        const float mn0 = fmaxf(m0, tm0), mn1 = fmaxf(m1, tm1);
        const float a0 = __expf(m0 - mn0), a1 = __expf(m1 - mn1);
        float rs0 = 0.f, rs1 = 0.f;
        #pragma unroll
        for (int nj = 0; nj < 8; nj++) {
            c_s[nj][0] = __expf(c_s[nj][0] - mn0);
            c_s[nj][1] = __expf(c_s[nj][1] - mn0);
            c_s[nj][2] = __expf(c_s[nj][2] - mn1);
            c_s[nj][3] = __expf(c_s[nj][3] - mn1);
            rs0 += c_s[nj][0] + c_s[nj][1];
            rs1 += c_s[nj][2] + c_s[nj][3];
        }
        rs0 += __shfl_xor_sync(0xffffffffu, rs0, 1);
        rs0 += __shfl_xor_sync(0xffffffffu, rs0, 2);
        rs1 += __shfl_xor_sync(0xffffffffu, rs1, 1);
        rs1 += __shfl_xor_sync(0xffffffffu, rs1, 2);
        l0 = l0*a0 + rs0;  l1 = l1*a1 + rs1;
        m0 = mn0;          m1 = mn1;
        #pragma unroll
        for (int nb = 0; nb < 16; nb++) {
            c_o[nb][0] *= a0; c_o[nb][1] *= a0;
            c_o[nb][2] *= a1; c_o[nb][3] *= a1;
        }

        #pragma unroll
        for (int kb = 0; kb < 4; kb++) {
            uint32_t pah[4], pal[4];
            pah[0] = packsplit(c_s[2*kb][0],   c_s[2*kb][1],   pal[0]);
            pah[1] = packsplit(c_s[2*kb][2],   c_s[2*kb][3],   pal[1]);
            pah[2] = packsplit(c_s[2*kb+1][0], c_s[2*kb+1][1], pal[2]);
            pah[3] = packsplit(c_s[2*kb+1][2], c_s[2*kb+1][3], pal[3]);
            #pragma unroll
            for (int nj2 = 0; nj2 < 8; nj2++) {
                uint32_t va = sw_addr(stg + 32768, nj2*16 + g8 + ((q2 >> 1) << 3),
                                      kb*2 + (q2 & 1));
                uint32_t vh4[4], vl4[4];
                ldsm4(vh4, va);
                ldsm4(vl4, va + 16384);
                uint32_t b0[2] = {vh4[0], vh4[1]}, b1[2] = {vh4[2], vh4[3]};
                uint32_t c0[2] = {vl4[0], vl4[1]}, c1[2] = {vl4[2], vl4[3]};
                mma16816(c_o[2*nj2],   pah, b0);
                mma16816(c_o[2*nj2],   pal, b0);
                mma16816(c_o[2*nj2],   pah, c0);
                mma16816(c_o[2*nj2+1], pah, b1);
                mma16816(c_o[2*nj2+1], pal, b1);
                mma16816(c_o[2*nj2+1], pah, c1);
            }
        }

        __syncthreads();
        if (t + 2 < 32)
            flash_ldkv(sb0 + 65536 + (t & 1)*65536, (t+2)*64, Kh, Kl, Vh, Vl, tid);
    }

    float* smemf = (float*)(dyns + pad + 65536);
    {
        const float r0i = 1.0f / l0, r1i = 1.0f / l1;
        const int row0 = wid*16 + gid, row1 = row0 + 8;
        #pragma unroll
        for (int nb = 0; nb < 16; nb++) {
            const int col = nb*8 + tig*2;
            smemf[row0*132 + col]     = c_o[nb][0]*r0i;
            smemf[row0*132 + col + 1] = c_o[nb][1]*r0i;
            smemf[row1*132 + col]     = c_o[nb][2]*r1i;
            smemf[row1*132 + col + 1] = c_o[nb][3]*r1i;
        }
    }
    __syncthreads();
    for (int v = tid; v < 4096; v += 256) {
        const int row = v >> 5, c4 = (v & 31) << 2;
        float4 val = *(const float4*)&smemf[row*132 + c4];
        const size_t go = ((size_t)(b*TT) + qt*128 + row)*DD + h*HD + c4;
        uint32_t lo0, lo1;
        uint32_t hi0 = packsplit(val.x, val.y, lo0);
        uint32_t hi1 = packsplit(val.z, val.w, lo1);
        *(uint32_t*)&ah[go]   = hi0; *(uint32_t*)&ah[go+2] = hi1;
        *(uint32_t*)&al[go]   = lo0; *(uint32_t*)&al[go+2] = lo1;
    }
}

// ---------------- elementwise split: fp32 -> bf16 hi/lo -------------------
__global__ __launch_bounds__(256) void split4(const float* __restrict__ in,
    bf16* __restrict__ oh, bf16* __restrict__ ol, int n4)
{
    int i = blockIdx.x*256 + threadIdx.x;
    if (i >= n4) return;
    float4 v = ((const float4*)in)[i];
    uint32_t l0, l1;
    uint32_t h0 = packsplit(v.x, v.y, l0);
    uint32_t h1 = packsplit(v.z, v.w, l1);
    ((uint32_t*)oh)[i*2]   = h0; ((uint32_t*)oh)[i*2+1] = h1;
    ((uint32_t*)ol)[i*2]   = l0; ((uint32_t*)ol)[i*2+1] = l1;
}

// ---------------- transpose + split ---------------------------------------
__global__ void transpose_split(const float* __restrict__ in, long izb, long izh, long ldin,
                                bf16* __restrict__ oh, bf16* __restrict__ ol,
                                long ozb, long ozh, long ldout)
{
    __shared__ float t[32][33];
    const int z = blockIdx.z, zb = z >> 4, zh = z & 15;
    const float* pin = in + (size_t)zb*izb + (size_t)zh*izh;
    bf16* poh = oh + (size_t)zb*ozb + (size_t)zh*ozh;
    bf16* pol = ol + (size_t)zb*ozb + (size_t)zh*ozh;
    const int r0 = blockIdx.y*32, c0 = blockIdx.x*32;
    const int tx = threadIdx.x, ty = threadIdx.y;
    #pragma unroll
    for (int i = 0; i < 32; i += 8)
        t[ty+i][tx] = pin[(size_t)(r0+ty+i)*ldin + c0+tx];
    __syncthreads();
    #pragma unroll
    for (int i = 0; i < 32; i += 8) {
        float vv = t[tx][ty+i];
        size_t o = (size_t)(c0+ty+i)*ldout + r0 + tx;
        bf16 h = __float2bfloat16(vv);
        poh[o] = h;
        pol[o] = __float2bfloat16(vv - __bfloat162float(h));
    }
}

// ---------------- fused rmsnorm + rope -> split bf16 -----------------------
__global__ __launch_bounds__(256) void rmsnorm_rope_split(
    const float* __restrict__ in, const float* __restrict__ g,
    const float* __restrict__ cosp, const float* __restrict__ sinp,
    float scale, bf16* __restrict__ oh, bf16* __restrict__ ol)
{
    __shared__ float s[DD];
    __shared__ float red[8];
    const int row = blockIdx.x;
    const int t = row & (TT - 1);
    const float* p = in + (size_t)row * DD;
    const int tid = threadIdx.x;

    float ss = 0.f;
    for (int c = tid; c < DD; c += 256) { float x = p[c]; s[c] = x; ss += x*x; }
    #pragma unroll
    for (int o = 16; o > 0; o >>= 1) ss += __shfl_xor_sync(0xffffffffu, ss, o);
    if ((tid & 31) == 0) red[tid >> 5] = ss;
    __syncthreads();
    float tot = red[0]+red[1]+red[2]+red[3]+red[4]+red[5]+red[6]+red[7];
    const float inv = rsqrtf(tot * (1.0f / (float)DD) + 1e-6f);

    for (int c = tid; c < DD; c += 256) {
        const int pidx = c & 127;
        const int base = c - pidx;
        float o;
        if (pidx < 64) {
            float x1 = s[c] * inv * g[c];
            float x2 = s[base + 64 + pidx] * inv * g[base + 64 + pidx];
            o = x1 * cosp[t*64 + pidx] - sinp[t*64 + pidx] * x2;
        } else {
            const int pp = pidx - 64;
            float x2 = s[c] * inv * g[c];
            float x1 = s[base + pp] * inv * g[base + pp];
            o = x2 * cosp[t*64 + pp] + sinp[t*64 + pp] * x1;
        }
        o *= scale;
        bf16 h = __float2bfloat16(o);
        oh[(size_t)row*DD + c] = h;
        ol[(size_t)row*DD + c] = __float2bfloat16(o - __bfloat162float(h));
    }
}

// ---------------------------------------------------------------------------
extern "C" void kernel_launch(void* const* d_in, const int* in_sizes, int n_in,
                              void* d_out, int out_size)
{
    const float* x    = (const float*)d_in[0];
    const float* cosp = (const float*)d_in[1];
    const float* sinp = (const float*)d_in[2];
    const float* w[5] = { (const float*)d_in[3], (const float*)d_in[5],
                          (const float*)d_in[7], (const float*)d_in[11],
                          (const float*)d_in[13] };
    const float* bq = (const float*)d_in[4];
    const float* bk = (const float*)d_in[6];
    const float* bv = (const float*)d_in[8];
    const float* gq = (const float*)d_in[9];
    const float* gk = (const float*)d_in[10];
    const float* bo = (const float*)d_in[12];
    const float* bg = (const float*)d_in[14];
    float* out = (float*)d_out;

    bf16 *xh, *xl, *wth, *wtl, *qh, *ql, *kh, *kl, *vth, *vtl, *ah, *al, *oh, *ol;
    float *tmp, *of;
    cudaGetSymbolAddress((void**)&xh, g_xh);   cudaGetSymbolAddress((void**)&xl, g_xl);
    cudaGetSymbolAddress((void**)&wth, g_wth); cudaGetSymbolAddress((void**)&wtl, g_wtl);
    cudaGetSymbolAddress((void**)&tmp, g_tmp);
    cudaGetSymbolAddress((void**)&qh, g_qh);   cudaGetSymbolAddress((void**)&ql, g_ql);
    cudaGetSymbolAddress((void**)&kh, g_kh);   cudaGetSymbolAddress((void**)&kl, g_kl);
    cudaGetSymbolAddress((void**)&vth, g_vth); cudaGetSymbolAddress((void**)&vtl, g_vtl);
    cudaGetSymbolAddress((void**)&ah, g_ah);   cudaGetSymbolAddress((void**)&al, g_al);
    cudaGetSymbolAddress((void**)&of, g_of);
    cudaGetSymbolAddress((void**)&oh, g_oh);   cudaGetSymbolAddress((void**)&ol, g_ol);

    const int SMEMSZ  = 2*STG_SZ + 1024;          // gemm_t3 (256x128)
    const int SMEMF   = 3*65536 + 1024;           // flash
    cudaFuncSetAttribute(gemm_t3, cudaFuncAttributeMaxDynamicSharedMemorySize, SMEMSZ);
    cudaFuncSetAttribute(flash_attn, cudaFuncAttributeMaxDynamicSharedMemorySize, SMEMF);

    dim3 blk(256), tb(32, 8);
    const long DDl = DD;

    // input + weight prep
    split4<<<(MROWS*DD/4 + 255)/256, blk>>>(x, xh, xl, MROWS*DD/4);
    for (int i = 0; i < 5; i++)
        transpose_split<<<dim3(64,64,1), tb>>>(w[i], 0, 0, DDl,
            wth + (size_t)i*DD*DD, wtl + (size_t)i*DD*DD, 0, 0, DDl);

    dim3 gproj(DD/128, MROWS/256, 1);   // (16, 16)

    // Q
    gemm_t3<<<gproj, blk, SMEMSZ>>>(xh, xl, DDl, wth, wtl, DDl,
        bq, nullptr, tmp, nullptr, nullptr, DDl, DD, 0);
    rmsnorm_rope_split<<<MROWS, blk>>>(tmp, gq, cosp, sinp, 0.08838834764831845f, qh, ql);
    // K
    gemm_t3<<<gproj, blk, SMEMSZ>>>(xh, xl, DDl, wth + (size_t)DD*DD, wtl + (size_t)DD*DD, DDl,
        bk, nullptr, tmp, nullptr, nullptr, DDl, DD, 0);
    rmsnorm_rope_split<<<MROWS, blk>>>(tmp, gk, cosp, sinp, 1.0f, kh, kl);
    // V (+ transpose to [b,h,d,t])
    gemm_t3<<<gproj, blk, SMEMSZ>>>(xh, xl, DDl, wth + 2ULL*DD*DD, wtl + 2ULL*DD*DD, DDl,
        bv, nullptr, tmp, nullptr, nullptr, DDl, DD, 0);
    transpose_split<<<dim3(4,64,NB), tb>>>(tmp, (long)TT*DD, (long)HD, DDl,
        vth, vtl, 16L*HD*TT, (long)HD*TT, (long)TT);

    // fused attention (scale folded into q)
    flash_attn<<<dim3(16, 32), blk, SMEMF>>>(qh, ql, kh, kl, vth, vtl, ah, al);

    // out proj (fp32 + split)
    gemm_t3<<<gproj, blk, SMEMSZ>>>(ah, al, DDl, wth + 3ULL*DD*DD, wtl + 3ULL*DD*DD, DDl,
        bo, nullptr, of, oh, ol, DDl, DD, 2);
    // gate: out = of * sigmoid(o @ wg + bg)
    gemm_t3<<<gproj, blk, SMEMSZ>>>(oh, ol, DDl, wth + 4ULL*DD*DD, wtl + 4ULL*DD*DD, DDl,
        bg, of, out, nullptr, nullptr, DDl, DD, 3);
}

// round 8
// speedup vs baseline: 4.0978x; 1.2253x over previous
#include <cuda_runtime.h>
#include <cuda_bf16.h>
#include <cuda_fp16.h>
#include <cstdint>
#include <math.h>

#define BB 2
#define TT 2048
#define DD 2048
#define HH 16
#define HD 128
#define MROWS (BB*TT)     // 4096
#define NB (BB*HH)        // 32

typedef __nv_bfloat16 bf16;
typedef __half fp16;

// ---------------- scratch (device globals; allocation-free rule) ----------
__device__ fp16  g_xh[(size_t)MROWS*DD], g_xl[(size_t)MROWS*DD];
__device__ fp16  g_wt[5ULL*DD*DD];                               // transposed fp16 weights
__device__ float g_tmp[(size_t)MROWS*DD];                        // fp32 proj out
__device__ bf16  g_qh[(size_t)MROWS*DD], g_ql[(size_t)MROWS*DD];
__device__ bf16  g_kh[(size_t)MROWS*DD], g_kl[(size_t)MROWS*DD];
__device__ bf16  g_vth[(size_t)NB*HD*TT], g_vtl[(size_t)NB*HD*TT]; // v^T [b,h,d,t]
__device__ fp16  g_ah[(size_t)MROWS*DD], g_al[(size_t)MROWS*DD]; // attn hi/lo (fp16)
__device__ float g_of[(size_t)MROWS*DD];
__device__ fp16  g_oh[(size_t)MROWS*DD], g_ol[(size_t)MROWS*DD];

// ---------------- PTX helpers (plain sm_80+ PTX only) ---------------------
__device__ __forceinline__ uint32_t smem_u32(const void* p) {
    uint32_t a;
    asm("{ .reg .u64 t; cvta.to.shared.u64 t, %1; cvt.u32.u64 %0, t; }" : "=r"(a) : "l"(p));
    return a;
}
__device__ __forceinline__ void cpa16(uint32_t s, const void* g) {
    asm volatile("cp.async.cg.shared.global [%0], [%1], 16;" :: "r"(s), "l"(g));
}
#define CP_COMMIT()  asm volatile("cp.async.commit_group;" ::: "memory")

__device__ __forceinline__ void ldsm4(uint32_t* r, uint32_t a) {
    asm volatile("ldmatrix.sync.aligned.m8n8.x4.shared.b16 {%0,%1,%2,%3}, [%4];"
        : "=r"(r[0]), "=r"(r[1]), "=r"(r[2]), "=r"(r[3]) : "r"(a));
}
__device__ __forceinline__ void mma16816(float* c, const uint32_t* a, const uint32_t* b) {
    asm volatile("mma.sync.aligned.m16n8k16.row.col.f32.bf16.bf16.f32 "
        "{%0,%1,%2,%3}, {%4,%5,%6,%7}, {%8,%9}, {%0,%1,%2,%3};"
        : "+f"(c[0]), "+f"(c[1]), "+f"(c[2]), "+f"(c[3])
        : "r"(a[0]), "r"(a[1]), "r"(a[2]), "r"(a[3]), "r"(b[0]), "r"(b[1]));
}
__device__ __forceinline__ void mma16816h(float* c, const uint32_t* a, const uint32_t* b) {
    asm volatile("mma.sync.aligned.m16n8k16.row.col.f32.f16.f16.f32 "
        "{%0,%1,%2,%3}, {%4,%5,%6,%7}, {%8,%9}, {%0,%1,%2,%3};"
        : "+f"(c[0]), "+f"(c[1]), "+f"(c[2]), "+f"(c[3])
        : "r"(a[0]), "r"(a[1]), "r"(a[2]), "r"(a[3]), "r"(b[0]), "r"(b[1]));
}
__device__ __forceinline__ uint32_t sw_addr(uint32_t base, int row, int ch) {
    uint32_t off = (uint32_t)(row*128 + ch*16);
    return base + (off ^ ((off >> 3) & 0x70u));
}
__device__ __forceinline__ uint32_t packsplit(float a, float b, uint32_t& lo) {
    bf16 ha = __float2bfloat16(a), hb = __float2bfloat16(b);
    bf16 la = __float2bfloat16(a - __bfloat162float(ha));
    bf16 lb = __float2bfloat16(b - __bfloat162float(hb));
    __nv_bfloat162 H(ha, hb), L(la, lb);
    lo = *(uint32_t*)&L;
    return *(uint32_t*)&H;
}
__device__ __forceinline__ uint32_t packsplit_h(float a, float b, uint32_t& lo) {
    fp16 ha = __float2half_rn(a), hb = __float2half_rn(b);
    fp16 la = __float2half_rn(a - __half2float(ha));
    fp16 lb = __float2half_rn(b - __half2float(hb));
    __half2 H(ha, hb), L(la, lb);
    lo = *(uint32_t*)&L;
    return *(uint32_t*)&H;
}

// ============ 256x128x64 GEMM (fp16, A split-2, B plain) ====================
// stage layout (80KB): Ah 32KB | Al 32KB | B 16KB
#define STG_SZ 81920

__device__ __forceinline__ void ld_stage256(uint32_t sb,
    const fp16* Ah, const fp16* Al, long lda,
    const fp16* B, long ldb,
    int m0, int n0, int k0, int tid)
{
    #pragma unroll
    for (int t = 0; t < 20; t++) {
        int i = tid + t*256;
        if (i < 4096) {                       // A hi/lo: 256 rows x 128B each
            int half = i >> 11, j = i & 2047;
            int r = j >> 3, ch = j & 7;
            uint32_t off = (uint32_t)(r*128 + ch*16);
            uint32_t sw = off ^ ((off >> 3) & 0x70u);
            const fp16* src = (half ? Al : Ah) + (size_t)(m0 + r)*lda + k0 + ch*8;
            cpa16(sb + half*32768 + sw, src);
        } else {                              // B: 128 rows x 128B
            int j = i - 4096;
            int r = j >> 3, ch = j & 7;
            uint32_t off = (uint32_t)(r*128 + ch*16);
            uint32_t sw = off ^ ((off >> 3) & 0x70u);
            const fp16* src = B + (size_t)(n0 + r)*ldb + k0 + ch*8;
            cpa16(sb + 65536 + sw, src);
        }
    }
    CP_COMMIT();
}

// epi: 0 = fp32 (+bias), 2 = fp32 + fp16 split, 3 = gate
__global__ __launch_bounds__(256, 1) void gemm_h2(
    const fp16* __restrict__ Ah, const fp16* __restrict__ Al, long lda,
    const fp16* __restrict__ B, long ldb,
    const float* __restrict__ bias, const float* __restrict__ mul,
    float* __restrict__ Cf, fp16* __restrict__ Ch, fp16* __restrict__ Cl,
    long ldc, int K, int epi)
{
    extern __shared__ __align__(16) uint8_t dyns[];
    const int tid = threadIdx.x;
    uint32_t raw = smem_u32(dyns);
    uint32_t sb0 = (raw + 1023u) & ~1023u;
    uint32_t pad = sb0 - raw;

    const int m0 = blockIdx.y * 256, n0 = blockIdx.x * 128;
    const int lane = tid & 31, wid = tid >> 5;
    const int wm = wid >> 1, wn = wid & 1;       // 4 x 2 warps, each 64x64
    const int g8 = lane & 7, q = lane >> 3;

    float c[4][8][4];
    #pragma unroll
    for (int i = 0; i < 4; i++)
        #pragma unroll
        for (int j = 0; j < 8; j++)
            #pragma unroll
            for (int e = 0; e < 4; e++) c[i][j][e] = 0.f;

    const int nch = K >> 6;
    ld_stage256(sb0, Ah, Al, lda, B, ldb, m0, n0, 0, tid);

    for (int cc = 0; cc < nch; cc++) {
        const int s = cc & 1;
        const uint32_t sbs = sb0 + s*STG_SZ;
        if (cc + 1 < nch) {
            ld_stage256(sb0 + (s^1)*STG_SZ, Ah, Al, lda, B, ldb, m0, n0, (cc+1)*64, tid);
            asm volatile("cp.async.wait_group 1;" ::: "memory");
        } else {
            asm volatile("cp.async.wait_group 0;" ::: "memory");
        }
        __syncthreads();

        #pragma unroll
        for (int k16 = 0; k16 < 4; k16++) {
            uint32_t bh[8][2];
            #pragma unroll
            for (int nj = 0; nj < 4; nj++) {
                int row = wn*64 + nj*16 + g8 + ((q >> 1) << 3);
                int ch  = k16*2 + (q & 1);
                uint32_t r4[4];
                ldsm4(r4, sw_addr(sbs + 65536, row, ch));
                bh[2*nj][0] = r4[0]; bh[2*nj][1] = r4[1];
                bh[2*nj+1][0] = r4[2]; bh[2*nj+1][1] = r4[3];
            }
            #pragma unroll
            for (int mi = 0; mi < 4; mi++) {
                int row = wm*64 + mi*16 + g8 + ((q & 1) << 3);
                int ch  = k16*2 + (q >> 1);
                uint32_t a = sw_addr(sbs, row, ch);
                uint32_t ah4[4], al4[4];
                ldsm4(ah4, a);
                ldsm4(al4, a + 32768);
                #pragma unroll
                for (int ni = 0; ni < 8; ni++) {
                    mma16816h(c[mi][ni], ah4, bh[ni]);
                    mma16816h(c[mi][ni], al4, bh[ni]);
                }
            }
        }
        __syncthreads();
    }

    // ---- epilogue: frags -> padded fp32 smem [256][132] -> coalesced gmem ----
    float* smemf = (float*)(dyns + pad);
    {
        const int gid = lane >> 2, tig = lane & 3;
        #pragma unroll
        for (int mi = 0; mi < 4; mi++)
            #pragma unroll
            for (int ni = 0; ni < 8; ni++) {
                int r0 = wm*64 + mi*16 + gid;
                int col = wn*64 + ni*8 + tig*2;
                *(float2*)&smemf[r0*132 + col]     = make_float2(c[mi][ni][0], c[mi][ni][1]);
                *(float2*)&smemf[(r0+8)*132 + col] = make_float2(c[mi][ni][2], c[mi][ni][3]);
            }
    }
    __syncthreads();

    for (int v = tid; v < 8192; v += 256) {
        const int row = v >> 5, c4 = (v & 31) << 2;
        float4 val = *(const float4*)&smemf[row*132 + c4];
        const int gc = n0 + c4;
        const size_t go = (size_t)(m0 + row)*ldc + gc;
        if (bias) {
            val.x += bias[gc]; val.y += bias[gc+1]; val.z += bias[gc+2]; val.w += bias[gc+3];
        }
        if (epi == 0) {
            *(float4*)&Cf[go] = val;
        } else if (epi == 2) {
            *(float4*)&Cf[go] = val;
            uint32_t l0, l1;
            uint32_t h0 = packsplit_h(val.x, val.y, l0);
            uint32_t h1 = packsplit_h(val.z, val.w, l1);
            *(uint32_t*)&Ch[go]   = h0; *(uint32_t*)&Ch[go+2] = h1;
            *(uint32_t*)&Cl[go]   = l0; *(uint32_t*)&Cl[go+2] = l1;
        } else {  // gate
            const float4 m = *(const float4*)&mul[go];
            float4 o;
            o.x = m.x / (1.0f + __expf(-val.x));
            o.y = m.y / (1.0f + __expf(-val.y));
            o.z = m.z / (1.0f + __expf(-val.z));
            o.w = m.w / (1.0f + __expf(-val.w));
            *(float4*)&Cf[go] = o;
        }
    }
}

// ---------------- flash attention KV stage loader --------------------------
__device__ __forceinline__ void flash_ldkv(uint32_t stg, int kc0,
    const bf16* Kh, const bf16* Kl, const bf16* Vh, const bf16* Vl, int tid)
{
    #pragma unroll
    for (int t = 0; t < 16; t++) {
        int i = tid + t*256;
        if (i < 2048) {
            int p = i >> 9, j = i & 511;
            int r = j >> 3, ch = j & 7;
            uint32_t off = (uint32_t)(r*128 + ch*16);
            uint32_t sw = off ^ ((off >> 3) & 0x70u);
            const bf16* src = ((p < 2) ? Kh : Kl) + (size_t)(kc0 + r)*DD + (p & 1)*64 + ch*8;
            cpa16(stg + (p >> 1)*16384 + (p & 1)*8192 + sw, src);
        } else {
            int ii = i - 2048;
            int hi = ii >> 10, j = ii & 1023;
            int r = j >> 3, ch = j & 7;
            uint32_t off = (uint32_t)(r*128 + ch*16);
            uint32_t sw = off ^ ((off >> 3) & 0x70u);
            const bf16* src = (hi ? Vl : Vh) + (size_t)r*TT + kc0 + ch*8;
            cpa16(stg + 32768 + hi*16384 + sw, src);
        }
    }
    CP_COMMIT();
}

// ---------------- fused flash attention ------------------------------------
__global__ __launch_bounds__(256, 1) void flash_attn(
    const bf16* __restrict__ qh, const bf16* __restrict__ ql,
    const bf16* __restrict__ kh, const bf16* __restrict__ kl,
    const bf16* __restrict__ vth, const bf16* __restrict__ vtl,
    fp16* __restrict__ ah, fp16* __restrict__ al)
{
    extern __shared__ __align__(16) uint8_t dyns[];
    const int tid = threadIdx.x;
    uint32_t raw = smem_u32(dyns);
    uint32_t sb0 = (raw + 1023u) & ~1023u;
    uint32_t pad = sb0 - raw;

    const int qt = blockIdx.x;
    const int bh = blockIdx.y;
    const int b = bh >> 4, h = bh & 15;

    const bf16* Qh = qh + ((size_t)(b*TT) + qt*128)*DD + h*HD;
    const bf16* Ql = ql + ((size_t)(b*TT) + qt*128)*DD + h*HD;
    const bf16* Kh = kh + (size_t)(b*TT)*DD + h*HD;
    const bf16* Kl = kl + (size_t)(b*TT)*DD + h*HD;
    const bf16* Vh = vth + (size_t)bh*HD*TT;
    const bf16* Vl = vtl + (size_t)bh*HD*TT;

    const int lane = tid & 31, wid = tid >> 5;
    const int g8 = lane & 7, q2 = lane >> 3;
    const int gid = lane >> 2, tig = lane & 3;

    #pragma unroll
    for (int t = 0; t < 16; t++) {
        int i = tid + t*256;
        int half = i >> 11, j = i & 2047;
        int pd = j >> 10, jj = j & 1023;
        int r = jj >> 3, ch = jj & 7;
        uint32_t off = (uint32_t)(r*128 + ch*16);
        uint32_t sw = off ^ ((off >> 3) & 0x70u);
        const bf16* src = (half ? Ql : Qh) + (size_t)r*DD + pd*64 + ch*8;
        cpa16(sb0 + half*32768 + pd*16384 + sw, src);
    }
    CP_COMMIT();
    flash_ldkv(sb0 + 65536,  0, Kh, Kl, Vh, Vl, tid);
    flash_ldkv(sb0 + 131072, 64, Kh, Kl, Vh, Vl, tid);

    float c_o[16][4];
    #pragma unroll
    for (int i = 0; i < 16; i++)
        #pragma unroll
        for (int e = 0; e < 4; e++) c_o[i][e] = 0.f;
    float m0 = -1e30f, m1 = -1e30f, l0 = 0.f, l1 = 0.f;

    for (int t = 0; t < 32; t++) {
        if (t < 31) asm volatile("cp.async.wait_group 1;" ::: "memory");
        else        asm volatile("cp.async.wait_group 0;" ::: "memory");
        __syncthreads();
        const uint32_t stg = sb0 + 65536 + (t & 1)*65536;

        float c_s[8][4];
        #pragma unroll
        for (int i = 0; i < 8; i++)
            #pragma unroll
            for (int e = 0; e < 4; e++) c_s[i][e] = 0.f;

        #pragma unroll
        for (int k16 = 0; k16 < 8; k16++) {
            const int pd = k16 >> 2;
            uint32_t qa = sw_addr(sb0 + pd*16384, wid*16 + g8 + ((q2 & 1) << 3),
                                  (k16 & 3)*2 + (q2 >> 1));
            uint32_t qah[4], qal[4];
            ldsm4(qah, qa);
            ldsm4(qal, qa + 32768);
            uint32_t kbh[8][2], kbl[8][2];
            #pragma unroll
            for (int nj = 0; nj < 4; nj++) {
                uint32_t ka = sw_addr(stg + pd*8192, nj*16 + g8 + ((q2 >> 1) << 3),
                                      (k16 & 3)*2 + (q2 & 1));
                uint32_t r4[4];
                ldsm4(r4, ka);
                kbh[2*nj][0] = r4[0]; kbh[2*nj][1] = r4[1];
                kbh[2*nj+1][0] = r4[2]; kbh[2*nj+1][1] = r4[3];
                ldsm4(r4, ka + 16384);
                kbl[2*nj][0] = r4[0]; kbl[2*nj][1] = r4[1];
                kbl[2*nj+1][0] = r4[2]; kbl[2*nj+1][1] = r4[3];
            }
            #pragma unroll
            for (int nj = 0; nj < 8; nj++) {
                mma16816(c_s[nj], qah, kbh[nj]);
                mma16816(c_s[nj], qal, kbh[nj]);
                mma16816(c_s[nj], qah, kbl[nj]);
            }
        }

        float tm0 = -1e30f, tm1 = -1e30f;
        #pragma unroll
        for (int nj = 0; nj < 8; nj++) {
            tm0 = fmaxf(tm0, fmaxf(c_s[nj][0], c_s[nj][1]));
            tm1 = fmaxf(tm1, fmaxf(c_s[nj][2], c_s[nj][3]));
        }
        tm0 = fmaxf(tm0, __shfl_xor_sync(0xffffffffu, tm0, 1));
        tm0 = fmaxf(tm0, __shfl_xor_sync(0xffffffffu, tm0, 2));
        tm1 = fmaxf(tm1, __shfl_xor_sync(0xffffffffu, tm1, 1));
        tm1 = fmaxf(tm1, __shfl_xor_sync(0xffffffffu, tm1, 2));
        const float mn0 = fmaxf(m0, tm0), mn1 = fmaxf(m1, tm1);
        const float a0 = __expf(m0 - mn0), a1 = __expf(m1 - mn1);
        float rs0 = 0.f, rs1 = 0.f;
        #pragma unroll
        for (int nj = 0; nj < 8; nj++) {
            c_s[nj][0] = __expf(c_s[nj][0] - mn0);
            c_s[nj][1] = __expf(c_s[nj][1] - mn0);
            c_s[nj][2] = __expf(c_s[nj][2] - mn1);
            c_s[nj][3] = __expf(c_s[nj][3] - mn1);
            rs0 += c_s[nj][0] + c_s[nj][1];
            rs1 += c_s[nj][2] + c_s[nj][3];
        }
        rs0 += __shfl_xor_sync(0xffffffffu, rs0, 1);
        rs0 += __shfl_xor_sync(0xffffffffu, rs0, 2);
        rs1 += __shfl_xor_sync(0xffffffffu, rs1, 1);
        rs1 += __shfl_xor_sync(0xffffffffu, rs1, 2);
        l0 = l0*a0 + rs0;  l1 = l1*a1 + rs1;
        m0 = mn0;          m1 = mn1;
        #pragma unroll
        for (int nb = 0; nb < 16; nb++) {
            c_o[nb][0] *= a0; c_o[nb][1] *= a0;
            c_o[nb][2] *= a1; c_o[nb][3] *= a1;
        }

        #pragma unroll
        for (int kb = 0; kb < 4; kb++) {
            uint32_t pah[4], pal[4];
            pah[0] = packsplit(c_s[2*kb][0],   c_s[2*kb][1],   pal[0]);
            pah[1] = packsplit(c_s[2*kb][2],   c_s[2*kb][3],   pal[1]);
            pah[2] = packsplit(c_s[2*kb+1][0], c_s[2*kb+1][1], pal[2]);
            pah[3] = packsplit(c_s[2*kb+1][2], c_s[2*kb+1][3], pal[3]);
            #pragma unroll
            for (int nj2 = 0; nj2 < 8; nj2++) {
                uint32_t va = sw_addr(stg + 32768, nj2*16 + g8 + ((q2 >> 1) << 3),
                                      kb*2 + (q2 & 1));
                uint32_t vh4[4], vl4[4];
                ldsm4(vh4, va);
                ldsm4(vl4, va + 16384);
                uint32_t b0[2] = {vh4[0], vh4[1]}, b1[2] = {vh4[2], vh4[3]};
                uint32_t c0[2] = {vl4[0], vl4[1]}, c1[2] = {vl4[2], vl4[3]};
                mma16816(c_o[2*nj2],   pah, b0);
                mma16816(c_o[2*nj2],   pal, b0);
                mma16816(c_o[2*nj2],   pah, c0);
                mma16816(c_o[2*nj2+1], pah, b1);
                mma16816(c_o[2*nj2+1], pal, b1);
                mma16816(c_o[2*nj2+1], pah, c1);
            }
        }

        __syncthreads();
        if (t + 2 < 32)
            flash_ldkv(sb0 + 65536 + (t & 1)*65536, (t+2)*64, Kh, Kl, Vh, Vl, tid);
    }

    float* smemf = (float*)(dyns + pad + 65536);
    {
        const float r0i = 1.0f / l0, r1i = 1.0f / l1;
        const int row0 = wid*16 + gid, row1 = row0 + 8;
        #pragma unroll
        for (int nb = 0; nb < 16; nb++) {
            const int col = nb*8 + tig*2;
            smemf[row0*132 + col]     = c_o[nb][0]*r0i;
            smemf[row0*132 + col + 1] = c_o[nb][1]*r0i;
            smemf[row1*132 + col]     = c_o[nb][2]*r1i;
            smemf[row1*132 + col + 1] = c_o[nb][3]*r1i;
        }
    }
    __syncthreads();
    for (int v = tid; v < 4096; v += 256) {
        const int row = v >> 5, c4 = (v & 31) << 2;
        float4 val = *(const float4*)&smemf[row*132 + c4];
        const size_t go = ((size_t)(b*TT) + qt*128 + row)*DD + h*HD + c4;
        uint32_t lo0, lo1;
        uint32_t hi0 = packsplit_h(val.x, val.y, lo0);
        uint32_t hi1 = packsplit_h(val.z, val.w, lo1);
        *(uint32_t*)&ah[go]   = hi0; *(uint32_t*)&ah[go+2] = hi1;
        *(uint32_t*)&al[go]   = lo0; *(uint32_t*)&al[go+2] = lo1;
    }
}

// ---------------- elementwise split: fp32 -> fp16 hi/lo -------------------
__global__ __launch_bounds__(256) void split4h(const float* __restrict__ in,
    fp16* __restrict__ oh, fp16* __restrict__ ol, int n4)
{
    int i = blockIdx.x*256 + threadIdx.x;
    if (i >= n4) return;
    float4 v = ((const float4*)in)[i];
    uint32_t l0, l1;
    uint32_t h0 = packsplit_h(v.x, v.y, l0);
    uint32_t h1 = packsplit_h(v.z, v.w, l1);
    ((uint32_t*)oh)[i*2]   = h0; ((uint32_t*)oh)[i*2+1] = h1;
    ((uint32_t*)ol)[i*2]   = l0; ((uint32_t*)ol)[i*2+1] = l1;
}

// ---------------- weight transpose -> plain fp16 ---------------------------
__global__ void transpose_h(const float* __restrict__ in, fp16* __restrict__ out, int n)
{
    __shared__ float t[32][33];
    const float* pin = in;
    const int r0 = blockIdx.y*32, c0 = blockIdx.x*32;
    const int tx = threadIdx.x, ty = threadIdx.y;
    #pragma unroll
    for (int i = 0; i < 32; i += 8)
        t[ty+i][tx] = pin[(size_t)(r0+ty+i)*n + c0+tx];
    __syncthreads();
    #pragma unroll
    for (int i = 0; i < 32; i += 8)
        out[(size_t)(c0+ty+i)*n + r0 + tx] = __float2half_rn(t[tx][ty+i]);
}

// ---------------- transpose + split (bf16, for V) --------------------------
__global__ void transpose_split(const float* __restrict__ in, long izb, long izh, long ldin,
                                bf16* __restrict__ oh, bf16* __restrict__ ol,
                                long ozb, long ozh, long ldout)
{
    __shared__ float t[32][33];
    const int z = blockIdx.z, zb = z >> 4, zh = z & 15;
    const float* pin = in + (size_t)zb*izb + (size_t)zh*izh;
    bf16* poh = oh + (size_t)zb*ozb + (size_t)zh*ozh;
    bf16* pol = ol + (size_t)zb*ozb + (size_t)zh*ozh;
    const int r0 = blockIdx.y*32, c0 = blockIdx.x*32;
    const int tx = threadIdx.x, ty = threadIdx.y;
    #pragma unroll
    for (int i = 0; i < 32; i += 8)
        t[ty+i][tx] = pin[(size_t)(r0+ty+i)*ldin + c0+tx];
    __syncthreads();
    #pragma unroll
    for (int i = 0; i < 32; i += 8) {
        float vv = t[tx][ty+i];
        size_t o = (size_t)(c0+ty+i)*ldout + r0 + tx;
        bf16 h = __float2bfloat16(vv);
        poh[o] = h;
        pol[o] = __float2bfloat16(vv - __bfloat162float(h));
    }
}

// ---------------- fused rmsnorm + rope -> split bf16 -----------------------
__global__ __launch_bounds__(256) void rmsnorm_rope_split(
    const float* __restrict__ in, const float* __restrict__ g,
    const float* __restrict__ cosp, const float* __restrict__ sinp,
    float scale, bf16* __restrict__ oh, bf16* __restrict__ ol)
{
    __shared__ float s[DD];
    __shared__ float red[8];
    const int row = blockIdx.x;
    const int t = row & (TT - 1);
    const float* p = in + (size_t)row * DD;
    const int tid = threadIdx.x;

    float ss = 0.f;
    for (int c = tid; c < DD; c += 256) { float x = p[c]; s[c] = x; ss += x*x; }
    #pragma unroll
    for (int o = 16; o > 0; o >>= 1) ss += __shfl_xor_sync(0xffffffffu, ss, o);
    if ((tid & 31) == 0) red[tid >> 5] = ss;
    __syncthreads();
    float tot = red[0]+red[1]+red[2]+red[3]+red[4]+red[5]+red[6]+red[7];
    const float inv = rsqrtf(tot * (1.0f / (float)DD) + 1e-6f);

    for (int c = tid; c < DD; c += 256) {
        const int pidx = c & 127;
        const int base = c - pidx;
        float o;
        if (pidx < 64) {
            float x1 = s[c] * inv * g[c];
            float x2 = s[base + 64 + pidx] * inv * g[base + 64 + pidx];
            o = x1 * cosp[t*64 + pidx] - sinp[t*64 + pidx] * x2;
        } else {
            const int pp = pidx - 64;
            float x2 = s[c] * inv * g[c];
            float x1 = s[base + pp] * inv * g[base + pp];
            o = x2 * cosp[t*64 + pp] + sinp[t*64 + pp] * x1;
        }
        o *= scale;
        bf16 h = __float2bfloat16(o);
        oh[(size_t)row*DD + c] = h;
        ol[(size_t)row*DD + c] = __float2bfloat16(o - __bfloat162float(h));
    }
}

// ---------------------------------------------------------------------------
extern "C" void kernel_launch(void* const* d_in, const int* in_sizes, int n_in,
                              void* d_out, int out_size)
{
    const float* x    = (const float*)d_in[0];
    const float* cosp = (const float*)d_in[1];
    const float* sinp = (const float*)d_in[2];
    const float* w[5] = { (const float*)d_in[3], (const float*)d_in[5],
                          (const float*)d_in[7], (const float*)d_in[11],
                          (const float*)d_in[13] };
    const float* bq = (const float*)d_in[4];
    const float* bk = (const float*)d_in[6];
    const float* bv = (const float*)d_in[8];
    const float* gq = (const float*)d_in[9];
    const float* gk = (const float*)d_in[10];
    const float* bo = (const float*)d_in[12];
    const float* bg = (const float*)d_in[14];
    float* out = (float*)d_out;

    fp16 *xh, *xl, *wt, *ah, *al, *oh, *ol;
    bf16 *qh, *ql, *kh, *kl, *vth, *vtl;
    float *tmp, *of;
    cudaGetSymbolAddress((void**)&xh, g_xh);   cudaGetSymbolAddress((void**)&xl, g_xl);
    cudaGetSymbolAddress((void**)&wt, g_wt);
    cudaGetSymbolAddress((void**)&tmp, g_tmp);
    cudaGetSymbolAddress((void**)&qh, g_qh);   cudaGetSymbolAddress((void**)&ql, g_ql);
    cudaGetSymbolAddress((void**)&kh, g_kh);   cudaGetSymbolAddress((void**)&kl, g_kl);
    cudaGetSymbolAddress((void**)&vth, g_vth); cudaGetSymbolAddress((void**)&vtl, g_vtl);
    cudaGetSymbolAddress((void**)&ah, g_ah);   cudaGetSymbolAddress((void**)&al, g_al);
    cudaGetSymbolAddress((void**)&of, g_of);
    cudaGetSymbolAddress((void**)&oh, g_oh);   cudaGetSymbolAddress((void**)&ol, g_ol);

    const int SMEMSZ  = 2*STG_SZ + 1024;          // gemm_h2 (256x128, fp16)
    const int SMEMF   = 3*65536 + 1024;           // flash
    cudaFuncSetAttribute(gemm_h2, cudaFuncAttributeMaxDynamicSharedMemorySize, SMEMSZ);
    cudaFuncSetAttribute(flash_attn, cudaFuncAttributeMaxDynamicSharedMemorySize, SMEMF);

    dim3 blk(256), tb(32, 8);
    const long DDl = DD;

    // input + weight prep
    split4h<<<(MROWS*DD/4 + 255)/256, blk>>>(x, xh, xl, MROWS*DD/4);
    for (int i = 0; i < 5; i++)
        transpose_h<<<dim3(64,64,1), tb>>>(w[i], wt + (size_t)i*DD*DD, DD);

    dim3 gproj(DD/128, MROWS/256, 1);   // (16, 16)

    // Q
    gemm_h2<<<gproj, blk, SMEMSZ>>>(xh, xl, DDl, wt, DDl,
        bq, nullptr, tmp, nullptr, nullptr, DDl, DD, 0);
    rmsnorm_rope_split<<<MROWS, blk>>>(tmp, gq, cosp, sinp, 0.08838834764831845f, qh, ql);
    // K
    gemm_h2<<<gproj, blk, SMEMSZ>>>(xh, xl, DDl, wt + (size_t)DD*DD, DDl,
        bk, nullptr, tmp, nullptr, nullptr, DDl, DD, 0);
    rmsnorm_rope_split<<<MROWS, blk>>>(tmp, gk, cosp, sinp, 1.0f, kh, kl);
    // V (+ transpose to [b,h,d,t])
    gemm_h2<<<gproj, blk, SMEMSZ>>>(xh, xl, DDl, wt + 2ULL*DD*DD, DDl,
        bv, nullptr, tmp, nullptr, nullptr, DDl, DD, 0);
    transpose_split<<<dim3(4,64,NB), tb>>>(tmp, (long)TT*DD, (long)HD, DDl,
        vth, vtl, 16L*HD*TT, (long)HD*TT, (long)TT);

    // fused attention (scale folded into q)
    flash_attn<<<dim3(16, 32), blk, SMEMF>>>(qh, ql, kh, kl, vth, vtl, ah, al);

    // out proj (fp32 + fp16 split)
    gemm_h2<<<gproj, blk, SMEMSZ>>>(ah, al, DDl, wt + 3ULL*DD*DD, DDl,
        bo, nullptr, of, oh, ol, DDl, DD, 2);
    // gate: out = of * sigmoid(o @ wg + bg)
    gemm_h2<<<gproj, blk, SMEMSZ>>>(oh, ol, DDl, wt + 4ULL*DD*DD, DDl,
        bg, of, out, nullptr, nullptr, DDl, DD, 3);
}

// round 9
// speedup vs baseline: 4.5507x; 1.1105x over previous
#include <cuda_runtime.h>
#include <cuda_bf16.h>
#include <cuda_fp16.h>
#include <cstdint>
#include <math.h>

#define BB 2
#define TT 2048
#define DD 2048
#define HH 16
#define HD 128
#define MROWS (BB*TT)     // 4096
#define NB (BB*HH)        // 32

typedef __nv_bfloat16 bf16;
typedef __half fp16;

// ---------------- scratch (device globals; allocation-free rule) ----------
__device__ fp16  g_xh[(size_t)MROWS*DD], g_xl[(size_t)MROWS*DD];
__device__ fp16  g_wt[5ULL*DD*DD];                               // transposed fp16 weights
__device__ float g_tmp[(size_t)MROWS*DD];                        // fp32 proj out
__device__ fp16  g_qh[(size_t)MROWS*DD], g_ql[(size_t)MROWS*DD];
__device__ fp16  g_kh[(size_t)MROWS*DD];                         // K plain fp16
__device__ fp16  g_vt[(size_t)NB*HD*TT];                         // v^T [b,h,d,t] plain fp16
__device__ fp16  g_ah[(size_t)MROWS*DD], g_al[(size_t)MROWS*DD]; // attn hi/lo (fp16)
__device__ float g_of[(size_t)MROWS*DD];
__device__ fp16  g_oh[(size_t)MROWS*DD], g_ol[(size_t)MROWS*DD];

// ---------------- PTX helpers (plain sm_80+ PTX only) ---------------------
__device__ __forceinline__ uint32_t smem_u32(const void* p) {
    uint32_t a;
    asm("{ .reg .u64 t; cvta.to.shared.u64 t, %1; cvt.u32.u64 %0, t; }" : "=r"(a) : "l"(p));
    return a;
}
__device__ __forceinline__ void cpa16(uint32_t s, const void* g) {
    asm volatile("cp.async.cg.shared.global [%0], [%1], 16;" :: "r"(s), "l"(g));
}
#define CP_COMMIT()  asm volatile("cp.async.commit_group;" ::: "memory")

__device__ __forceinline__ void ldsm4(uint32_t* r, uint32_t a) {
    asm volatile("ldmatrix.sync.aligned.m8n8.x4.shared.b16 {%0,%1,%2,%3}, [%4];"
        : "=r"(r[0]), "=r"(r[1]), "=r"(r[2]), "=r"(r[3]) : "r"(a));
}
__device__ __forceinline__ void mma16816h(float* c, const uint32_t* a, const uint32_t* b) {
    asm volatile("mma.sync.aligned.m16n8k16.row.col.f32.f16.f16.f32 "
        "{%0,%1,%2,%3}, {%4,%5,%6,%7}, {%8,%9}, {%0,%1,%2,%3};"
        : "+f"(c[0]), "+f"(c[1]), "+f"(c[2]), "+f"(c[3])
        : "r"(a[0]), "r"(a[1]), "r"(a[2]), "r"(a[3]), "r"(b[0]), "r"(b[1]));
}
__device__ __forceinline__ uint32_t sw_addr(uint32_t base, int row, int ch) {
    uint32_t off = (uint32_t)(row*128 + ch*16);
    return base + (off ^ ((off >> 3) & 0x70u));
}
__device__ __forceinline__ uint32_t packsplit_h(float a, float b, uint32_t& lo) {
    fp16 ha = __float2half_rn(a), hb = __float2half_rn(b);
    fp16 la = __float2half_rn(a - __half2float(ha));
    fp16 lb = __float2half_rn(b - __half2float(hb));
    __half2 H(ha, hb), L(la, lb);
    lo = *(uint32_t*)&L;
    return *(uint32_t*)&H;
}

// ============ 256x128x64 GEMM (fp16, A split-2, B plain) ====================
// stage layout (80KB): Ah 32KB | Al 32KB | B 16KB
#define STG_SZ 81920

__device__ __forceinline__ void ld_stage256(uint32_t sb,
    const fp16* Ah, const fp16* Al, long lda,
    const fp16* B, long ldb,
    int m0, int n0, int k0, int tid)
{
    #pragma unroll
    for (int t = 0; t < 20; t++) {
        int i = tid + t*256;
        if (i < 4096) {                       // A hi/lo: 256 rows x 128B each
            int half = i >> 11, j = i & 2047;
            int r = j >> 3, ch = j & 7;
            uint32_t off = (uint32_t)(r*128 + ch*16);
            uint32_t sw = off ^ ((off >> 3) & 0x70u);
            const fp16* src = (half ? Al : Ah) + (size_t)(m0 + r)*lda + k0 + ch*8;
            cpa16(sb + half*32768 + sw, src);
        } else {                              // B: 128 rows x 128B
            int j = i - 4096;
            int r = j >> 3, ch = j & 7;
            uint32_t off = (uint32_t)(r*128 + ch*16);
            uint32_t sw = off ^ ((off >> 3) & 0x70u);
            const fp16* src = B + (size_t)(n0 + r)*ldb + k0 + ch*8;
            cpa16(sb + 65536 + sw, src);
        }
    }
    CP_COMMIT();
}

// epi: 0 = fp32 (+bias), 2 = fp32 + fp16 split, 3 = gate
__global__ __launch_bounds__(256, 1) void gemm_h2(
    const fp16* __restrict__ Ah, const fp16* __restrict__ Al, long lda,
    const fp16* __restrict__ B, long ldb,
    const float* __restrict__ bias, const float* __restrict__ mul,
    float* __restrict__ Cf, fp16* __restrict__ Ch, fp16* __restrict__ Cl,
    long ldc, int K, int epi)
{
    extern __shared__ __align__(16) uint8_t dyns[];
    const int tid = threadIdx.x;
    uint32_t raw = smem_u32(dyns);
    uint32_t sb0 = (raw + 1023u) & ~1023u;
    uint32_t pad = sb0 - raw;

    const int m0 = blockIdx.y * 256, n0 = blockIdx.x * 128;
    const int lane = tid & 31, wid = tid >> 5;
    const int wm = wid >> 1, wn = wid & 1;       // 4 x 2 warps, each 64x64
    const int g8 = lane & 7, q = lane >> 3;

    float c[4][8][4];
    #pragma unroll
    for (int i = 0; i < 4; i++)
        #pragma unroll
        for (int j = 0; j < 8; j++)
            #pragma unroll
            for (int e = 0; e < 4; e++) c[i][j][e] = 0.f;

    const int nch = K >> 6;
    ld_stage256(sb0, Ah, Al, lda, B, ldb, m0, n0, 0, tid);

    for (int cc = 0; cc < nch; cc++) {
        const int s = cc & 1;
        const uint32_t sbs = sb0 + s*STG_SZ;
        if (cc + 1 < nch) {
            ld_stage256(sb0 + (s^1)*STG_SZ, Ah, Al, lda, B, ldb, m0, n0, (cc+1)*64, tid);
            asm volatile("cp.async.wait_group 1;" ::: "memory");
        } else {
            asm volatile("cp.async.wait_group 0;" ::: "memory");
        }
        __syncthreads();

        #pragma unroll
        for (int k16 = 0; k16 < 4; k16++) {
            uint32_t bh[8][2];
            #pragma unroll
            for (int nj = 0; nj < 4; nj++) {
                int row = wn*64 + nj*16 + g8 + ((q >> 1) << 3);
                int ch  = k16*2 + (q & 1);
                uint32_t r4[4];
                ldsm4(r4, sw_addr(sbs + 65536, row, ch));
                bh[2*nj][0] = r4[0]; bh[2*nj][1] = r4[1];
                bh[2*nj+1][0] = r4[2]; bh[2*nj+1][1] = r4[3];
            }
            #pragma unroll
            for (int mi = 0; mi < 4; mi++) {
                int row = wm*64 + mi*16 + g8 + ((q & 1) << 3);
                int ch  = k16*2 + (q >> 1);
                uint32_t a = sw_addr(sbs, row, ch);
                uint32_t ah4[4], al4[4];
                ldsm4(ah4, a);
                ldsm4(al4, a + 32768);
                #pragma unroll
                for (int ni = 0; ni < 8; ni++) {
                    mma16816h(c[mi][ni], ah4, bh[ni]);
                    mma16816h(c[mi][ni], al4, bh[ni]);
                }
            }
        }
        __syncthreads();
    }

    // ---- epilogue: frags -> padded fp32 smem [256][132] -> coalesced gmem ----
    float* smemf = (float*)(dyns + pad);
    {
        const int gid = lane >> 2, tig = lane & 3;
        #pragma unroll
        for (int mi = 0; mi < 4; mi++)
            #pragma unroll
            for (int ni = 0; ni < 8; ni++) {
                int r0 = wm*64 + mi*16 + gid;
                int col = wn*64 + ni*8 + tig*2;
                *(float2*)&smemf[r0*132 + col]     = make_float2(c[mi][ni][0], c[mi][ni][1]);
                *(float2*)&smemf[(r0+8)*132 + col] = make_float2(c[mi][ni][2], c[mi][ni][3]);
            }
    }
    __syncthreads();

    for (int v = tid; v < 8192; v += 256) {
        const int row = v >> 5, c4 = (v & 31) << 2;
        float4 val = *(const float4*)&smemf[row*132 + c4];
        const int gc = n0 + c4;
        const size_t go = (size_t)(m0 + row)*ldc + gc;
        if (bias) {
            val.x += bias[gc]; val.y += bias[gc+1]; val.z += bias[gc+2]; val.w += bias[gc+3];
        }
        if (epi == 0) {
            *(float4*)&Cf[go] = val;
        } else if (epi == 2) {
            *(float4*)&Cf[go] = val;
            uint32_t l0, l1;
            uint32_t h0 = packsplit_h(val.x, val.y, l0);
            uint32_t h1 = packsplit_h(val.z, val.w, l1);
            *(uint32_t*)&Ch[go]   = h0; *(uint32_t*)&Ch[go+2] = h1;
            *(uint32_t*)&Cl[go]   = l0; *(uint32_t*)&Cl[go+2] = l1;
        } else {  // gate
            const float4 m = *(const float4*)&mul[go];
            float4 o;
            o.x = m.x / (1.0f + __expf(-val.x));
            o.y = m.y / (1.0f + __expf(-val.y));
            o.z = m.z / (1.0f + __expf(-val.z));
            o.w = m.w / (1.0f + __expf(-val.w));
            *(float4*)&Cf[go] = o;
        }
    }
}

// ---------------- flash attention KV stage loader (plain fp16) -------------
// stage layout (32KB): K 2 panels of 8KB | V 16KB
__device__ __forceinline__ void flash_ldkv(uint32_t stg, int kc0,
    const fp16* K, const fp16* V, int tid)
{
    #pragma unroll
    for (int t = 0; t < 8; t++) {
        int i = tid + t*256;
        if (i < 1024) {                       // K: 64 rows x 2 panels x 128B
            int p = i >> 9, j = i & 511;
            int r = j >> 3, ch = j & 7;
            uint32_t off = (uint32_t)(r*128 + ch*16);
            uint32_t sw = off ^ ((off >> 3) & 0x70u);
            const fp16* src = K + (size_t)(kc0 + r)*DD + p*64 + ch*8;
            cpa16(stg + p*8192 + sw, src);
        } else {                              // V: 128 rows (d) x 64 t = 128B rows
            int j = i - 1024;
            int r = j >> 3, ch = j & 7;
            uint32_t off = (uint32_t)(r*128 + ch*16);
            uint32_t sw = off ^ ((off >> 3) & 0x70u);
            const fp16* src = V + (size_t)r*TT + kc0 + ch*8;
            cpa16(stg + 16384 + sw, src);
        }
    }
    CP_COMMIT();
}

// ---------------- fused flash attention (fp16 2-term) ----------------------
// grid (16 qtiles, 32 bh); 256 thr; 8 warps x 16 q-rows; kc tile = 64
__global__ __launch_bounds__(256, 1) void flash_attn(
    const fp16* __restrict__ qh, const fp16* __restrict__ ql,
    const fp16* __restrict__ kk, const fp16* __restrict__ vt,
    fp16* __restrict__ ah, fp16* __restrict__ al)
{
    extern __shared__ __align__(16) uint8_t dyns[];
    const int tid = threadIdx.x;
    uint32_t raw = smem_u32(dyns);
    uint32_t sb0 = (raw + 1023u) & ~1023u;
    uint32_t pad = sb0 - raw;

    const int qt = blockIdx.x;
    const int bh = blockIdx.y;
    const int b = bh >> 4, h = bh & 15;

    const fp16* Qh = qh + ((size_t)(b*TT) + qt*128)*DD + h*HD;
    const fp16* Ql = ql + ((size_t)(b*TT) + qt*128)*DD + h*HD;
    const fp16* K  = kk + (size_t)(b*TT)*DD + h*HD;
    const fp16* V  = vt + (size_t)bh*HD*TT;

    const int lane = tid & 31, wid = tid >> 5;
    const int g8 = lane & 7, q2 = lane >> 3;
    const int gid = lane >> 2, tig = lane & 3;

    // Q: 4 panels of 16KB (Qh p0, Qh p1 | Ql p0, Ql p1) at sb0..64KB
    #pragma unroll
    for (int t = 0; t < 16; t++) {
        int i = tid + t*256;
        int half = i >> 11, j = i & 2047;
        int pd = j >> 10, jj = j & 1023;
        int r = jj >> 3, ch = jj & 7;
        uint32_t off = (uint32_t)(r*128 + ch*16);
        uint32_t sw = off ^ ((off >> 3) & 0x70u);
        const fp16* src = (half ? Ql : Qh) + (size_t)r*DD + pd*64 + ch*8;
        cpa16(sb0 + half*32768 + pd*16384 + sw, src);
    }
    CP_COMMIT();
    flash_ldkv(sb0 + 65536, 0,  K, V, tid);
    flash_ldkv(sb0 + 98304, 64, K, V, tid);

    float c_o[16][4];
    #pragma unroll
    for (int i = 0; i < 16; i++)
        #pragma unroll
        for (int e = 0; e < 4; e++) c_o[i][e] = 0.f;
    float m0 = -1e30f, m1 = -1e30f, l0 = 0.f, l1 = 0.f;

    for (int t = 0; t < 32; t++) {
        if (t < 31) asm volatile("cp.async.wait_group 1;" ::: "memory");
        else        asm volatile("cp.async.wait_group 0;" ::: "memory");
        __syncthreads();
        const uint32_t stg = sb0 + 65536 + (t & 1)*32768;

        // ---- S = Q @ K^T (128 x 64, Q split-2, K plain) ----
        float c_s[8][4];
        #pragma unroll
        for (int i = 0; i < 8; i++)
            #pragma unroll
            for (int e = 0; e < 4; e++) c_s[i][e] = 0.f;

        #pragma unroll
        for (int k16 = 0; k16 < 8; k16++) {
            const int pd = k16 >> 2;
            uint32_t qa = sw_addr(sb0 + pd*16384, wid*16 + g8 + ((q2 & 1) << 3),
                                  (k16 & 3)*2 + (q2 >> 1));
            uint32_t qah[4], qal[4];
            ldsm4(qah, qa);
            ldsm4(qal, qa + 32768);
            uint32_t kbh[8][2];
            #pragma unroll
            for (int nj = 0; nj < 4; nj++) {
                uint32_t ka = sw_addr(stg + pd*8192, nj*16 + g8 + ((q2 >> 1) << 3),
                                      (k16 & 3)*2 + (q2 & 1));
                uint32_t r4[4];
                ldsm4(r4, ka);
                kbh[2*nj][0] = r4[0]; kbh[2*nj][1] = r4[1];
                kbh[2*nj+1][0] = r4[2]; kbh[2*nj+1][1] = r4[3];
            }
            #pragma unroll
            for (int nj = 0; nj < 8; nj++) {
                mma16816h(c_s[nj], qah, kbh[nj]);
                mma16816h(c_s[nj], qal, kbh[nj]);
            }
        }

        // ---- online softmax ----
        float tm0 = -1e30f, tm1 = -1e30f;
        #pragma unroll
        for (int nj = 0; nj < 8; nj++) {
            tm0 = fmaxf(tm0, fmaxf(c_s[nj][0], c_s[nj][1]));
            tm1 = fmaxf(tm1, fmaxf(c_s[nj][2], c_s[nj][3]));
        }
        tm0 = fmaxf(tm0, __shfl_xor_sync(0xffffffffu, tm0, 1));
        tm0 = fmaxf(tm0, __shfl_xor_sync(0xffffffffu, tm0, 2));
        tm1 = fmaxf(tm1, __shfl_xor_sync(0xffffffffu, tm1, 1));
        tm1 = fmaxf(tm1, __shfl_xor_sync(0xffffffffu, tm1, 2));
        const float mn0 = fmaxf(m0, tm0), mn1 = fmaxf(m1, tm1);
        const float a0 = __expf(m0 - mn0), a1 = __expf(m1 - mn1);
        float rs0 = 0.f, rs1 = 0.f;
        #pragma unroll
        for (int nj = 0; nj < 8; nj++) {
            c_s[nj][0] = __expf(c_s[nj][0] - mn0);
            c_s[nj][1] = __expf(c_s[nj][1] - mn0);
            c_s[nj][2] = __expf(c_s[nj][2] - mn1);
            c_s[nj][3] = __expf(c_s[nj][3] - mn1);
            rs0 += c_s[nj][0] + c_s[nj][1];
            rs1 += c_s[nj][2] + c_s[nj][3];
        }
        rs0 += __shfl_xor_sync(0xffffffffu, rs0, 1);
        rs0 += __shfl_xor_sync(0xffffffffu, rs0, 2);
        rs1 += __shfl_xor_sync(0xffffffffu, rs1, 1);
        rs1 += __shfl_xor_sync(0xffffffffu, rs1, 2);
        l0 = l0*a0 + rs0;  l1 = l1*a1 + rs1;
        m0 = mn0;          m1 = mn1;
        #pragma unroll
        for (int nb = 0; nb < 16; nb++) {
            c_o[nb][0] *= a0; c_o[nb][1] *= a0;
            c_o[nb][2] *= a1; c_o[nb][3] *= a1;
        }

        // ---- O += P @ V  (P split-2 in registers, V plain) ----
        #pragma unroll
        for (int kb = 0; kb < 4; kb++) {
            uint32_t pah[4], pal[4];
            pah[0] = packsplit_h(c_s[2*kb][0],   c_s[2*kb][1],   pal[0]);
            pah[1] = packsplit_h(c_s[2*kb][2],   c_s[2*kb][3],   pal[1]);
            pah[2] = packsplit_h(c_s[2*kb+1][0], c_s[2*kb+1][1], pal[2]);
            pah[3] = packsplit_h(c_s[2*kb+1][2], c_s[2*kb+1][3], pal[3]);
            #pragma unroll
            for (int nj2 = 0; nj2 < 8; nj2++) {
                uint32_t va = sw_addr(stg + 16384, nj2*16 + g8 + ((q2 >> 1) << 3),
                                      kb*2 + (q2 & 1));
                uint32_t vh4[4];
                ldsm4(vh4, va);
                uint32_t b0[2] = {vh4[0], vh4[1]}, b1[2] = {vh4[2], vh4[3]};
                mma16816h(c_o[2*nj2],   pah, b0);
                mma16816h(c_o[2*nj2],   pal, b0);
                mma16816h(c_o[2*nj2+1], pah, b1);
                mma16816h(c_o[2*nj2+1], pal, b1);
            }
        }

        __syncthreads();
        if (t + 2 < 32)
            flash_ldkv(sb0 + 65536 + (t & 1)*32768, (t+2)*64, K, V, tid);
    }

    // ---- epilogue: O/l -> padded fp32 smem -> coalesced split write ----
    float* smemf = (float*)(dyns + pad);   // reuse Q region (done), [128][132]
    {
        const float r0i = 1.0f / l0, r1i = 1.0f / l1;
        const int row0 = wid*16 + gid, row1 = row0 + 8;
        #pragma unroll
        for (int nb = 0; nb < 16; nb++) {
            const int col = nb*8 + tig*2;
            smemf[row0*132 + col]     = c_o[nb][0]*r0i;
            smemf[row0*132 + col + 1] = c_o[nb][1]*r0i;
            smemf[row1*132 + col]     = c_o[nb][2]*r1i;
            smemf[row1*132 + col + 1] = c_o[nb][3]*r1i;
        }
    }
    __syncthreads();
    for (int v = tid; v < 4096; v += 256) {
        const int row = v >> 5, c4 = (v & 31) << 2;
        float4 val = *(const float4*)&smemf[row*132 + c4];
        const size_t go = ((size_t)(b*TT) + qt*128 + row)*DD + h*HD + c4;
        uint32_t lo0, lo1;
        uint32_t hi0 = packsplit_h(val.x, val.y, lo0);
        uint32_t hi1 = packsplit_h(val.z, val.w, lo1);
        *(uint32_t*)&ah[go]   = hi0; *(uint32_t*)&ah[go+2] = hi1;
        *(uint32_t*)&al[go]   = lo0; *(uint32_t*)&al[go+2] = lo1;
    }
}

// ---------------- elementwise split: fp32 -> fp16 hi/lo -------------------
__global__ __launch_bounds__(256) void split4h(const float* __restrict__ in,
    fp16* __restrict__ oh, fp16* __restrict__ ol, int n4)
{
    int i = blockIdx.x*256 + threadIdx.x;
    if (i >= n4) return;
    float4 v = ((const float4*)in)[i];
    uint32_t l0, l1;
    uint32_t h0 = packsplit_h(v.x, v.y, l0);
    uint32_t h1 = packsplit_h(v.z, v.w, l1);
    ((uint32_t*)oh)[i*2]   = h0; ((uint32_t*)oh)[i*2+1] = h1;
    ((uint32_t*)ol)[i*2]   = l0; ((uint32_t*)ol)[i*2+1] = l1;
}

// ---------------- weight transpose -> plain fp16 ---------------------------
__global__ void transpose_h(const float* __restrict__ in, fp16* __restrict__ out, int n)
{
    __shared__ float t[32][33];
    const int r0 = blockIdx.y*32, c0 = blockIdx.x*32;
    const int tx = threadIdx.x, ty = threadIdx.y;
    #pragma unroll
    for (int i = 0; i < 32; i += 8)
        t[ty+i][tx] = in[(size_t)(r0+ty+i)*n + c0+tx];
    __syncthreads();
    #pragma unroll
    for (int i = 0; i < 32; i += 8)
        out[(size_t)(c0+ty+i)*n + r0 + tx] = __float2half_rn(t[tx][ty+i]);
}

// ---------------- V transpose -> plain fp16 [b,h,d,t] -----------------------
__global__ void transpose_v(const float* __restrict__ in, fp16* __restrict__ out)
{
    __shared__ float t[32][33];
    const int z = blockIdx.z, zb = z >> 4, zh = z & 15;
    const float* pin = in + (size_t)zb*TT*DD + (size_t)zh*HD;
    fp16* pout = out + (size_t)z*HD*TT;
    const int r0 = blockIdx.y*32, c0 = blockIdx.x*32;   // r = t, c = d
    const int tx = threadIdx.x, ty = threadIdx.y;
    #pragma unroll
    for (int i = 0; i < 32; i += 8)
        t[ty+i][tx] = pin[(size_t)(r0+ty+i)*DD + c0+tx];
    __syncthreads();
    #pragma unroll
    for (int i = 0; i < 32; i += 8)
        pout[(size_t)(c0+ty+i)*TT + r0 + tx] = __float2half_rn(t[tx][ty+i]);
}

// ---------------- fused rmsnorm + rope -> fp16 (hi + optional lo) ----------
__global__ __launch_bounds__(256) void rmsnorm_rope_h(
    const float* __restrict__ in, const float* __restrict__ g,
    const float* __restrict__ cosp, const float* __restrict__ sinp,
    float scale, fp16* __restrict__ oh, fp16* __restrict__ ol)
{
    __shared__ float s[DD];
    __shared__ float red[8];
    const int row = blockIdx.x;
    const int t = row & (TT - 1);
    const float* p = in + (size_t)row * DD;
    const int tid = threadIdx.x;

    float ss = 0.f;
    for (int c = tid; c < DD; c += 256) { float x = p[c]; s[c] = x; ss += x*x; }
    #pragma unroll
    for (int o = 16; o > 0; o >>= 1) ss += __shfl_xor_sync(0xffffffffu, ss, o);
    if ((tid & 31) == 0) red[tid >> 5] = ss;
    __syncthreads();
    float tot = red[0]+red[1]+red[2]+red[3]+red[4]+red[5]+red[6]+red[7];
    const float inv = rsqrtf(tot * (1.0f / (float)DD) + 1e-6f);

    for (int c = tid; c < DD; c += 256) {
        const int pidx = c & 127;
        const int base = c - pidx;
        float o;
        if (pidx < 64) {
            float x1 = s[c] * inv * g[c];
            float x2 = s[base + 64 + pidx] * inv * g[base + 64 + pidx];
            o = x1 * cosp[t*64 + pidx] - sinp[t*64 + pidx] * x2;
        } else {
            const int pp = pidx - 64;
            float x2 = s[c] * inv * g[c];
            float x1 = s[base + pp] * inv * g[base + pp];
            o = x2 * cosp[t*64 + pp] + sinp[t*64 + pp] * x1;
        }
        o *= scale;
        fp16 h = __float2half_rn(o);
        oh[(size_t)row*DD + c] = h;
        if (ol) ol[(size_t)row*DD + c] = __float2half_rn(o - __half2float(h));
    }
}

// ---------------------------------------------------------------------------
extern "C" void kernel_launch(void* const* d_in, const int* in_sizes, int n_in,
                              void* d_out, int out_size)
{
    const float* x    = (const float*)d_in[0];
    const float* cosp = (const float*)d_in[1];
    const float* sinp = (const float*)d_in[2];
    const float* w[5] = { (const float*)d_in[3], (const float*)d_in[5],
                          (const float*)d_in[7], (const float*)d_in[11],
                          (const float*)d_in[13] };
    const float* bq = (const float*)d_in[4];
    const float* bk = (const float*)d_in[6];
    const float* bv = (const float*)d_in[8];
    const float* gq = (const float*)d_in[9];
    const float* gk = (const float*)d_in[10];
    const float* bo = (const float*)d_in[12];
    const float* bg = (const float*)d_in[14];
    float* out = (float*)d_out;

    fp16 *xh, *xl, *wt, *qh, *ql, *kh, *vt, *ah, *al, *oh, *ol;
    float *tmp, *of;
    cudaGetSymbolAddress((void**)&xh, g_xh);   cudaGetSymbolAddress((void**)&xl, g_xl);
    cudaGetSymbolAddress((void**)&wt, g_wt);
    cudaGetSymbolAddress((void**)&tmp, g_tmp);
    cudaGetSymbolAddress((void**)&qh, g_qh);   cudaGetSymbolAddress((void**)&ql, g_ql);
    cudaGetSymbolAddress((void**)&kh, g_kh);
    cudaGetSymbolAddress((void**)&vt, g_vt);
    cudaGetSymbolAddress((void**)&ah, g_ah);   cudaGetSymbolAddress((void**)&al, g_al);
    cudaGetSymbolAddress((void**)&of, g_of);
    cudaGetSymbolAddress((void**)&oh, g_oh);   cudaGetSymbolAddress((void**)&ol, g_ol);

    const int SMEMSZ  = 2*STG_SZ + 1024;          // gemm_h2 (256x128, fp16)
    const int SMEMF   = 65536 + 2*32768 + 1024;   // flash: Q 64KB + 2 x 32KB stages
    cudaFuncSetAttribute(gemm_h2, cudaFuncAttributeMaxDynamicSharedMemorySize, SMEMSZ);
    cudaFuncSetAttribute(flash_attn, cudaFuncAttributeMaxDynamicSharedMemorySize, SMEMF);

    dim3 blk(256), tb(32, 8);
    const long DDl = DD;

    // input + weight prep
    split4h<<<(MROWS*DD/4 + 255)/256, blk>>>(x, xh, xl, MROWS*DD/4);
    for (int i = 0; i < 5; i++)
        transpose_h<<<dim3(64,64,1), tb>>>(w[i], wt + (size_t)i*DD*DD, DD);

    dim3 gproj(DD/128, MROWS/256, 1);   // (16, 16)

    // Q
    gemm_h2<<<gproj, blk, SMEMSZ>>>(xh, xl, DDl, wt, DDl,
        bq, nullptr, tmp, nullptr, nullptr, DDl, DD, 0);
    rmsnorm_rope_h<<<MROWS, blk>>>(tmp, gq, cosp, sinp, 0.08838834764831845f, qh, ql);
    // K (plain fp16)
    gemm_h2<<<gproj, blk, SMEMSZ>>>(xh, xl, DDl, wt + (size_t)DD*DD, DDl,
        bk, nullptr, tmp, nullptr, nullptr, DDl, DD, 0);
    rmsnorm_rope_h<<<MROWS, blk>>>(tmp, gk, cosp, sinp, 1.0f, kh, nullptr);
    // V (+ transpose to [b,h,d,t], plain fp16)
    gemm_h2<<<gproj, blk, SMEMSZ>>>(xh, xl, DDl, wt + 2ULL*DD*DD, DDl,
        bv, nullptr, tmp, nullptr, nullptr, DDl, DD, 0);
    transpose_v<<<dim3(4,64,NB), tb>>>(tmp, vt);

    // fused attention (scale folded into q)
    flash_attn<<<dim3(16, 32), blk, SMEMF>>>(qh, ql, kh, vt, ah, al);

    // out proj (fp32 + fp16 split)
    gemm_h2<<<gproj, blk, SMEMSZ>>>(ah, al, DDl, wt + 3ULL*DD*DD, DDl,
        bo, nullptr, of, oh, ol, DDl, DD, 2);
    // gate: out = of * sigmoid(o @ wg + bg)
    gemm_h2<<<gproj, blk, SMEMSZ>>>(oh, ol, DDl, wt + 4ULL*DD*DD, DDl,
        bg, of, out, nullptr, nullptr, DDl, DD, 3);
}

// round 10
// speedup vs baseline: 5.0738x; 1.1149x over previous
#include <cuda_runtime.h>
#include <cuda_bf16.h>
#include <cuda_fp16.h>
#include <cstdint>
#include <math.h>

#define BB 2
#define TT 2048
#define DD 2048
#define HH 16
#define HD 128
#define MROWS (BB*TT)     // 4096
#define NB (BB*HH)        // 32

typedef __half fp16;

// ---------------- scratch (device globals; allocation-free rule) ----------
__device__ fp16  g_xh[(size_t)MROWS*DD], g_xl[(size_t)MROWS*DD];
__device__ fp16  g_wt[5ULL*DD*DD];                               // transposed fp16 weights
__device__ float g_tmp[(size_t)MROWS*DD];                        // fp32 proj out
__device__ fp16  g_qh[(size_t)MROWS*DD], g_ql[(size_t)MROWS*DD];
__device__ fp16  g_kh[(size_t)MROWS*DD];                         // K plain fp16
__device__ fp16  g_vt[(size_t)NB*HD*TT];                         // v^T [b,h,d,t] plain fp16
__device__ fp16  g_ah[(size_t)MROWS*DD];                         // attn plain fp16
__device__ float g_of[(size_t)MROWS*DD];
__device__ fp16  g_oh[(size_t)MROWS*DD];

// ---------------- PTX helpers (plain sm_80+ PTX only) ---------------------
__device__ __forceinline__ uint32_t smem_u32(const void* p) {
    uint32_t a;
    asm("{ .reg .u64 t; cvta.to.shared.u64 t, %1; cvt.u32.u64 %0, t; }" : "=r"(a) : "l"(p));
    return a;
}
__device__ __forceinline__ void cpa16(uint32_t s, const void* g) {
    asm volatile("cp.async.cg.shared.global [%0], [%1], 16;" :: "r"(s), "l"(g));
}
#define CP_COMMIT()  asm volatile("cp.async.commit_group;" ::: "memory")

__device__ __forceinline__ void ldsm4(uint32_t* r, uint32_t a) {
    asm volatile("ldmatrix.sync.aligned.m8n8.x4.shared.b16 {%0,%1,%2,%3}, [%4];"
        : "=r"(r[0]), "=r"(r[1]), "=r"(r[2]), "=r"(r[3]) : "r"(a));
}
__device__ __forceinline__ void mma16816h(float* c, const uint32_t* a, const uint32_t* b) {
    asm volatile("mma.sync.aligned.m16n8k16.row.col.f32.f16.f16.f32 "
        "{%0,%1,%2,%3}, {%4,%5,%6,%7}, {%8,%9}, {%0,%1,%2,%3};"
        : "+f"(c[0]), "+f"(c[1]), "+f"(c[2]), "+f"(c[3])
        : "r"(a[0]), "r"(a[1]), "r"(a[2]), "r"(a[3]), "r"(b[0]), "r"(b[1]));
}
__device__ __forceinline__ uint32_t sw_addr(uint32_t base, int row, int ch) {
    uint32_t off = (uint32_t)(row*128 + ch*16);
    return base + (off ^ ((off >> 3) & 0x70u));
}
__device__ __forceinline__ uint32_t packsplit_h(float a, float b, uint32_t& lo) {
    fp16 ha = __float2half_rn(a), hb = __float2half_rn(b);
    fp16 la = __float2half_rn(a - __half2float(ha));
    fp16 lb = __float2half_rn(b - __half2float(hb));
    __half2 H(ha, hb), L(la, lb);
    lo = *(uint32_t*)&L;
    return *(uint32_t*)&H;
}
__device__ __forceinline__ uint32_t pack_h(float a, float b) {
    __half2 H(__float2half_rn(a), __float2half_rn(b));
    return *(uint32_t*)&H;
}

// ============ 256x128x64 GEMM (fp16, A split-2 or single, B plain) =========
// stage layout (80KB): Ah 32KB | Al 32KB | B 16KB   (Al region unused if !Al)
#define STG_SZ 81920

__device__ __forceinline__ void ld_stage256(uint32_t sb,
    const fp16* Ah, const fp16* Al, long lda,
    const fp16* B, long ldb,
    int m0, int n0, int k0, int tid)
{
    #pragma unroll
    for (int t = 0; t < 8; t++) {       // Ah: 256 rows x 128B
        int j = tid + t*256;
        int r = j >> 3, ch = j & 7;
        uint32_t off = (uint32_t)(r*128 + ch*16);
        uint32_t sw = off ^ ((off >> 3) & 0x70u);
        cpa16(sb + sw, Ah + (size_t)(m0 + r)*lda + k0 + ch*8);
    }
    if (Al) {
        #pragma unroll
        for (int t = 0; t < 8; t++) {   // Al: 256 rows x 128B
            int j = tid + t*256;
            int r = j >> 3, ch = j & 7;
            uint32_t off = (uint32_t)(r*128 + ch*16);
            uint32_t sw = off ^ ((off >> 3) & 0x70u);
            cpa16(sb + 32768 + sw, Al + (size_t)(m0 + r)*lda + k0 + ch*8);
        }
    }
    #pragma unroll
    for (int t = 0; t < 4; t++) {       // B: 128 rows x 128B
        int j = tid + t*256;
        int r = j >> 3, ch = j & 7;
        uint32_t off = (uint32_t)(r*128 + ch*16);
        uint32_t sw = off ^ ((off >> 3) & 0x70u);
        cpa16(sb + 65536 + sw, B + (size_t)(n0 + r)*ldb + k0 + ch*8);
    }
    CP_COMMIT();
}

// epi: 0 = fp32 (+bias), 2 = fp32 + fp16 hi, 3 = gate
__global__ __launch_bounds__(256, 1) void gemm_h2(
    const fp16* __restrict__ Ah, const fp16* __restrict__ Al, long lda,
    const fp16* __restrict__ B, long ldb,
    const float* __restrict__ bias, const float* __restrict__ mul,
    float* __restrict__ Cf, fp16* __restrict__ Ch,
    long ldc, int K, int epi)
{
    extern __shared__ __align__(16) uint8_t dyns[];
    const int tid = threadIdx.x;
    uint32_t raw = smem_u32(dyns);
    uint32_t sb0 = (raw + 1023u) & ~1023u;
    uint32_t pad = sb0 - raw;

    const int m0 = blockIdx.y * 256, n0 = blockIdx.x * 128;
    const int lane = tid & 31, wid = tid >> 5;
    const int wm = wid >> 1, wn = wid & 1;       // 4 x 2 warps, each 64x64
    const int g8 = lane & 7, q = lane >> 3;

    float c[4][8][4];
    #pragma unroll
    for (int i = 0; i < 4; i++)
        #pragma unroll
        for (int j = 0; j < 8; j++)
            #pragma unroll
            for (int e = 0; e < 4; e++) c[i][j][e] = 0.f;

    const int nch = K >> 6;
    ld_stage256(sb0, Ah, Al, lda, B, ldb, m0, n0, 0, tid);

    for (int cc = 0; cc < nch; cc++) {
        const int s = cc & 1;
        const uint32_t sbs = sb0 + s*STG_SZ;
        if (cc + 1 < nch) {
            ld_stage256(sb0 + (s^1)*STG_SZ, Ah, Al, lda, B, ldb, m0, n0, (cc+1)*64, tid);
            asm volatile("cp.async.wait_group 1;" ::: "memory");
        } else {
            asm volatile("cp.async.wait_group 0;" ::: "memory");
        }
        __syncthreads();

        #pragma unroll
        for (int k16 = 0; k16 < 4; k16++) {
            uint32_t bh[8][2];
            #pragma unroll
            for (int nj = 0; nj < 4; nj++) {
                int row = wn*64 + nj*16 + g8 + ((q >> 1) << 3);
                int ch  = k16*2 + (q & 1);
                uint32_t r4[4];
                ldsm4(r4, sw_addr(sbs + 65536, row, ch));
                bh[2*nj][0] = r4[0]; bh[2*nj][1] = r4[1];
                bh[2*nj+1][0] = r4[2]; bh[2*nj+1][1] = r4[3];
            }
            #pragma unroll
            for (int mi = 0; mi < 4; mi++) {
                int row = wm*64 + mi*16 + g8 + ((q & 1) << 3);
                int ch  = k16*2 + (q >> 1);
                uint32_t a = sw_addr(sbs, row, ch);
                uint32_t ah4[4];
                ldsm4(ah4, a);
                #pragma unroll
                for (int ni = 0; ni < 8; ni++)
                    mma16816h(c[mi][ni], ah4, bh[ni]);
                if (Al) {
                    uint32_t al4[4];
                    ldsm4(al4, a + 32768);
                    #pragma unroll
                    for (int ni = 0; ni < 8; ni++)
                        mma16816h(c[mi][ni], al4, bh[ni]);
                }
            }
        }
        __syncthreads();
    }

    // ---- epilogue: frags -> padded fp32 smem [256][132] -> coalesced gmem ----
    float* smemf = (float*)(dyns + pad);
    {
        const int gid = lane >> 2, tig = lane & 3;
        #pragma unroll
        for (int mi = 0; mi < 4; mi++)
            #pragma unroll
            for (int ni = 0; ni < 8; ni++) {
                int r0 = wm*64 + mi*16 + gid;
                int col = wn*64 + ni*8 + tig*2;
                *(float2*)&smemf[r0*132 + col]     = make_float2(c[mi][ni][0], c[mi][ni][1]);
                *(float2*)&smemf[(r0+8)*132 + col] = make_float2(c[mi][ni][2], c[mi][ni][3]);
            }
    }
    __syncthreads();

    for (int v = tid; v < 8192; v += 256) {
        const int row = v >> 5, c4 = (v & 31) << 2;
        float4 val = *(const float4*)&smemf[row*132 + c4];
        const int gc = n0 + c4;
        const size_t go = (size_t)(m0 + row)*ldc + gc;
        if (bias) {
            val.x += bias[gc]; val.y += bias[gc+1]; val.z += bias[gc+2]; val.w += bias[gc+3];
        }
        if (epi == 0) {
            *(float4*)&Cf[go] = val;
        } else if (epi == 2) {
            *(float4*)&Cf[go] = val;
            *(uint32_t*)&Ch[go]   = pack_h(val.x, val.y);
            *(uint32_t*)&Ch[go+2] = pack_h(val.z, val.w);
        } else {  // gate
            const float4 m = *(const float4*)&mul[go];
            float4 o;
            o.x = m.x / (1.0f + __expf(-val.x));
            o.y = m.y / (1.0f + __expf(-val.y));
            o.z = m.z / (1.0f + __expf(-val.z));
            o.w = m.w / (1.0f + __expf(-val.w));
            *(float4*)&Cf[go] = o;
        }
    }
}

// ---------------- flash attention KV stage loader (plain fp16) -------------
// stage layout (32KB): K 2 panels of 8KB | V 16KB
__device__ __forceinline__ void flash_ldkv(uint32_t stg, int kc0,
    const fp16* K, const fp16* V, int tid)
{
    #pragma unroll
    for (int t = 0; t < 8; t++) {
        int i = tid + t*256;
        if (i < 1024) {                       // K: 64 rows x 2 panels x 128B
            int p = i >> 9, j = i & 511;
            int r = j >> 3, ch = j & 7;
            uint32_t off = (uint32_t)(r*128 + ch*16);
            uint32_t sw = off ^ ((off >> 3) & 0x70u);
            const fp16* src = K + (size_t)(kc0 + r)*DD + p*64 + ch*8;
            cpa16(stg + p*8192 + sw, src);
        } else {                              // V: 128 rows (d) x 64 t = 128B rows
            int j = i - 1024;
            int r = j >> 3, ch = j & 7;
            uint32_t off = (uint32_t)(r*128 + ch*16);
            uint32_t sw = off ^ ((off >> 3) & 0x70u);
            const fp16* src = V + (size_t)r*TT + kc0 + ch*8;
            cpa16(stg + 16384 + sw, src);
        }
    }
    CP_COMMIT();
}

// ---------------- fused flash attention (fp16 2-term) ----------------------
// grid (16 qtiles, 32 bh); 256 thr; 8 warps x 16 q-rows; kc tile = 64
__global__ __launch_bounds__(256, 1) void flash_attn(
    const fp16* __restrict__ qh, const fp16* __restrict__ ql,
    const fp16* __restrict__ kk, const fp16* __restrict__ vt,
    fp16* __restrict__ ah)
{
    extern __shared__ __align__(16) uint8_t dyns[];
    const int tid = threadIdx.x;
    uint32_t raw = smem_u32(dyns);
    uint32_t sb0 = (raw + 1023u) & ~1023u;
    uint32_t pad = sb0 - raw;

    const int qt = blockIdx.x;
    const int bh = blockIdx.y;
    const int b = bh >> 4, h = bh & 15;

    const fp16* Qh = qh + ((size_t)(b*TT) + qt*128)*DD + h*HD;
    const fp16* Ql = ql + ((size_t)(b*TT) + qt*128)*DD + h*HD;
    const fp16* K  = kk + (size_t)(b*TT)*DD + h*HD;
    const fp16* V  = vt + (size_t)bh*HD*TT;

    const int lane = tid & 31, wid = tid >> 5;
    const int g8 = lane & 7, q2 = lane >> 3;
    const int gid = lane >> 2, tig = lane & 3;

    // Q: 4 panels of 16KB (Qh p0, Qh p1 | Ql p0, Ql p1) at sb0..64KB
    #pragma unroll
    for (int t = 0; t < 16; t++) {
        int i = tid + t*256;
        int half = i >> 11, j = i & 2047;
        int pd = j >> 10, jj = j & 1023;
        int r = jj >> 3, ch = jj & 7;
        uint32_t off = (uint32_t)(r*128 + ch*16);
        uint32_t sw = off ^ ((off >> 3) & 0x70u);
        const fp16* src = (half ? Ql : Qh) + (size_t)r*DD + pd*64 + ch*8;
        cpa16(sb0 + half*32768 + pd*16384 + sw, src);
    }
    CP_COMMIT();
    flash_ldkv(sb0 + 65536, 0,  K, V, tid);
    flash_ldkv(sb0 + 98304, 64, K, V, tid);

    float c_o[16][4];
    #pragma unroll
    for (int i = 0; i < 16; i++)
        #pragma unroll
        for (int e = 0; e < 4; e++) c_o[i][e] = 0.f;
    float m0 = -1e30f, m1 = -1e30f, l0 = 0.f, l1 = 0.f;

    for (int t = 0; t < 32; t++) {
        if (t < 31) asm volatile("cp.async.wait_group 1;" ::: "memory");
        else        asm volatile("cp.async.wait_group 0;" ::: "memory");
        __syncthreads();
        const uint32_t stg = sb0 + 65536 + (t & 1)*32768;

        // ---- S = Q @ K^T (128 x 64, Q split-2, K plain) ----
        float c_s[8][4];
        #pragma unroll
        for (int i = 0; i < 8; i++)
            #pragma unroll
            for (int e = 0; e < 4; e++) c_s[i][e] = 0.f;

        #pragma unroll
        for (int k16 = 0; k16 < 8; k16++) {
            const int pd = k16 >> 2;
            uint32_t qa = sw_addr(sb0 + pd*16384, wid*16 + g8 + ((q2 & 1) << 3),
                                  (k16 & 3)*2 + (q2 >> 1));
            uint32_t qah[4], qal[4];
            ldsm4(qah, qa);
            ldsm4(qal, qa + 32768);
            uint32_t kbh[8][2];
            #pragma unroll
            for (int nj = 0; nj < 4; nj++) {
                uint32_t ka = sw_addr(stg + pd*8192, nj*16 + g8 + ((q2 >> 1) << 3),
                                      (k16 & 3)*2 + (q2 & 1));
                uint32_t r4[4];
                ldsm4(r4, ka);
                kbh[2*nj][0] = r4[0]; kbh[2*nj][1] = r4[1];
                kbh[2*nj+1][0] = r4[2]; kbh[2*nj+1][1] = r4[3];
            }
            #pragma unroll
            for (int nj = 0; nj < 8; nj++) {
                mma16816h(c_s[nj], qah, kbh[nj]);
                mma16816h(c_s[nj], qal, kbh[nj]);
            }
        }

        // ---- online softmax ----
        float tm0 = -1e30f, tm1 = -1e30f;
        #pragma unroll
        for (int nj = 0; nj < 8; nj++) {
            tm0 = fmaxf(tm0, fmaxf(c_s[nj][0], c_s[nj][1]));
            tm1 = fmaxf(tm1, fmaxf(c_s[nj][2], c_s[nj][3]));
        }
        tm0 = fmaxf(tm0, __shfl_xor_sync(0xffffffffu, tm0, 1));
        tm0 = fmaxf(tm0, __shfl_xor_sync(0xffffffffu, tm0, 2));
        tm1 = fmaxf(tm1, __shfl_xor_sync(0xffffffffu, tm1, 1));
        tm1 = fmaxf(tm1, __shfl_xor_sync(0xffffffffu, tm1, 2));
        const float mn0 = fmaxf(m0, tm0), mn1 = fmaxf(m1, tm1);
        const float a0 = __expf(m0 - mn0), a1 = __expf(m1 - mn1);
        float rs0 = 0.f, rs1 = 0.f;
        #pragma unroll
        for (int nj = 0; nj < 8; nj++) {
            c_s[nj][0] = __expf(c_s[nj][0] - mn0);
            c_s[nj][1] = __expf(c_s[nj][1] - mn0);
            c_s[nj][2] = __expf(c_s[nj][2] - mn1);
            c_s[nj][3] = __expf(c_s[nj][3] - mn1);
            rs0 += c_s[nj][0] + c_s[nj][1];
            rs1 += c_s[nj][2] + c_s[nj][3];
        }
        rs0 += __shfl_xor_sync(0xffffffffu, rs0, 1);
        rs0 += __shfl_xor_sync(0xffffffffu, rs0, 2);
        rs1 += __shfl_xor_sync(0xffffffffu, rs1, 1);
        rs1 += __shfl_xor_sync(0xffffffffu, rs1, 2);
        l0 = l0*a0 + rs0;  l1 = l1*a1 + rs1;
        m0 = mn0;          m1 = mn1;
        #pragma unroll
        for (int nb = 0; nb < 16; nb++) {
            c_o[nb][0] *= a0; c_o[nb][1] *= a0;
            c_o[nb][2] *= a1; c_o[nb][3] *= a1;
        }

        // ---- O += P @ V  (P split-2 in registers, V plain) ----
        #pragma unroll
        for (int kb = 0; kb < 4; kb++) {
            uint32_t pah[4], pal[4];
            pah[0] = packsplit_h(c_s[2*kb][0],   c_s[2*kb][1],   pal[0]);
            pah[1] = packsplit_h(c_s[2*kb][2],   c_s[2*kb][3],   pal[1]);
            pah[2] = packsplit_h(c_s[2*kb+1][0], c_s[2*kb+1][1], pal[2]);
            pah[3] = packsplit_h(c_s[2*kb+1][2], c_s[2*kb+1][3], pal[3]);
            #pragma unroll
            for (int nj2 = 0; nj2 < 8; nj2++) {
                uint32_t va = sw_addr(stg + 16384, nj2*16 + g8 + ((q2 >> 1) << 3),
                                      kb*2 + (q2 & 1));
                uint32_t vh4[4];
                ldsm4(vh4, va);
                uint32_t b0[2] = {vh4[0], vh4[1]}, b1[2] = {vh4[2], vh4[3]};
                mma16816h(c_o[2*nj2],   pah, b0);
                mma16816h(c_o[2*nj2],   pal, b0);
                mma16816h(c_o[2*nj2+1], pah, b1);
                mma16816h(c_o[2*nj2+1], pal, b1);
            }
        }

        __syncthreads();
        if (t + 2 < 32)
            flash_ldkv(sb0 + 65536 + (t & 1)*32768, (t+2)*64, K, V, tid);
    }

    // ---- epilogue: O/l -> padded fp32 smem -> coalesced fp16 write ----
    float* smemf = (float*)(dyns + pad);   // reuse Q region (done), [128][132]
    {
        const float r0i = 1.0f / l0, r1i = 1.0f / l1;
        const int row0 = wid*16 + gid, row1 = row0 + 8;
        #pragma unroll
        for (int nb = 0; nb < 16; nb++) {
            const int col = nb*8 + tig*2;
            smemf[row0*132 + col]     = c_o[nb][0]*r0i;
            smemf[row0*132 + col + 1] = c_o[nb][1]*r0i;
            smemf[row1*132 + col]     = c_o[nb][2]*r1i;
            smemf[row1*132 + col + 1] = c_o[nb][3]*r1i;
        }
    }
    __syncthreads();
    for (int v = tid; v < 4096; v += 256) {
        const int row = v >> 5, c4 = (v & 31) << 2;
        float4 val = *(const float4*)&smemf[row*132 + c4];
        const size_t go = ((size_t)(b*TT) + qt*128 + row)*DD + h*HD + c4;
        *(uint32_t*)&ah[go]   = pack_h(val.x, val.y);
        *(uint32_t*)&ah[go+2] = pack_h(val.z, val.w);
    }
}

// ---------------- elementwise split: fp32 -> fp16 hi/lo -------------------
__global__ __launch_bounds__(256) void split4h(const float* __restrict__ in,
    fp16* __restrict__ oh, fp16* __restrict__ ol, int n4)
{
    int i = blockIdx.x*256 + threadIdx.x;
    if (i >= n4) return;
    float4 v = ((const float4*)in)[i];
    uint32_t l0, l1;
    uint32_t h0 = packsplit_h(v.x, v.y, l0);
    uint32_t h1 = packsplit_h(v.z, v.w, l1);
    ((uint32_t*)oh)[i*2]   = h0; ((uint32_t*)oh)[i*2+1] = h1;
    ((uint32_t*)ol)[i*2]   = l0; ((uint32_t*)ol)[i*2+1] = l1;
}

// ---------------- weight transpose -> plain fp16 ---------------------------
__global__ void transpose_h(const float* __restrict__ in, fp16* __restrict__ out, int n)
{
    __shared__ float t[32][33];
    const int r0 = blockIdx.y*32, c0 = blockIdx.x*32;
    const int tx = threadIdx.x, ty = threadIdx.y;
    #pragma unroll
    for (int i = 0; i < 32; i += 8)
        t[ty+i][tx] = in[(size_t)(r0+ty+i)*n + c0+tx];
    __syncthreads();
    #pragma unroll
    for (int i = 0; i < 32; i += 8)
        out[(size_t)(c0+ty+i)*n + r0 + tx] = __float2half_rn(t[tx][ty+i]);
}

// ---------------- V transpose -> plain fp16 [b,h,d,t] -----------------------
__global__ void transpose_v(const float* __restrict__ in, fp16* __restrict__ out)
{
    __shared__ float t[32][33];
    const int z = blockIdx.z, zb = z >> 4, zh = z & 15;
    const float* pin = in + (size_t)zb*TT*DD + (size_t)zh*HD;
    fp16* pout = out + (size_t)z*HD*TT;
    const int r0 = blockIdx.y*32, c0 = blockIdx.x*32;   // r = t, c = d
    const int tx = threadIdx.x, ty = threadIdx.y;
    #pragma unroll
    for (int i = 0; i < 32; i += 8)
        t[ty+i][tx] = pin[(size_t)(r0+ty+i)*DD + c0+tx];
    __syncthreads();
    #pragma unroll
    for (int i = 0; i < 32; i += 8)
        pout[(size_t)(c0+ty+i)*TT + r0 + tx] = __float2half_rn(t[tx][ty+i]);
}

// ---------------- fused rmsnorm + rope -> fp16 (hi + optional lo) ----------
__global__ __launch_bounds__(256) void rmsnorm_rope_h(
    const float* __restrict__ in, const float* __restrict__ g,
    const float* __restrict__ cosp, const float* __restrict__ sinp,
    float scale, fp16* __restrict__ oh, fp16* __restrict__ ol)
{
    __shared__ float s[DD];
    __shared__ float red[8];
    const int row = blockIdx.x;
    const int t = row & (TT - 1);
    const float* p = in + (size_t)row * DD;
    const int tid = threadIdx.x;

    float ss = 0.f;
    for (int c = tid; c < DD; c += 256) { float x = p[c]; s[c] = x; ss += x*x; }
    #pragma unroll
    for (int o = 16; o > 0; o >>= 1) ss += __shfl_xor_sync(0xffffffffu, ss, o);
    if ((tid & 31) == 0) red[tid >> 5] = ss;
    __syncthreads();
    float tot = red[0]+red[1]+red[2]+red[3]+red[4]+red[5]+red[6]+red[7];
    const float inv = rsqrtf(tot * (1.0f / (float)DD) + 1e-6f);

    for (int c = tid; c < DD; c += 256) {
        const int pidx = c & 127;
        const int base = c - pidx;
        float o;
        if (pidx < 64) {
            float x1 = s[c] * inv * g[c];
            float x2 = s[base + 64 + pidx] * inv * g[base + 64 + pidx];
            o = x1 * cosp[t*64 + pidx] - sinp[t*64 + pidx] * x2;
        } else {
            const int pp = pidx - 64;
            float x2 = s[c] * inv * g[c];
            float x1 = s[base + pp] * inv * g[base + pp];
            o = x2 * cosp[t*64 + pp] + sinp[t*64 + pp] * x1;
        }
        o *= scale;
        fp16 h = __float2half_rn(o);
        oh[(size_t)row*DD + c] = h;
        if (ol) ol[(size_t)row*DD + c] = __float2half_rn(o - __half2float(h));
    }
}

// ---------------------------------------------------------------------------
extern "C" void kernel_launch(void* const* d_in, const int* in_sizes, int n_in,
                              void* d_out, int out_size)
{
    const float* x    = (const float*)d_in[0];
    const float* cosp = (const float*)d_in[1];
    const float* sinp = (const float*)d_in[2];
    const float* w[5] = { (const float*)d_in[3], (const float*)d_in[5],
                          (const float*)d_in[7], (const float*)d_in[11],
                          (const float*)d_in[13] };
    const float* bq = (const float*)d_in[4];
    const float* bk = (const float*)d_in[6];
    const float* bv = (const float*)d_in[8];
    const float* gq = (const float*)d_in[9];
    const float* gk = (const float*)d_in[10];
    const float* bo = (const float*)d_in[12];
    const float* bg = (const float*)d_in[14];
    float* out = (float*)d_out;

    fp16 *xh, *xl, *wt, *qh, *ql, *kh, *vt, *ah, *oh;
    float *tmp, *of;
    cudaGetSymbolAddress((void**)&xh, g_xh);   cudaGetSymbolAddress((void**)&xl, g_xl);
    cudaGetSymbolAddress((void**)&wt, g_wt);
    cudaGetSymbolAddress((void**)&tmp, g_tmp);
    cudaGetSymbolAddress((void**)&qh, g_qh);   cudaGetSymbolAddress((void**)&ql, g_ql);
    cudaGetSymbolAddress((void**)&kh, g_kh);
    cudaGetSymbolAddress((void**)&vt, g_vt);
    cudaGetSymbolAddress((void**)&ah, g_ah);
    cudaGetSymbolAddress((void**)&of, g_of);
    cudaGetSymbolAddress((void**)&oh, g_oh);

    const int SMEMSZ  = 2*STG_SZ + 1024;          // gemm_h2 (256x128, fp16)
    const int SMEMF   = 65536 + 2*32768 + 1024;   // flash: Q 64KB + 2 x 32KB stages
    cudaFuncSetAttribute(gemm_h2, cudaFuncAttributeMaxDynamicSharedMemorySize, SMEMSZ);
    cudaFuncSetAttribute(flash_attn, cudaFuncAttributeMaxDynamicSharedMemorySize, SMEMF);

    dim3 blk(256), tb(32, 8);
    const long DDl = DD;

    // input + weight prep
    split4h<<<(MROWS*DD/4 + 255)/256, blk>>>(x, xh, xl, MROWS*DD/4);
    for (int i = 0; i < 5; i++)
        transpose_h<<<dim3(64,64,1), tb>>>(w[i], wt + (size_t)i*DD*DD, DD);

    dim3 gproj(DD/128, MROWS/256, 1);   // (16, 16)

    // Q  (A split-2)
    gemm_h2<<<gproj, blk, SMEMSZ>>>(xh, xl, DDl, wt, DDl,
        bq, nullptr, tmp, nullptr, DDl, DD, 0);
    rmsnorm_rope_h<<<MROWS, blk>>>(tmp, gq, cosp, sinp, 0.08838834764831845f, qh, ql);
    // K  (A split-2; K output plain fp16)
    gemm_h2<<<gproj, blk, SMEMSZ>>>(xh, xl, DDl, wt + (size_t)DD*DD, DDl,
        bk, nullptr, tmp, nullptr, DDl, DD, 0);
    rmsnorm_rope_h<<<MROWS, blk>>>(tmp, gk, cosp, sinp, 1.0f, kh, nullptr);
    // V  (A split-2; + transpose to [b,h,d,t] plain fp16)
    gemm_h2<<<gproj, blk, SMEMSZ>>>(xh, xl, DDl, wt + 2ULL*DD*DD, DDl,
        bv, nullptr, tmp, nullptr, DDl, DD, 0);
    transpose_v<<<dim3(4,64,NB), tb>>>(tmp, vt);

    // fused attention (scale folded into q) -> plain fp16 attn
    flash_attn<<<dim3(16, 32), blk, SMEMF>>>(qh, ql, kh, vt, ah);

    // out proj — SINGLE-PASS fp16 A (attn), fp32 + fp16-hi epilogue
    gemm_h2<<<gproj, blk, SMEMSZ>>>(ah, nullptr, DDl, wt + 3ULL*DD*DD, DDl,
        bo, nullptr, of, oh, DDl, DD, 2);
    // gate — SINGLE-PASS fp16 A (oh): out = of * sigmoid(oh @ wg + bg)
    gemm_h2<<<gproj, blk, SMEMSZ>>>(oh, nullptr, DDl, wt + 4ULL*DD*DD, DDl,
        bg, of, out, nullptr, DDl, DD, 3);
}

// round 11
// speedup vs baseline: 6.5596x; 1.2928x over previous
#include <cuda_runtime.h>
#include <cuda_bf16.h>
#include <cuda_fp16.h>
#include <cstdint>
#include <math.h>

#define BB 2
#define TT 2048
#define DD 2048
#define HH 16
#define HD 128
#define MROWS (BB*TT)     // 4096
#define NB (BB*HH)        // 32

typedef __half fp16;

// ---------------- scratch (device globals; allocation-free rule) ----------
__device__ fp16  g_xh[(size_t)MROWS*DD];                         // x plain fp16
__device__ fp16  g_wt[5ULL*DD*DD];                               // transposed fp16 weights
__device__ float g_tmp[(size_t)MROWS*DD];                        // fp32 proj out
__device__ fp16  g_qh[(size_t)MROWS*DD], g_ql[(size_t)MROWS*DD];
__device__ fp16  g_kh[(size_t)MROWS*DD];                         // K plain fp16
__device__ fp16  g_vt[(size_t)NB*HD*TT];                         // v^T [b,h,d,t] plain fp16
__device__ fp16  g_ah[(size_t)MROWS*DD];                         // attn plain fp16
__device__ float g_of[(size_t)MROWS*DD];
__device__ fp16  g_oh[(size_t)MROWS*DD];

// ---------------- PTX helpers (plain sm_80+ PTX only) ---------------------
__device__ __forceinline__ uint32_t smem_u32(const void* p) {
    uint32_t a;
    asm("{ .reg .u64 t; cvta.to.shared.u64 t, %1; cvt.u32.u64 %0, t; }" : "=r"(a) : "l"(p));
    return a;
}
__device__ __forceinline__ void cpa16(uint32_t s, const void* g) {
    asm volatile("cp.async.cg.shared.global [%0], [%1], 16;" :: "r"(s), "l"(g));
}
#define CP_COMMIT()  asm volatile("cp.async.commit_group;" ::: "memory")

__device__ __forceinline__ void ldsm4(uint32_t* r, uint32_t a) {
    asm volatile("ldmatrix.sync.aligned.m8n8.x4.shared.b16 {%0,%1,%2,%3}, [%4];"
        : "=r"(r[0]), "=r"(r[1]), "=r"(r[2]), "=r"(r[3]) : "r"(a));
}
__device__ __forceinline__ void mma16816h(float* c, const uint32_t* a, const uint32_t* b) {
    asm volatile("mma.sync.aligned.m16n8k16.row.col.f32.f16.f16.f32 "
        "{%0,%1,%2,%3}, {%4,%5,%6,%7}, {%8,%9}, {%0,%1,%2,%3};"
        : "+f"(c[0]), "+f"(c[1]), "+f"(c[2]), "+f"(c[3])
        : "r"(a[0]), "r"(a[1]), "r"(a[2]), "r"(a[3]), "r"(b[0]), "r"(b[1]));
}
__device__ __forceinline__ uint32_t sw_addr(uint32_t base, int row, int ch) {
    uint32_t off = (uint32_t)(row*128 + ch*16);
    return base + (off ^ ((off >> 3) & 0x70u));
}
__device__ __forceinline__ uint32_t packsplit_h(float a, float b, uint32_t& lo) {
    fp16 ha = __float2half_rn(a), hb = __float2half_rn(b);
    fp16 la = __float2half_rn(a - __half2float(ha));
    fp16 lb = __float2half_rn(b - __half2float(hb));
    __half2 H(ha, hb), L(la, lb);
    lo = *(uint32_t*)&L;
    return *(uint32_t*)&H;
}
__device__ __forceinline__ uint32_t pack_h(float a, float b) {
    __half2 H(__float2half_rn(a), __float2half_rn(b));
    return *(uint32_t*)&H;
}

// ============ 256x128x64 GEMM (fp16 single-pass) ============================
// stage layout (48KB): A 32KB | B 16KB
#define STG_SZ 49152

__device__ __forceinline__ void ld_stage256(uint32_t sb,
    const fp16* A, long lda, const fp16* B, long ldb,
    int m0, int n0, int k0, int tid)
{
    #pragma unroll
    for (int t = 0; t < 12; t++) {
        int i = tid + t*256;
        if (i < 2048) {                       // A: 256 rows x 128B
            int r = i >> 3, ch = i & 7;
            uint32_t off = (uint32_t)(r*128 + ch*16);
            uint32_t sw = off ^ ((off >> 3) & 0x70u);
            cpa16(sb + sw, A + (size_t)(m0 + r)*lda + k0 + ch*8);
        } else {                              // B: 128 rows x 128B
            int j = i - 2048;
            int r = j >> 3, ch = j & 7;
            uint32_t off = (uint32_t)(r*128 + ch*16);
            uint32_t sw = off ^ ((off >> 3) & 0x70u);
            cpa16(sb + 32768 + sw, B + (size_t)(n0 + r)*ldb + k0 + ch*8);
        }
    }
    CP_COMMIT();
}

// epi: 0 = fp32 (+bias), 2 = fp32 + fp16 hi, 3 = gate
__global__ __launch_bounds__(256, 1) void gemm_h2(
    const fp16* __restrict__ A, long lda,
    const fp16* __restrict__ B, long ldb,
    const float* __restrict__ bias, const float* __restrict__ mul,
    float* __restrict__ Cf, fp16* __restrict__ Ch,
    long ldc, int K, int epi)
{
    extern __shared__ __align__(16) uint8_t dyns[];
    const int tid = threadIdx.x;
    uint32_t raw = smem_u32(dyns);
    uint32_t sb0 = (raw + 1023u) & ~1023u;
    uint32_t pad = sb0 - raw;

    const int m0 = blockIdx.y * 256, n0 = blockIdx.x * 128;
    const int lane = tid & 31, wid = tid >> 5;
    const int wm = wid >> 1, wn = wid & 1;       // 4 x 2 warps, each 64x64
    const int g8 = lane & 7, q = lane >> 3;

    float c[4][8][4];
    #pragma unroll
    for (int i = 0; i < 4; i++)
        #pragma unroll
        for (int j = 0; j < 8; j++)
            #pragma unroll
            for (int e = 0; e < 4; e++) c[i][j][e] = 0.f;

    const int nch = K >> 6;
    ld_stage256(sb0, A, lda, B, ldb, m0, n0, 0, tid);

    for (int cc = 0; cc < nch; cc++) {
        const int s = cc & 1;
        const uint32_t sbs = sb0 + s*STG_SZ;
        if (cc + 1 < nch) {
            ld_stage256(sb0 + (s^1)*STG_SZ, A, lda, B, ldb, m0, n0, (cc+1)*64, tid);
            asm volatile("cp.async.wait_group 1;" ::: "memory");
        } else {
            asm volatile("cp.async.wait_group 0;" ::: "memory");
        }
        __syncthreads();

        #pragma unroll
        for (int k16 = 0; k16 < 4; k16++) {
            uint32_t bh[8][2];
            #pragma unroll
            for (int nj = 0; nj < 4; nj++) {
                int row = wn*64 + nj*16 + g8 + ((q >> 1) << 3);
                int ch  = k16*2 + (q & 1);
                uint32_t r4[4];
                ldsm4(r4, sw_addr(sbs + 32768, row, ch));
                bh[2*nj][0] = r4[0]; bh[2*nj][1] = r4[1];
                bh[2*nj+1][0] = r4[2]; bh[2*nj+1][1] = r4[3];
            }
            #pragma unroll
            for (int mi = 0; mi < 4; mi++) {
                int row = wm*64 + mi*16 + g8 + ((q & 1) << 3);
                int ch  = k16*2 + (q >> 1);
                uint32_t ah4[4];
                ldsm4(ah4, sw_addr(sbs, row, ch));
                #pragma unroll
                for (int ni = 0; ni < 8; ni++)
                    mma16816h(c[mi][ni], ah4, bh[ni]);
            }
        }
        __syncthreads();
    }

    // ---- epilogue: frags -> padded fp32 smem [256][132] -> coalesced gmem ----
    float* smemf = (float*)(dyns + pad);
    {
        const int gid = lane >> 2, tig = lane & 3;
        #pragma unroll
        for (int mi = 0; mi < 4; mi++)
            #pragma unroll
            for (int ni = 0; ni < 8; ni++) {
                int r0 = wm*64 + mi*16 + gid;
                int col = wn*64 + ni*8 + tig*2;
                *(float2*)&smemf[r0*132 + col]     = make_float2(c[mi][ni][0], c[mi][ni][1]);
                *(float2*)&smemf[(r0+8)*132 + col] = make_float2(c[mi][ni][2], c[mi][ni][3]);
            }
    }
    __syncthreads();

    for (int v = tid; v < 8192; v += 256) {
        const int row = v >> 5, c4 = (v & 31) << 2;
        float4 val = *(const float4*)&smemf[row*132 + c4];
        const int gc = n0 + c4;
        const size_t go = (size_t)(m0 + row)*ldc + gc;
        if (bias) {
            val.x += bias[gc]; val.y += bias[gc+1]; val.z += bias[gc+2]; val.w += bias[gc+3];
        }
        if (epi == 0) {
            *(float4*)&Cf[go] = val;
        } else if (epi == 2) {
            *(float4*)&Cf[go] = val;
            *(uint32_t*)&Ch[go]   = pack_h(val.x, val.y);
            *(uint32_t*)&Ch[go+2] = pack_h(val.z, val.w);
        } else {  // gate
            const float4 m = *(const float4*)&mul[go];
            float4 o;
            o.x = m.x / (1.0f + __expf(-val.x));
            o.y = m.y / (1.0f + __expf(-val.y));
            o.z = m.z / (1.0f + __expf(-val.z));
            o.w = m.w / (1.0f + __expf(-val.w));
            *(float4*)&Cf[go] = o;
        }
    }
}

// ---------------- flash attention KV stage loader (plain fp16) -------------
// stage layout (32KB): K 2 panels of 8KB | V 16KB
__device__ __forceinline__ void flash_ldkv(uint32_t stg, int kc0,
    const fp16* K, const fp16* V, int tid)
{
    #pragma unroll
    for (int t = 0; t < 8; t++) {
        int i = tid + t*256;
        if (i < 1024) {                       // K: 64 rows x 2 panels x 128B
            int p = i >> 9, j = i & 511;
            int r = j >> 3, ch = j & 7;
            uint32_t off = (uint32_t)(r*128 + ch*16);
            uint32_t sw = off ^ ((off >> 3) & 0x70u);
            const fp16* src = K + (size_t)(kc0 + r)*DD + p*64 + ch*8;
            cpa16(stg + p*8192 + sw, src);
        } else {                              // V: 128 rows (d) x 64 t = 128B rows
            int j = i - 1024;
            int r = j >> 3, ch = j & 7;
            uint32_t off = (uint32_t)(r*128 + ch*16);
            uint32_t sw = off ^ ((off >> 3) & 0x70u);
            const fp16* src = V + (size_t)r*TT + kc0 + ch*8;
            cpa16(stg + 16384 + sw, src);
        }
    }
    CP_COMMIT();
}

// ---------------- fused flash attention (fp16 2-term) ----------------------
// grid (16 qtiles, 32 bh); 256 thr; 8 warps x 16 q-rows; kc tile = 64
__global__ __launch_bounds__(256, 1) void flash_attn(
    const fp16* __restrict__ qh, const fp16* __restrict__ ql,
    const fp16* __restrict__ kk, const fp16* __restrict__ vt,
    fp16* __restrict__ ah)
{
    extern __shared__ __align__(16) uint8_t dyns[];
    const int tid = threadIdx.x;
    uint32_t raw = smem_u32(dyns);
    uint32_t sb0 = (raw + 1023u) & ~1023u;
    uint32_t pad = sb0 - raw;

    const int qt = blockIdx.x;
    const int bh = blockIdx.y;
    const int b = bh >> 4, h = bh & 15;

    const fp16* Qh = qh + ((size_t)(b*TT) + qt*128)*DD + h*HD;
    const fp16* Ql = ql + ((size_t)(b*TT) + qt*128)*DD + h*HD;
    const fp16* K  = kk + (size_t)(b*TT)*DD + h*HD;
    const fp16* V  = vt + (size_t)bh*HD*TT;

    const int lane = tid & 31, wid = tid >> 5;
    const int g8 = lane & 7, q2 = lane >> 3;
    const int gid = lane >> 2, tig = lane & 3;

    // Q: 4 panels of 16KB (Qh p0, Qh p1 | Ql p0, Ql p1) at sb0..64KB
    #pragma unroll
    for (int t = 0; t < 16; t++) {
        int i = tid + t*256;
        int half = i >> 11, j = i & 2047;
        int pd = j >> 10, jj = j & 1023;
        int r = jj >> 3, ch = jj & 7;
        uint32_t off = (uint32_t)(r*128 + ch*16);
        uint32_t sw = off ^ ((off >> 3) & 0x70u);
        const fp16* src = (half ? Ql : Qh) + (size_t)r*DD + pd*64 + ch*8;
        cpa16(sb0 + half*32768 + pd*16384 + sw, src);
    }
    CP_COMMIT();
    flash_ldkv(sb0 + 65536, 0,  K, V, tid);
    flash_ldkv(sb0 + 98304, 64, K, V, tid);

    float c_o[16][4];
    #pragma unroll
    for (int i = 0; i < 16; i++)
        #pragma unroll
        for (int e = 0; e < 4; e++) c_o[i][e] = 0.f;
    float m0 = -1e30f, m1 = -1e30f, l0 = 0.f, l1 = 0.f;

    for (int t = 0; t < 32; t++) {
        if (t < 31) asm volatile("cp.async.wait_group 1;" ::: "memory");
        else        asm volatile("cp.async.wait_group 0;" ::: "memory");
        __syncthreads();
        const uint32_t stg = sb0 + 65536 + (t & 1)*32768;

        // ---- S = Q @ K^T (128 x 64, Q split-2, K plain) ----
        float c_s[8][4];
        #pragma unroll
        for (int i = 0; i < 8; i++)
            #pragma unroll
            for (int e = 0; e < 4; e++) c_s[i][e] = 0.f;

        #pragma unroll
        for (int k16 = 0; k16 < 8; k16++) {
            const int pd = k16 >> 2;
            uint32_t qa = sw_addr(sb0 + pd*16384, wid*16 + g8 + ((q2 & 1) << 3),
                                  (k16 & 3)*2 + (q2 >> 1));
            uint32_t qah[4], qal[4];
            ldsm4(qah, qa);
            ldsm4(qal, qa + 32768);
            uint32_t kbh[8][2];
            #pragma unroll
            for (int nj = 0; nj < 4; nj++) {
                uint32_t ka = sw_addr(stg + pd*8192, nj*16 + g8 + ((q2 >> 1) << 3),
                                      (k16 & 3)*2 + (q2 & 1));
                uint32_t r4[4];
                ldsm4(r4, ka);
                kbh[2*nj][0] = r4[0]; kbh[2*nj][1] = r4[1];
                kbh[2*nj+1][0] = r4[2]; kbh[2*nj+1][1] = r4[3];
            }
            #pragma unroll
            for (int nj = 0; nj < 8; nj++) {
                mma16816h(c_s[nj], qah, kbh[nj]);
                mma16816h(c_s[nj], qal, kbh[nj]);
            }
        }

        // ---- online softmax ----
        float tm0 = -1e30f, tm1 = -1e30f;
        #pragma unroll
        for (int nj = 0; nj < 8; nj++) {
            tm0 = fmaxf(tm0, fmaxf(c_s[nj][0], c_s[nj][1]));
            tm1 = fmaxf(tm1, fmaxf(c_s[nj][2], c_s[nj][3]));
        }
        tm0 = fmaxf(tm0, __shfl_xor_sync(0xffffffffu, tm0, 1));
        tm0 = fmaxf(tm0, __shfl_xor_sync(0xffffffffu, tm0, 2));
        tm1 = fmaxf(tm1, __shfl_xor_sync(0xffffffffu, tm1, 1));
        tm1 = fmaxf(tm1, __shfl_xor_sync(0xffffffffu, tm1, 2));
        const float mn0 = fmaxf(m0, tm0), mn1 = fmaxf(m1, tm1);
        const float a0 = __expf(m0 - mn0), a1 = __expf(m1 - mn1);
        float rs0 = 0.f, rs1 = 0.f;
        #pragma unroll
        for (int nj = 0; nj < 8; nj++) {
            c_s[nj][0] = __expf(c_s[nj][0] - mn0);
            c_s[nj][1] = __expf(c_s[nj][1] - mn0);
            c_s[nj][2] = __expf(c_s[nj][2] - mn1);
            c_s[nj][3] = __expf(c_s[nj][3] - mn1);
            rs0 += c_s[nj][0] + c_s[nj][1];
            rs1 += c_s[nj][2] + c_s[nj][3];
        }
        rs0 += __shfl_xor_sync(0xffffffffu, rs0, 1);
        rs0 += __shfl_xor_sync(0xffffffffu, rs0, 2);
        rs1 += __shfl_xor_sync(0xffffffffu, rs1, 1);
        rs1 += __shfl_xor_sync(0xffffffffu, rs1, 2);
        l0 = l0*a0 + rs0;  l1 = l1*a1 + rs1;
        m0 = mn0;          m1 = mn1;
        #pragma unroll
        for (int nb = 0; nb < 16; nb++) {
            c_o[nb][0] *= a0; c_o[nb][1] *= a0;
            c_o[nb][2] *= a1; c_o[nb][3] *= a1;
        }

        // ---- O += P @ V  (P split-2 in registers, V plain) ----
        #pragma unroll
        for (int kb = 0; kb < 4; kb++) {
            uint32_t pah[4], pal[4];
            pah[0] = packsplit_h(c_s[2*kb][0],   c_s[2*kb][1],   pal[0]);
            pah[1] = packsplit_h(c_s[2*kb][2],   c_s[2*kb][3],   pal[1]);
            pah[2] = packsplit_h(c_s[2*kb+1][0], c_s[2*kb+1][1], pal[2]);
            pah[3] = packsplit_h(c_s[2*kb+1][2], c_s[2*kb+1][3], pal[3]);
            #pragma unroll
            for (int nj2 = 0; nj2 < 8; nj2++) {
                uint32_t va = sw_addr(stg + 16384, nj2*16 + g8 + ((q2 >> 1) << 3),
                                      kb*2 + (q2 & 1));
                uint32_t vh4[4];
                ldsm4(vh4, va);
                uint32_t b0[2] = {vh4[0], vh4[1]}, b1[2] = {vh4[2], vh4[3]};
                mma16816h(c_o[2*nj2],   pah, b0);
                mma16816h(c_o[2*nj2],   pal, b0);
                mma16816h(c_o[2*nj2+1], pah, b1);
                mma16816h(c_o[2*nj2+1], pal, b1);
            }
        }

        __syncthreads();
        if (t + 2 < 32)
            flash_ldkv(sb0 + 65536 + (t & 1)*32768, (t+2)*64, K, V, tid);
    }

    // ---- epilogue: O/l -> padded fp32 smem -> coalesced fp16 write ----
    float* smemf = (float*)(dyns + pad);   // reuse Q region (done), [128][132]
    {
        const float r0i = 1.0f / l0, r1i = 1.0f / l1;
        const int row0 = wid*16 + gid, row1 = row0 + 8;
        #pragma unroll
        for (int nb = 0; nb < 16; nb++) {
            const int col = nb*8 + tig*2;
            smemf[row0*132 + col]     = c_o[nb][0]*r0i;
            smemf[row0*132 + col + 1] = c_o[nb][1]*r0i;
            smemf[row1*132 + col]     = c_o[nb][2]*r1i;
            smemf[row1*132 + col + 1] = c_o[nb][3]*r1i;
        }
    }
    __syncthreads();
    for (int v = tid; v < 4096; v += 256) {
        const int row = v >> 5, c4 = (v & 31) << 2;
        float4 val = *(const float4*)&smemf[row*132 + c4];
        const size_t go = ((size_t)(b*TT) + qt*128 + row)*DD + h*HD + c4;
        *(uint32_t*)&ah[go]   = pack_h(val.x, val.y);
        *(uint32_t*)&ah[go+2] = pack_h(val.z, val.w);
    }
}

// ---------------- elementwise convert: fp32 -> fp16 ------------------------
__global__ __launch_bounds__(256) void convert4h(const float* __restrict__ in,
    fp16* __restrict__ oh, int n4)
{
    int i = blockIdx.x*256 + threadIdx.x;
    if (i >= n4) return;
    float4 v = ((const float4*)in)[i];
    ((uint32_t*)oh)[i*2]   = pack_h(v.x, v.y);
    ((uint32_t*)oh)[i*2+1] = pack_h(v.z, v.w);
}

// ---------------- weight transpose -> plain fp16 ---------------------------
__global__ void transpose_h(const float* __restrict__ in, fp16* __restrict__ out, int n)
{
    __shared__ float t[32][33];
    const int r0 = blockIdx.y*32, c0 = blockIdx.x*32;
    const int tx = threadIdx.x, ty = threadIdx.y;
    #pragma unroll
    for (int i = 0; i < 32; i += 8)
        t[ty+i][tx] = in[(size_t)(r0+ty+i)*n + c0+tx];
    __syncthreads();
    #pragma unroll
    for (int i = 0; i < 32; i += 8)
        out[(size_t)(c0+ty+i)*n + r0 + tx] = __float2half_rn(t[tx][ty+i]);
}

// ---------------- V transpose -> plain fp16 [b,h,d,t] -----------------------
__global__ void transpose_v(const float* __restrict__ in, fp16* __restrict__ out)
{
    __shared__ float t[32][33];
    const int z = blockIdx.z, zb = z >> 4, zh = z & 15;
    const float* pin = in + (size_t)zb*TT*DD + (size_t)zh*HD;
    fp16* pout = out + (size_t)z*HD*TT;
    const int r0 = blockIdx.y*32, c0 = blockIdx.x*32;   // r = t, c = d
    const int tx = threadIdx.x, ty = threadIdx.y;
    #pragma unroll
    for (int i = 0; i < 32; i += 8)
        t[ty+i][tx] = pin[(size_t)(r0+ty+i)*DD + c0+tx];
    __syncthreads();
    #pragma unroll
    for (int i = 0; i < 32; i += 8)
        pout[(size_t)(c0+ty+i)*TT + r0 + tx] = __float2half_rn(t[tx][ty+i]);
}

// ---------------- fused rmsnorm + rope -> fp16 (hi + optional lo) ----------
__global__ __launch_bounds__(256) void rmsnorm_rope_h(
    const float* __restrict__ in, const float* __restrict__ g,
    const float* __restrict__ cosp, const float* __restrict__ sinp,
    float scale, fp16* __restrict__ oh, fp16* __restrict__ ol)
{
    __shared__ float s[DD];
    __shared__ float red[8];
    const int row = blockIdx.x;
    const int t = row & (TT - 1);
    const float* p = in + (size_t)row * DD;
    const int tid = threadIdx.x;

    float ss = 0.f;
    for (int c = tid; c < DD; c += 256) { float x = p[c]; s[c] = x; ss += x*x; }
    #pragma unroll
    for (int o = 16; o > 0; o >>= 1) ss += __shfl_xor_sync(0xffffffffu, ss, o);
    if ((tid & 31) == 0) red[tid >> 5] = ss;
    __syncthreads();
    float tot = red[0]+red[1]+red[2]+red[3]+red[4]+red[5]+red[6]+red[7];
    const float inv = rsqrtf(tot * (1.0f / (float)DD) + 1e-6f);

    for (int c = tid; c < DD; c += 256) {
        const int pidx = c & 127;
        const int base = c - pidx;
        float o;
        if (pidx < 64) {
            float x1 = s[c] * inv * g[c];
            float x2 = s[base + 64 + pidx] * inv * g[base + 64 + pidx];
            o = x1 * cosp[t*64 + pidx] - sinp[t*64 + pidx] * x2;
        } else {
            const int pp = pidx - 64;
            float x2 = s[c] * inv * g[c];
            float x1 = s[base + pp] * inv * g[base + pp];
            o = x2 * cosp[t*64 + pp] + sinp[t*64 + pp] * x1;
        }
        o *= scale;
        fp16 h = __float2half_rn(o);
        oh[(size_t)row*DD + c] = h;
        if (ol) ol[(size_t)row*DD + c] = __float2half_rn(o - __half2float(h));
    }
}

// ---------------------------------------------------------------------------
extern "C" void kernel_launch(void* const* d_in, const int* in_sizes, int n_in,
                              void* d_out, int out_size)
{
    const float* x    = (const float*)d_in[0];
    const float* cosp = (const float*)d_in[1];
    const float* sinp = (const float*)d_in[2];
    const float* w[5] = { (const float*)d_in[3], (const float*)d_in[5],
                          (const float*)d_in[7], (const float*)d_in[11],
                          (const float*)d_in[13] };
    const float* bq = (const float*)d_in[4];
    const float* bk = (const float*)d_in[6];
    const float* bv = (const float*)d_in[8];
    const float* gq = (const float*)d_in[9];
    const float* gk = (const float*)d_in[10];
    const float* bo = (const float*)d_in[12];
    const float* bg = (const float*)d_in[14];
    float* out = (float*)d_out;

    fp16 *xh, *wt, *qh, *ql, *kh, *vt, *ah, *oh;
    float *tmp, *of;
    cudaGetSymbolAddress((void**)&xh, g_xh);
    cudaGetSymbolAddress((void**)&wt, g_wt);
    cudaGetSymbolAddress((void**)&tmp, g_tmp);
    cudaGetSymbolAddress((void**)&qh, g_qh);   cudaGetSymbolAddress((void**)&ql, g_ql);
    cudaGetSymbolAddress((void**)&kh, g_kh);
    cudaGetSymbolAddress((void**)&vt, g_vt);
    cudaGetSymbolAddress((void**)&ah, g_ah);
    cudaGetSymbolAddress((void**)&of, g_of);
    cudaGetSymbolAddress((void**)&oh, g_oh);

    // gemm: dynamic smem = max(2 stages, epilogue 256x132 fp32) + align pad
    const int SMEMSZ  = 256*132*4 + 1024;         // 136192 > 2*STG_SZ (98304)
    const int SMEMF   = 65536 + 2*32768 + 1024;   // flash: Q 64KB + 2 x 32KB stages
    cudaFuncSetAttribute(gemm_h2, cudaFuncAttributeMaxDynamicSharedMemorySize, SMEMSZ);
    cudaFuncSetAttribute(flash_attn, cudaFuncAttributeMaxDynamicSharedMemorySize, SMEMF);

    dim3 blk(256), tb(32, 8);
    const long DDl = DD;

    // input + weight prep
    convert4h<<<(MROWS*DD/4 + 255)/256, blk>>>(x, xh, MROWS*DD/4);
    for (int i = 0; i < 5; i++)
        transpose_h<<<dim3(64,64,1), tb>>>(w[i], wt + (size_t)i*DD*DD, DD);

    dim3 gproj(DD/128, MROWS/256, 1);   // (16, 16)

    // Q  (single-pass x)
    gemm_h2<<<gproj, blk, SMEMSZ>>>(xh, DDl, wt, DDl,
        bq, nullptr, tmp, nullptr, DDl, DD, 0);
    rmsnorm_rope_h<<<MROWS, blk>>>(tmp, gq, cosp, sinp, 0.08838834764831845f, qh, ql);
    // K  (single-pass x; K output plain fp16)
    gemm_h2<<<gproj, blk, SMEMSZ>>>(xh, DDl, wt + (size_t)DD*DD, DDl,
        bk, nullptr, tmp, nullptr, DDl, DD, 0);
    rmsnorm_rope_h<<<MROWS, blk>>>(tmp, gk, cosp, sinp, 1.0f, kh, nullptr);
    // V  (single-pass x; + transpose to [b,h,d,t] plain fp16)
    gemm_h2<<<gproj, blk, SMEMSZ>>>(xh, DDl, wt + 2ULL*DD*DD, DDl,
        bv, nullptr, tmp, nullptr, DDl, DD, 0);
    transpose_v<<<dim3(4,64,NB), tb>>>(tmp, vt);

    // fused attention (scale folded into q) -> plain fp16 attn
    flash_attn<<<dim3(16, 32), blk, SMEMF>>>(qh, ql, kh, vt, ah);

    // out proj — single-pass fp16 A (attn), fp32 + fp16-hi epilogue
    gemm_h2<<<gproj, blk, SMEMSZ>>>(ah, DDl, wt + 3ULL*DD*DD, DDl,
        bo, nullptr, of, oh, DDl, DD, 2);
    // gate — single-pass fp16 A (oh): out = of * sigmoid(oh @ wg + bg)
    gemm_h2<<<gproj, blk, SMEMSZ>>>(oh, DDl, wt + 4ULL*DD*DD, DDl,
        bg, of, out, nullptr, DDl, DD, 3);
}

// round 12
// speedup vs baseline: 7.6042x; 1.1593x over previous
#include <cuda_runtime.h>
#include <cuda_bf16.h>
#include <cuda_fp16.h>
#include <cstdint>
#include <math.h>

#define BB 2
#define TT 2048
#define DD 2048
#define HH 16
#define HD 128
#define MROWS (BB*TT)     // 4096
#define NB (BB*HH)        // 32

typedef __half fp16;

// ---------------- scratch (device globals; allocation-free rule) ----------
__device__ fp16  g_xh[(size_t)MROWS*DD];                         // x plain fp16
__device__ fp16  g_wt[5ULL*DD*DD];                               // transposed fp16 weights
__device__ float g_tmp[(size_t)MROWS*DD];                        // fp32 proj out
__device__ fp16  g_qh[(size_t)MROWS*DD];                         // Q plain fp16
__device__ fp16  g_kh[(size_t)MROWS*DD];                         // K plain fp16
__device__ fp16  g_vt[(size_t)NB*HD*TT];                         // v^T [b,h,d,t] plain fp16
__device__ fp16  g_ah[(size_t)MROWS*DD];                         // attn plain fp16
__device__ float g_of[(size_t)MROWS*DD];
__device__ fp16  g_oh[(size_t)MROWS*DD];

// ---------------- PTX helpers (plain sm_80+ PTX only) ---------------------
__device__ __forceinline__ uint32_t smem_u32(const void* p) {
    uint32_t a;
    asm("{ .reg .u64 t; cvta.to.shared.u64 t, %1; cvt.u32.u64 %0, t; }" : "=r"(a) : "l"(p));
    return a;
}
__device__ __forceinline__ void cpa16(uint32_t s, const void* g) {
    asm volatile("cp.async.cg.shared.global [%0], [%1], 16;" :: "r"(s), "l"(g));
}
#define CP_COMMIT()  asm volatile("cp.async.commit_group;" ::: "memory")

__device__ __forceinline__ void ldsm4(uint32_t* r, uint32_t a) {
    asm volatile("ldmatrix.sync.aligned.m8n8.x4.shared.b16 {%0,%1,%2,%3}, [%4];"
        : "=r"(r[0]), "=r"(r[1]), "=r"(r[2]), "=r"(r[3]) : "r"(a));
}
__device__ __forceinline__ void mma16816h(float* c, const uint32_t* a, const uint32_t* b) {
    asm volatile("mma.sync.aligned.m16n8k16.row.col.f32.f16.f16.f32 "
        "{%0,%1,%2,%3}, {%4,%5,%6,%7}, {%8,%9}, {%0,%1,%2,%3};"
        : "+f"(c[0]), "+f"(c[1]), "+f"(c[2]), "+f"(c[3])
        : "r"(a[0]), "r"(a[1]), "r"(a[2]), "r"(a[3]), "r"(b[0]), "r"(b[1]));
}
__device__ __forceinline__ uint32_t sw_addr(uint32_t base, int row, int ch) {
    uint32_t off = (uint32_t)(row*128 + ch*16);
    return base + (off ^ ((off >> 3) & 0x70u));
}
__device__ __forceinline__ uint32_t pack_h(float a, float b) {
    __half2 H(__float2half_rn(a), __float2half_rn(b));
    return *(uint32_t*)&H;
}

// ============ 256x128x64 GEMM (fp16 single-pass) ============================
// stage layout (48KB): A 32KB | B 16KB
#define STG_SZ 49152

__device__ __forceinline__ void ld_stage256(uint32_t sb,
    const fp16* A, long lda, const fp16* B, long ldb,
    int m0, int n0, int k0, int tid)
{
    #pragma unroll
    for (int t = 0; t < 12; t++) {
        int i = tid + t*256;
        if (i < 2048) {                       // A: 256 rows x 128B
            int r = i >> 3, ch = i & 7;
            uint32_t off = (uint32_t)(r*128 + ch*16);
            uint32_t sw = off ^ ((off >> 3) & 0x70u);
            cpa16(sb + sw, A + (size_t)(m0 + r)*lda + k0 + ch*8);
        } else {                              // B: 128 rows x 128B
            int j = i - 2048;
            int r = j >> 3, ch = j & 7;
            uint32_t off = (uint32_t)(r*128 + ch*16);
            uint32_t sw = off ^ ((off >> 3) & 0x70u);
            cpa16(sb + 32768 + sw, B + (size_t)(n0 + r)*ldb + k0 + ch*8);
        }
    }
    CP_COMMIT();
}

// epi: 0 = fp32 (+bias), 2 = fp32 + fp16 hi, 3 = gate
__global__ __launch_bounds__(256, 1) void gemm_h2(
    const fp16* __restrict__ A, long lda,
    const fp16* __restrict__ B, long ldb,
    const float* __restrict__ bias, const float* __restrict__ mul,
    float* __restrict__ Cf, fp16* __restrict__ Ch,
    long ldc, int K, int epi)
{
    extern __shared__ __align__(16) uint8_t dyns[];
    const int tid = threadIdx.x;
    uint32_t raw = smem_u32(dyns);
    uint32_t sb0 = (raw + 1023u) & ~1023u;
    uint32_t pad = sb0 - raw;

    const int m0 = blockIdx.y * 256, n0 = blockIdx.x * 128;
    const int lane = tid & 31, wid = tid >> 5;
    const int wm = wid >> 1, wn = wid & 1;       // 4 x 2 warps, each 64x64
    const int g8 = lane & 7, q = lane >> 3;

    float c[4][8][4];
    #pragma unroll
    for (int i = 0; i < 4; i++)
        #pragma unroll
        for (int j = 0; j < 8; j++)
            #pragma unroll
            for (int e = 0; e < 4; e++) c[i][j][e] = 0.f;

    const int nch = K >> 6;
    ld_stage256(sb0, A, lda, B, ldb, m0, n0, 0, tid);

    for (int cc = 0; cc < nch; cc++) {
        const int s = cc & 1;
        const uint32_t sbs = sb0 + s*STG_SZ;
        if (cc + 1 < nch) {
            ld_stage256(sb0 + (s^1)*STG_SZ, A, lda, B, ldb, m0, n0, (cc+1)*64, tid);
            asm volatile("cp.async.wait_group 1;" ::: "memory");
        } else {
            asm volatile("cp.async.wait_group 0;" ::: "memory");
        }
        __syncthreads();

        #pragma unroll
        for (int k16 = 0; k16 < 4; k16++) {
            uint32_t bh[8][2];
            #pragma unroll
            for (int nj = 0; nj < 4; nj++) {
                int row = wn*64 + nj*16 + g8 + ((q >> 1) << 3);
                int ch  = k16*2 + (q & 1);
                uint32_t r4[4];
                ldsm4(r4, sw_addr(sbs + 32768, row, ch));
                bh[2*nj][0] = r4[0]; bh[2*nj][1] = r4[1];
                bh[2*nj+1][0] = r4[2]; bh[2*nj+1][1] = r4[3];
            }
            #pragma unroll
            for (int mi = 0; mi < 4; mi++) {
                int row = wm*64 + mi*16 + g8 + ((q & 1) << 3);
                int ch  = k16*2 + (q >> 1);
                uint32_t ah4[4];
                ldsm4(ah4, sw_addr(sbs, row, ch));
                #pragma unroll
                for (int ni = 0; ni < 8; ni++)
                    mma16816h(c[mi][ni], ah4, bh[ni]);
            }
        }
        __syncthreads();
    }

    // ---- epilogue: frags -> padded fp32 smem [256][132] -> coalesced gmem ----
    float* smemf = (float*)(dyns + pad);
    {
        const int gid = lane >> 2, tig = lane & 3;
        #pragma unroll
        for (int mi = 0; mi < 4; mi++)
            #pragma unroll
            for (int ni = 0; ni < 8; ni++) {
                int r0 = wm*64 + mi*16 + gid;
                int col = wn*64 + ni*8 + tig*2;
                *(float2*)&smemf[r0*132 + col]     = make_float2(c[mi][ni][0], c[mi][ni][1]);
                *(float2*)&smemf[(r0+8)*132 + col] = make_float2(c[mi][ni][2], c[mi][ni][3]);
            }
    }
    __syncthreads();

    for (int v = tid; v < 8192; v += 256) {
        const int row = v >> 5, c4 = (v & 31) << 2;
        float4 val = *(const float4*)&smemf[row*132 + c4];
        const int gc = n0 + c4;
        const size_t go = (size_t)(m0 + row)*ldc + gc;
        if (bias) {
            val.x += bias[gc]; val.y += bias[gc+1]; val.z += bias[gc+2]; val.w += bias[gc+3];
        }
        if (epi == 0) {
            *(float4*)&Cf[go] = val;
        } else if (epi == 2) {
            *(float4*)&Cf[go] = val;
            *(uint32_t*)&Ch[go]   = pack_h(val.x, val.y);
            *(uint32_t*)&Ch[go+2] = pack_h(val.z, val.w);
        } else {  // gate
            const float4 m = *(const float4*)&mul[go];
            float4 o;
            o.x = m.x / (1.0f + __expf(-val.x));
            o.y = m.y / (1.0f + __expf(-val.y));
            o.z = m.z / (1.0f + __expf(-val.z));
            o.w = m.w / (1.0f + __expf(-val.w));
            *(float4*)&Cf[go] = o;
        }
    }
}

// ---------------- flash attention KV stage loader (plain fp16) -------------
// stage layout (32KB): K 2 panels of 8KB | V 16KB
__device__ __forceinline__ void flash_ldkv(uint32_t stg, int kc0,
    const fp16* K, const fp16* V, int tid)
{
    #pragma unroll
    for (int t = 0; t < 8; t++) {
        int i = tid + t*256;
        if (i < 1024) {                       // K: 64 rows x 2 panels x 128B
            int p = i >> 9, j = i & 511;
            int r = j >> 3, ch = j & 7;
            uint32_t off = (uint32_t)(r*128 + ch*16);
            uint32_t sw = off ^ ((off >> 3) & 0x70u);
            const fp16* src = K + (size_t)(kc0 + r)*DD + p*64 + ch*8;
            cpa16(stg + p*8192 + sw, src);
        } else {                              // V: 128 rows (d) x 64 t = 128B rows
            int j = i - 1024;
            int r = j >> 3, ch = j & 7;
            uint32_t off = (uint32_t)(r*128 + ch*16);
            uint32_t sw = off ^ ((off >> 3) & 0x70u);
            const fp16* src = V + (size_t)r*TT + kc0 + ch*8;
            cpa16(stg + 16384 + sw, src);
        }
    }
    CP_COMMIT();
}

// ---------------- fused flash attention (fp16 single-pass) -----------------
// grid (16 qtiles, 32 bh); 256 thr; 8 warps x 16 q-rows; kc tile = 64
__global__ __launch_bounds__(256, 1) void flash_attn(
    const fp16* __restrict__ qq, const fp16* __restrict__ kk,
    const fp16* __restrict__ vt, fp16* __restrict__ ah)
{
    extern __shared__ __align__(16) uint8_t dyns[];
    const int tid = threadIdx.x;
    uint32_t raw = smem_u32(dyns);
    uint32_t sb0 = (raw + 1023u) & ~1023u;
    uint32_t pad = sb0 - raw;

    const int qt = blockIdx.x;
    const int bh = blockIdx.y;
    const int b = bh >> 4, h = bh & 15;

    const fp16* Q = qq + ((size_t)(b*TT) + qt*128)*DD + h*HD;
    const fp16* K = kk + (size_t)(b*TT)*DD + h*HD;
    const fp16* V = vt + (size_t)bh*HD*TT;

    const int lane = tid & 31, wid = tid >> 5;
    const int g8 = lane & 7, q2 = lane >> 3;
    const int gid = lane >> 2, tig = lane & 3;

    // Q: 2 panels of 16KB at sb0..32KB
    #pragma unroll
    for (int t = 0; t < 8; t++) {
        int i = tid + t*256;
        int pd = i >> 10, jj = i & 1023;
        int r = jj >> 3, ch = jj & 7;
        uint32_t off = (uint32_t)(r*128 + ch*16);
        uint32_t sw = off ^ ((off >> 3) & 0x70u);
        cpa16(sb0 + pd*16384 + sw, Q + (size_t)r*DD + pd*64 + ch*8);
    }
    CP_COMMIT();
    flash_ldkv(sb0 + 32768, 0,  K, V, tid);
    flash_ldkv(sb0 + 65536, 64, K, V, tid);

    float c_o[16][4];
    #pragma unroll
    for (int i = 0; i < 16; i++)
        #pragma unroll
        for (int e = 0; e < 4; e++) c_o[i][e] = 0.f;
    float m0 = -1e30f, m1 = -1e30f, l0 = 0.f, l1 = 0.f;

    for (int t = 0; t < 32; t++) {
        if (t < 31) asm volatile("cp.async.wait_group 1;" ::: "memory");
        else        asm volatile("cp.async.wait_group 0;" ::: "memory");
        __syncthreads();
        const uint32_t stg = sb0 + 32768 + (t & 1)*32768;

        // ---- S = Q @ K^T (128 x 64, single-pass) ----
        float c_s[8][4];
        #pragma unroll
        for (int i = 0; i < 8; i++)
            #pragma unroll
            for (int e = 0; e < 4; e++) c_s[i][e] = 0.f;

        #pragma unroll
        for (int k16 = 0; k16 < 8; k16++) {
            const int pd = k16 >> 2;
            uint32_t qa = sw_addr(sb0 + pd*16384, wid*16 + g8 + ((q2 & 1) << 3),
                                  (k16 & 3)*2 + (q2 >> 1));
            uint32_t qah[4];
            ldsm4(qah, qa);
            uint32_t kbh[8][2];
            #pragma unroll
            for (int nj = 0; nj < 4; nj++) {
                uint32_t ka = sw_addr(stg + pd*8192, nj*16 + g8 + ((q2 >> 1) << 3),
                                      (k16 & 3)*2 + (q2 & 1));
                uint32_t r4[4];
                ldsm4(r4, ka);
                kbh[2*nj][0] = r4[0]; kbh[2*nj][1] = r4[1];
                kbh[2*nj+1][0] = r4[2]; kbh[2*nj+1][1] = r4[3];
            }
            #pragma unroll
            for (int nj = 0; nj < 8; nj++)
                mma16816h(c_s[nj], qah, kbh[nj]);
        }

        // ---- online softmax ----
        float tm0 = -1e30f, tm1 = -1e30f;
        #pragma unroll
        for (int nj = 0; nj < 8; nj++) {
            tm0 = fmaxf(tm0, fmaxf(c_s[nj][0], c_s[nj][1]));
            tm1 = fmaxf(tm1, fmaxf(c_s[nj][2], c_s[nj][3]));
        }
        tm0 = fmaxf(tm0, __shfl_xor_sync(0xffffffffu, tm0, 1));
        tm0 = fmaxf(tm0, __shfl_xor_sync(0xffffffffu, tm0, 2));
        tm1 = fmaxf(tm1, __shfl_xor_sync(0xffffffffu, tm1, 1));
        tm1 = fmaxf(tm1, __shfl_xor_sync(0xffffffffu, tm1, 2));
        const float mn0 = fmaxf(m0, tm0), mn1 = fmaxf(m1, tm1);
        const float a0 = __expf(m0 - mn0), a1 = __expf(m1 - mn1);
        float rs0 = 0.f, rs1 = 0.f;
        #pragma unroll
        for (int nj = 0; nj < 8; nj++) {
            c_s[nj][0] = __expf(c_s[nj][0] - mn0);
            c_s[nj][1] = __expf(c_s[nj][1] - mn0);
            c_s[nj][2] = __expf(c_s[nj][2] - mn1);
            c_s[nj][3] = __expf(c_s[nj][3] - mn1);
            rs0 += c_s[nj][0] + c_s[nj][1];
            rs1 += c_s[nj][2] + c_s[nj][3];
        }
        rs0 += __shfl_xor_sync(0xffffffffu, rs0, 1);
        rs0 += __shfl_xor_sync(0xffffffffu, rs0, 2);
        rs1 += __shfl_xor_sync(0xffffffffu, rs1, 1);
        rs1 += __shfl_xor_sync(0xffffffffu, rs1, 2);
        l0 = l0*a0 + rs0;  l1 = l1*a1 + rs1;
        m0 = mn0;          m1 = mn1;
        #pragma unroll
        for (int nb = 0; nb < 16; nb++) {
            c_o[nb][0] *= a0; c_o[nb][1] *= a0;
            c_o[nb][2] *= a1; c_o[nb][3] *= a1;
        }

        // ---- O += P @ V  (P plain fp16 in registers, V plain) ----
        #pragma unroll
        for (int kb = 0; kb < 4; kb++) {
            uint32_t pah[4];
            pah[0] = pack_h(c_s[2*kb][0],   c_s[2*kb][1]);
            pah[1] = pack_h(c_s[2*kb][2],   c_s[2*kb][3]);
            pah[2] = pack_h(c_s[2*kb+1][0], c_s[2*kb+1][1]);
            pah[3] = pack_h(c_s[2*kb+1][2], c_s[2*kb+1][3]);
            #pragma unroll
            for (int nj2 = 0; nj2 < 8; nj2++) {
                uint32_t va = sw_addr(stg + 16384, nj2*16 + g8 + ((q2 >> 1) << 3),
                                      kb*2 + (q2 & 1));
                uint32_t vh4[4];
                ldsm4(vh4, va);
                uint32_t b0[2] = {vh4[0], vh4[1]}, b1[2] = {vh4[2], vh4[3]};
                mma16816h(c_o[2*nj2],   pah, b0);
                mma16816h(c_o[2*nj2+1], pah, b1);
            }
        }

        __syncthreads();
        if (t + 2 < 32)
            flash_ldkv(sb0 + 32768 + (t & 1)*32768, (t+2)*64, K, V, tid);
    }

    // ---- epilogue: O/l -> padded fp32 smem -> coalesced fp16 write ----
    float* smemf = (float*)(dyns + pad);   // reuse, [128][132] = 67.6KB < 97KB
    {
        const float r0i = 1.0f / l0, r1i = 1.0f / l1;
        const int row0 = wid*16 + gid, row1 = row0 + 8;
        #pragma unroll
        for (int nb = 0; nb < 16; nb++) {
            const int col = nb*8 + tig*2;
            smemf[row0*132 + col]     = c_o[nb][0]*r0i;
            smemf[row0*132 + col + 1] = c_o[nb][1]*r0i;
            smemf[row1*132 + col]     = c_o[nb][2]*r1i;
            smemf[row1*132 + col + 1] = c_o[nb][3]*r1i;
        }
    }
    __syncthreads();
    for (int v = tid; v < 4096; v += 256) {
        const int row = v >> 5, c4 = (v & 31) << 2;
        float4 val = *(const float4*)&smemf[row*132 + c4];
        const size_t go = ((size_t)(b*TT) + qt*128 + row)*DD + h*HD + c4;
        *(uint32_t*)&ah[go]   = pack_h(val.x, val.y);
        *(uint32_t*)&ah[go+2] = pack_h(val.z, val.w);
    }
}

// ---------------- elementwise convert: fp32 -> fp16 ------------------------
__global__ __launch_bounds__(256) void convert4h(const float* __restrict__ in,
    fp16* __restrict__ oh, int n4)
{
    int i = blockIdx.x*256 + threadIdx.x;
    if (i >= n4) return;
    float4 v = ((const float4*)in)[i];
    ((uint32_t*)oh)[i*2]   = pack_h(v.x, v.y);
    ((uint32_t*)oh)[i*2+1] = pack_h(v.z, v.w);
}

// ---------------- weight transpose -> plain fp16 ---------------------------
__global__ void transpose_h(const float* __restrict__ in, fp16* __restrict__ out, int n)
{
    __shared__ float t[32][33];
    const int r0 = blockIdx.y*32, c0 = blockIdx.x*32;
    const int tx = threadIdx.x, ty = threadIdx.y;
    #pragma unroll
    for (int i = 0; i < 32; i += 8)
        t[ty+i][tx] = in[(size_t)(r0+ty+i)*n + c0+tx];
    __syncthreads();
    #pragma unroll
    for (int i = 0; i < 32; i += 8)
        out[(size_t)(c0+ty+i)*n + r0 + tx] = __float2half_rn(t[tx][ty+i]);
}

// ---------------- V transpose -> plain fp16 [b,h,d,t] -----------------------
__global__ void transpose_v(const float* __restrict__ in, fp16* __restrict__ out)
{
    __shared__ float t[32][33];
    const int z = blockIdx.z, zb = z >> 4, zh = z & 15;
    const float* pin = in + (size_t)zb*TT*DD + (size_t)zh*HD;
    fp16* pout = out + (size_t)z*HD*TT;
    const int r0 = blockIdx.y*32, c0 = blockIdx.x*32;   // r = t, c = d
    const int tx = threadIdx.x, ty = threadIdx.y;
    #pragma unroll
    for (int i = 0; i < 32; i += 8)
        t[ty+i][tx] = pin[(size_t)(r0+ty+i)*DD + c0+tx];
    __syncthreads();
    #pragma unroll
    for (int i = 0; i < 32; i += 8)
        pout[(size_t)(c0+ty+i)*TT + r0 + tx] = __float2half_rn(t[tx][ty+i]);
}

// ---------------- fused rmsnorm + rope -> plain fp16 -----------------------
__global__ __launch_bounds__(256) void rmsnorm_rope_h(
    const float* __restrict__ in, const float* __restrict__ g,
    const float* __restrict__ cosp, const float* __restrict__ sinp,
    float scale, fp16* __restrict__ oh)
{
    __shared__ float s[DD];
    __shared__ float red[8];
    const int row = blockIdx.x;
    const int t = row & (TT - 1);
    const float* p = in + (size_t)row * DD;
    const int tid = threadIdx.x;

    float ss = 0.f;
    for (int c = tid; c < DD; c += 256) { float x = p[c]; s[c] = x; ss += x*x; }
    #pragma unroll
    for (int o = 16; o > 0; o >>= 1) ss += __shfl_xor_sync(0xffffffffu, ss, o);
    if ((tid & 31) == 0) red[tid >> 5] = ss;
    __syncthreads();
    float tot = red[0]+red[1]+red[2]+red[3]+red[4]+red[5]+red[6]+red[7];
    const float inv = rsqrtf(tot * (1.0f / (float)DD) + 1e-6f);

    for (int c = tid; c < DD; c += 256) {
        const int pidx = c & 127;
        const int base = c - pidx;
        float o;
        if (pidx < 64) {
            float x1 = s[c] * inv * g[c];
            float x2 = s[base + 64 + pidx] * inv * g[base + 64 + pidx];
            o = x1 * cosp[t*64 + pidx] - sinp[t*64 + pidx] * x2;
        } else {
            const int pp = pidx - 64;
            float x2 = s[c] * inv * g[c];
            float x1 = s[base + pp] * inv * g[base + pp];
            o = x2 * cosp[t*64 + pp] + sinp[t*64 + pp] * x1;
        }
        o *= scale;
        oh[(size_t)row*DD + c] = __float2half_rn(o);
    }
}

// ---------------------------------------------------------------------------
extern "C" void kernel_launch(void* const* d_in, const int* in_sizes, int n_in,
                              void* d_out, int out_size)
{
    const float* x    = (const float*)d_in[0];
    const float* cosp = (const float*)d_in[1];
    const float* sinp = (const float*)d_in[2];
    const float* w[5] = { (const float*)d_in[3], (const float*)d_in[5],
                          (const float*)d_in[7], (const float*)d_in[11],
                          (const float*)d_in[13] };
    const float* bq = (const float*)d_in[4];
    const float* bk = (const float*)d_in[6];
    const float* bv = (const float*)d_in[8];
    const float* gq = (const float*)d_in[9];
    const float* gk = (const float*)d_in[10];
    const float* bo = (const float*)d_in[12];
    const float* bg = (const float*)d_in[14];
    float* out = (float*)d_out;

    fp16 *xh, *wt, *qh, *kh, *vt, *ah, *oh;
    float *tmp, *of;
    cudaGetSymbolAddress((void**)&xh, g_xh);
    cudaGetSymbolAddress((void**)&wt, g_wt);
    cudaGetSymbolAddress((void**)&tmp, g_tmp);
    cudaGetSymbolAddress((void**)&qh, g_qh);
    cudaGetSymbolAddress((void**)&kh, g_kh);
    cudaGetSymbolAddress((void**)&vt, g_vt);
    cudaGetSymbolAddress((void**)&ah, g_ah);
    cudaGetSymbolAddress((void**)&of, g_of);
    cudaGetSymbolAddress((void**)&oh, g_oh);

    // gemm: dynamic smem = max(2 stages, epilogue 256x132 fp32) + align pad
    const int SMEMSZ  = 256*132*4 + 1024;         // 136192 > 2*STG_SZ (98304)
    const int SMEMF   = 32768 + 2*32768 + 1024;   // flash: Q 32KB + 2 x 32KB stages
    cudaFuncSetAttribute(gemm_h2, cudaFuncAttributeMaxDynamicSharedMemorySize, SMEMSZ);
    cudaFuncSetAttribute(flash_attn, cudaFuncAttributeMaxDynamicSharedMemorySize, SMEMF);

    dim3 blk(256), tb(32, 8);
    const long DDl = DD;

    // input + weight prep
    convert4h<<<(MROWS*DD/4 + 255)/256, blk>>>(x, xh, MROWS*DD/4);
    for (int i = 0; i < 5; i++)
        transpose_h<<<dim3(64,64,1), tb>>>(w[i], wt + (size_t)i*DD*DD, DD);

    dim3 gproj(DD/128, MROWS/256, 1);   // (16, 16)

    // Q  (single-pass; Q output plain fp16)
    gemm_h2<<<gproj, blk, SMEMSZ>>>(xh, DDl, wt, DDl,
        bq, nullptr, tmp, nullptr, DDl, DD, 0);
    rmsnorm_rope_h<<<MROWS, blk>>>(tmp, gq, cosp, sinp, 0.08838834764831845f, qh);
    // K  (single-pass; K output plain fp16)
    gemm_h2<<<gproj, blk, SMEMSZ>>>(xh, DDl, wt + (size_t)DD*DD, DDl,
        bk, nullptr, tmp, nullptr, DDl, DD, 0);
    rmsnorm_rope_h<<<MROWS, blk>>>(tmp, gk, cosp, sinp, 1.0f, kh);
    // V  (single-pass; + transpose to [b,h,d,t] plain fp16)
    gemm_h2<<<gproj, blk, SMEMSZ>>>(xh, DDl, wt + 2ULL*DD*DD, DDl,
        bv, nullptr, tmp, nullptr, DDl, DD, 0);
    transpose_v<<<dim3(4,64,NB), tb>>>(tmp, vt);

    // fused attention (scale folded into q) -> plain fp16 attn
    flash_attn<<<dim3(16, 32), blk, SMEMF>>>(qh, kh, vt, ah);

    // out proj — single-pass fp16 A (attn), fp32 + fp16-hi epilogue
    gemm_h2<<<gproj, blk, SMEMSZ>>>(ah, DDl, wt + 3ULL*DD*DD, DDl,
        bo, nullptr, of, oh, DDl, DD, 2);
    // gate — single-pass fp16 A (oh): out = of * sigmoid(oh @ wg + bg)
    gemm_h2<<<gproj, blk, SMEMSZ>>>(oh, DDl, wt + 4ULL*DD*DD, DDl,
        bg, of, out, nullptr, DDl, DD, 3);
}

// round 14
// speedup vs baseline: 8.0180x; 1.0544x over previous
#include <cuda_runtime.h>
#include <cuda_bf16.h>
#include <cuda_fp16.h>
#include <cstdint>
#include <math.h>

#define BB 2
#define TT 2048
#define DD 2048
#define HH 16
#define HD 128
#define MROWS (BB*TT)     // 4096
#define NB (BB*HH)        // 32

typedef __half fp16;

// ---------------- scratch (device globals; allocation-free rule) ----------
__device__ fp16  g_xh[(size_t)MROWS*DD];                         // x plain fp16
__device__ fp16  g_wt[5ULL*DD*DD];                               // transposed fp16 weights
__device__ float g_tmp[(size_t)MROWS*DD];                        // fp32 proj out
__device__ fp16  g_qh[(size_t)MROWS*DD];                         // Q plain fp16
__device__ fp16  g_kh[(size_t)MROWS*DD];                         // K plain fp16
__device__ fp16  g_vt[(size_t)NB*HD*TT];                         // v^T [b,h,d,t] plain fp16
__device__ fp16  g_ah[(size_t)MROWS*DD];                         // attn plain fp16
__device__ float g_of[(size_t)MROWS*DD];
__device__ fp16  g_oh[(size_t)MROWS*DD];

// ---------------- PTX helpers (plain sm_80+ PTX only) ---------------------
__device__ __forceinline__ uint32_t smem_u32(const void* p) {
    uint32_t a;
    asm("{ .reg .u64 t; cvta.to.shared.u64 t, %1; cvt.u32.u64 %0, t; }" : "=r"(a) : "l"(p));
    return a;
}
__device__ __forceinline__ void cpa16(uint32_t s, const void* g) {
    asm volatile("cp.async.cg.shared.global [%0], [%1], 16;" :: "r"(s), "l"(g));
}
#define CP_COMMIT()  asm volatile("cp.async.commit_group;" ::: "memory")

__device__ __forceinline__ void ldsm4(uint32_t* r, uint32_t a) {
    asm volatile("ldmatrix.sync.aligned.m8n8.x4.shared.b16 {%0,%1,%2,%3}, [%4];"
        : "=r"(r[0]), "=r"(r[1]), "=r"(r[2]), "=r"(r[3]) : "r"(a));
}
__device__ __forceinline__ void mma16816h(float* c, const uint32_t* a, const uint32_t* b) {
    asm volatile("mma.sync.aligned.m16n8k16.row.col.f32.f16.f16.f32 "
        "{%0,%1,%2,%3}, {%4,%5,%6,%7}, {%8,%9}, {%0,%1,%2,%3};"
        : "+f"(c[0]), "+f"(c[1]), "+f"(c[2]), "+f"(c[3])
        : "r"(a[0]), "r"(a[1]), "r"(a[2]), "r"(a[3]), "r"(b[0]), "r"(b[1]));
}
__device__ __forceinline__ uint32_t sw_addr(uint32_t base, int row, int ch) {
    uint32_t off = (uint32_t)(row*128 + ch*16);
    return base + (off ^ ((off >> 3) & 0x70u));
}
__device__ __forceinline__ uint32_t pack_h(float a, float b) {
    __half2 H(__float2half_rn(a), __float2half_rn(b));
    return *(uint32_t*)&H;
}

// ============ 128x128x64 GEMM (fp16 single-pass, 2 CTAs/SM) =================
// stage layout (32KB): A 16KB | B 16KB
#define STG_SZ 32768

__device__ __forceinline__ void ld_stage128(uint32_t sb,
    const fp16* A, long lda, const fp16* B, long ldb,
    int m0, int n0, int k0, int tid)
{
    #pragma unroll
    for (int t = 0; t < 8; t++) {
        int i = tid + t*256;
        if (i < 1024) {                       // A: 128 rows x 128B
            int r = i >> 3, ch = i & 7;
            uint32_t off = (uint32_t)(r*128 + ch*16);
            uint32_t sw = off ^ ((off >> 3) & 0x70u);
            cpa16(sb + sw, A + (size_t)(m0 + r)*lda + k0 + ch*8);
        } else {                              // B: 128 rows x 128B
            int j = i - 1024;
            int r = j >> 3, ch = j & 7;
            uint32_t off = (uint32_t)(r*128 + ch*16);
            uint32_t sw = off ^ ((off >> 3) & 0x70u);
            cpa16(sb + 16384 + sw, B + (size_t)(n0 + r)*ldb + k0 + ch*8);
        }
    }
    CP_COMMIT();
}

// epi: 0 = fp32 (+bias), 2 = fp32 + fp16 hi, 3 = gate
__global__ __launch_bounds__(256, 2) void gemm_h2(
    const fp16* __restrict__ A, long lda,
    const fp16* __restrict__ B, long ldb,
    const float* __restrict__ bias, const float* __restrict__ mul,
    float* __restrict__ Cf, fp16* __restrict__ Ch,
    long ldc, int K, int epi)
{
    extern __shared__ __align__(16) uint8_t dyns[];
    const int tid = threadIdx.x;
    uint32_t raw = smem_u32(dyns);
    uint32_t sb0 = (raw + 1023u) & ~1023u;
    uint32_t pad = sb0 - raw;

    const int m0 = blockIdx.y * 128, n0 = blockIdx.x * 128;
    const int lane = tid & 31, wid = tid >> 5;
    const int wm = wid >> 1, wn = wid & 1;       // 4 x 2 warps, each 32x64
    const int g8 = lane & 7, q = lane >> 3;

    float c[2][8][4];
    #pragma unroll
    for (int i = 0; i < 2; i++)
        #pragma unroll
        for (int j = 0; j < 8; j++)
            #pragma unroll
            for (int e = 0; e < 4; e++) c[i][j][e] = 0.f;

    const int nch = K >> 6;
    ld_stage128(sb0, A, lda, B, ldb, m0, n0, 0, tid);

    for (int cc = 0; cc < nch; cc++) {
        const int s = cc & 1;
        const uint32_t sbs = sb0 + s*STG_SZ;
        if (cc + 1 < nch) {
            ld_stage128(sb0 + (s^1)*STG_SZ, A, lda, B, ldb, m0, n0, (cc+1)*64, tid);
            asm volatile("cp.async.wait_group 1;" ::: "memory");
        } else {
            asm volatile("cp.async.wait_group 0;" ::: "memory");
        }
        __syncthreads();

        #pragma unroll
        for (int k16 = 0; k16 < 4; k16++) {
            uint32_t bh[8][2];
            #pragma unroll
            for (int nj = 0; nj < 4; nj++) {
                int row = wn*64 + nj*16 + g8 + ((q >> 1) << 3);
                int ch  = k16*2 + (q & 1);
                uint32_t r4[4];
                ldsm4(r4, sw_addr(sbs + 16384, row, ch));
                bh[2*nj][0] = r4[0]; bh[2*nj][1] = r4[1];
                bh[2*nj+1][0] = r4[2]; bh[2*nj+1][1] = r4[3];
            }
            #pragma unroll
            for (int mi = 0; mi < 2; mi++) {
                int row = wm*32 + mi*16 + g8 + ((q & 1) << 3);
                int ch  = k16*2 + (q >> 1);
                uint32_t ah4[4];
                ldsm4(ah4, sw_addr(sbs, row, ch));
                #pragma unroll
                for (int ni = 0; ni < 8; ni++)
                    mma16816h(c[mi][ni], ah4, bh[ni]);
            }
        }
        __syncthreads();
    }

    // ---- epilogue: frags -> padded fp32 smem [128][132] -> coalesced gmem ----
    float* smemf = (float*)(dyns + pad);
    {
        const int gid = lane >> 2, tig = lane & 3;
        #pragma unroll
        for (int mi = 0; mi < 2; mi++)
            #pragma unroll
            for (int ni = 0; ni < 8; ni++) {
                int r0 = wm*32 + mi*16 + gid;
                int col = wn*64 + ni*8 + tig*2;
                *(float2*)&smemf[r0*132 + col]     = make_float2(c[mi][ni][0], c[mi][ni][1]);
                *(float2*)&smemf[(r0+8)*132 + col] = make_float2(c[mi][ni][2], c[mi][ni][3]);
            }
    }
    __syncthreads();

    for (int v = tid; v < 4096; v += 256) {
        const int row = v >> 5, c4 = (v & 31) << 2;
        float4 val = *(const float4*)&smemf[row*132 + c4];
        const int gc = n0 + c4;
        const size_t go = (size_t)(m0 + row)*ldc + gc;
        if (bias) {
            val.x += bias[gc]; val.y += bias[gc+1]; val.z += bias[gc+2]; val.w += bias[gc+3];
        }
        if (epi == 0) {
            *(float4*)&Cf[go] = val;
        } else if (epi == 2) {
            *(float4*)&Cf[go] = val;
            *(uint32_t*)&Ch[go]   = pack_h(val.x, val.y);
            *(uint32_t*)&Ch[go+2] = pack_h(val.z, val.w);
        } else {  // gate
            const float4 m = *(const float4*)&mul[go];
            float4 o;
            o.x = m.x / (1.0f + __expf(-val.x));
            o.y = m.y / (1.0f + __expf(-val.y));
            o.z = m.z / (1.0f + __expf(-val.z));
            o.w = m.w / (1.0f + __expf(-val.w));
            *(float4*)&Cf[go] = o;
        }
    }
}

// ---------------- flash attention KV stage loader (plain fp16) -------------
// stage layout (32KB): K 2 panels of 8KB | V 16KB
__device__ __forceinline__ void flash_ldkv(uint32_t stg, int kc0,
    const fp16* K, const fp16* V, int tid)
{
    #pragma unroll
    for (int t = 0; t < 8; t++) {
        int i = tid + t*256;
        if (i < 1024) {                       // K: 64 rows x 2 panels x 128B
            int p = i >> 9, j = i & 511;
            int r = j >> 3, ch = j & 7;
            uint32_t off = (uint32_t)(r*128 + ch*16);
            uint32_t sw = off ^ ((off >> 3) & 0x70u);
            const fp16* src = K + (size_t)(kc0 + r)*DD + p*64 + ch*8;
            cpa16(stg + p*8192 + sw, src);
        } else {                              // V: 128 rows (d) x 64 t = 128B rows
            int j = i - 1024;
            int r = j >> 3, ch = j & 7;
            uint32_t off = (uint32_t)(r*128 + ch*16);
            uint32_t sw = off ^ ((off >> 3) & 0x70u);
            const fp16* src = V + (size_t)r*TT + kc0 + ch*8;
            cpa16(stg + 16384 + sw, src);
        }
    }
    CP_COMMIT();
}

// ---------------- fused flash attention (fp16 single-pass) -----------------
// grid (16 qtiles, 32 bh); 256 thr; 8 warps x 16 q-rows; kc tile = 64
__global__ __launch_bounds__(256, 1) void flash_attn(
    const fp16* __restrict__ qq, const fp16* __restrict__ kk,
    const fp16* __restrict__ vt, fp16* __restrict__ ah)
{
    extern __shared__ __align__(16) uint8_t dyns[];
    const int tid = threadIdx.x;
    uint32_t raw = smem_u32(dyns);
    uint32_t sb0 = (raw + 1023u) & ~1023u;
    uint32_t pad = sb0 - raw;

    const int qt = blockIdx.x;
    const int bh = blockIdx.y;
    const int b = bh >> 4, h = bh & 15;

    const fp16* Q = qq + ((size_t)(b*TT) + qt*128)*DD + h*HD;
    const fp16* K = kk + (size_t)(b*TT)*DD + h*HD;
    const fp16* V = vt + (size_t)bh*HD*TT;

    const int lane = tid & 31, wid = tid >> 5;
    const int g8 = lane & 7, q2 = lane >> 3;
    const int gid = lane >> 2, tig = lane & 3;

    // Q: 2 panels of 16KB at sb0..32KB
    #pragma unroll
    for (int t = 0; t < 8; t++) {
        int i = tid + t*256;
        int pd = i >> 10, jj = i & 1023;
        int r = jj >> 3, ch = jj & 7;
        uint32_t off = (uint32_t)(r*128 + ch*16);
        uint32_t sw = off ^ ((off >> 3) & 0x70u);
        cpa16(sb0 + pd*16384 + sw, Q + (size_t)r*DD + pd*64 + ch*8);
    }
    CP_COMMIT();
    flash_ldkv(sb0 + 32768, 0,  K, V, tid);
    flash_ldkv(sb0 + 65536, 64, K, V, tid);

    float c_o[16][4];
    #pragma unroll
    for (int i = 0; i < 16; i++)
        #pragma unroll
        for (int e = 0; e < 4; e++) c_o[i][e] = 0.f;
    float m0 = -1e30f, m1 = -1e30f, l0 = 0.f, l1 = 0.f;

    for (int t = 0; t < 32; t++) {
        if (t < 31) asm volatile("cp.async.wait_group 1;" ::: "memory");
        else        asm volatile("cp.async.wait_group 0;" ::: "memory");
        __syncthreads();
        const uint32_t stg = sb0 + 32768 + (t & 1)*32768;

        // ---- S = Q @ K^T (128 x 64, single-pass) ----
        float c_s[8][4];
        #pragma unroll
        for (int i = 0; i < 8; i++)
            #pragma unroll
            for (int e = 0; e < 4; e++) c_s[i][e] = 0.f;

        #pragma unroll
        for (int k16 = 0; k16 < 8; k16++) {
            const int pd = k16 >> 2;
            uint32_t qa = sw_addr(sb0 + pd*16384, wid*16 + g8 + ((q2 & 1) << 3),
                                  (k16 & 3)*2 + (q2 >> 1));
            uint32_t qah[4];
            ldsm4(qah, qa);
            uint32_t kbh[8][2];
            #pragma unroll
            for (int nj = 0; nj < 4; nj++) {
                uint32_t ka = sw_addr(stg + pd*8192, nj*16 + g8 + ((q2 >> 1) << 3),
                                      (k16 & 3)*2 + (q2 & 1));
                uint32_t r4[4];
                ldsm4(r4, ka);
                kbh[2*nj][0] = r4[0]; kbh[2*nj][1] = r4[1];
                kbh[2*nj+1][0] = r4[2]; kbh[2*nj+1][1] = r4[3];
            }
            #pragma unroll
            for (int nj = 0; nj < 8; nj++)
                mma16816h(c_s[nj], qah, kbh[nj]);
        }

        // ---- online softmax ----
        float tm0 = -1e30f, tm1 = -1e30f;
        #pragma unroll
        for (int nj = 0; nj < 8; nj++) {
            tm0 = fmaxf(tm0, fmaxf(c_s[nj][0], c_s[nj][1]));
            tm1 = fmaxf(tm1, fmaxf(c_s[nj][2], c_s[nj][3]));
        }
        tm0 = fmaxf(tm0, __shfl_xor_sync(0xffffffffu, tm0, 1));
        tm0 = fmaxf(tm0, __shfl_xor_sync(0xffffffffu, tm0, 2));
        tm1 = fmaxf(tm1, __shfl_xor_sync(0xffffffffu, tm1, 1));
        tm1 = fmaxf(tm1, __shfl_xor_sync(0xffffffffu, tm1, 2));
        const float mn0 = fmaxf(m0, tm0), mn1 = fmaxf(m1, tm1);
        const float a0 = __expf(m0 - mn0), a1 = __expf(m1 - mn1);
        float rs0 = 0.f, rs1 = 0.f;
        #pragma unroll
        for (int nj = 0; nj < 8; nj++) {
            c_s[nj][0] = __expf(c_s[nj][0] - mn0);
            c_s[nj][1] = __expf(c_s[nj][1] - mn0);
            c_s[nj][2] = __expf(c_s[nj][2] - mn1);
            c_s[nj][3] = __expf(c_s[nj][3] - mn1);
            rs0 += c_s[nj][0] + c_s[nj][1];
            rs1 += c_s[nj][2] + c_s[nj][3];
        }
        rs0 += __shfl_xor_sync(0xffffffffu, rs0, 1);
        rs0 += __shfl_xor_sync(0xffffffffu, rs0, 2);
        rs1 += __shfl_xor_sync(0xffffffffu, rs1, 1);
        rs1 += __shfl_xor_sync(0xffffffffu, rs1, 2);
        l0 = l0*a0 + rs0;  l1 = l1*a1 + rs1;
        m0 = mn0;          m1 = mn1;
        #pragma unroll
        for (int nb = 0; nb < 16; nb++) {
            c_o[nb][0] *= a0; c_o[nb][1] *= a0;
            c_o[nb][2] *= a1; c_o[nb][3] *= a1;
        }

        // ---- O += P @ V  (P plain fp16 in registers, V plain) ----
        #pragma unroll
        for (int kb = 0; kb < 4; kb++) {
            uint32_t pah[4];
            pah[0] = pack_h(c_s[2*kb][0],   c_s[2*kb][1]);
            pah[1] = pack_h(c_s[2*kb][2],   c_s[2*kb][3]);
            pah[2] = pack_h(c_s[2*kb+1][0], c_s[2*kb+1][1]);
            pah[3] = pack_h(c_s[2*kb+1][2], c_s[2*kb+1][3]);
            #pragma unroll
            for (int nj2 = 0; nj2 < 8; nj2++) {
                uint32_t va = sw_addr(stg + 16384, nj2*16 + g8 + ((q2 >> 1) << 3),
                                      kb*2 + (q2 & 1));
                uint32_t vh4[4];
                ldsm4(vh4, va);
                uint32_t b0[2] = {vh4[0], vh4[1]}, b1[2] = {vh4[2], vh4[3]};
                mma16816h(c_o[2*nj2],   pah, b0);
                mma16816h(c_o[2*nj2+1], pah, b1);
            }
        }

        __syncthreads();
        if (t + 2 < 32)
            flash_ldkv(sb0 + 32768 + (t & 1)*32768, (t+2)*64, K, V, tid);
    }

    // ---- epilogue: O/l -> padded fp32 smem -> coalesced fp16 write ----
    float* smemf = (float*)(dyns + pad);   // reuse, [128][132] = 67.6KB < 97KB
    {
        const float r0i = 1.0f / l0, r1i = 1.0f / l1;
        const int row0 = wid*16 + gid, row1 = row0 + 8;
        #pragma unroll
        for (int nb = 0; nb < 16; nb++) {
            const int col = nb*8 + tig*2;
            smemf[row0*132 + col]     = c_o[nb][0]*r0i;
            smemf[row0*132 + col + 1] = c_o[nb][1]*r0i;
            smemf[row1*132 + col]     = c_o[nb][2]*r1i;
            smemf[row1*132 + col + 1] = c_o[nb][3]*r1i;
        }
    }
    __syncthreads();
    for (int v = tid; v < 4096; v += 256) {
        const int row = v >> 5, c4 = (v & 31) << 2;
        float4 val = *(const float4*)&smemf[row*132 + c4];
        const size_t go = ((size_t)(b*TT) + qt*128 + row)*DD + h*HD + c4;
        *(uint32_t*)&ah[go]   = pack_h(val.x, val.y);
        *(uint32_t*)&ah[go+2] = pack_h(val.z, val.w);
    }
}

// ---------------- elementwise convert: fp32 -> fp16 ------------------------
__global__ __launch_bounds__(256) void convert4h(const float* __restrict__ in,
    fp16* __restrict__ oh, int n4)
{
    int i = blockIdx.x*256 + threadIdx.x;
    if (i >= n4) return;
    float4 v = ((const float4*)in)[i];
    ((uint32_t*)oh)[i*2]   = pack_h(v.x, v.y);
    ((uint32_t*)oh)[i*2+1] = pack_h(v.z, v.w);
}

// ---------------- weight transpose -> plain fp16 ---------------------------
__global__ void transpose_h(const float* __restrict__ in, fp16* __restrict__ out, int n)
{
    __shared__ float t[32][33];
    const int r0 = blockIdx.y*32, c0 = blockIdx.x*32;
    const int tx = threadIdx.x, ty = threadIdx.y;
    #pragma unroll
    for (int i = 0; i < 32; i += 8)
        t[ty+i][tx] = in[(size_t)(r0+ty+i)*n + c0+tx];
    __syncthreads();
    #pragma unroll
    for (int i = 0; i < 32; i += 8)
        out[(size_t)(c0+ty+i)*n + r0 + tx] = __float2half_rn(t[tx][ty+i]);
}

// ---------------- V transpose -> plain fp16 [b,h,d,t] -----------------------
__global__ void transpose_v(const float* __restrict__ in, fp16* __restrict__ out)
{
    __shared__ float t[32][33];
    const int z = blockIdx.z, zb = z >> 4, zh = z & 15;
    const float* pin = in + (size_t)zb*TT*DD + (size_t)zh*HD;
    fp16* pout = out + (size_t)z*HD*TT;
    const int r0 = blockIdx.y*32, c0 = blockIdx.x*32;   // r = t, c = d
    const int tx = threadIdx.x, ty = threadIdx.y;
    #pragma unroll
    for (int i = 0; i < 32; i += 8)
        t[ty+i][tx] = pin[(size_t)(r0+ty+i)*DD + c0+tx];
    __syncthreads();
    #pragma unroll
    for (int i = 0; i < 32; i += 8)
        pout[(size_t)(c0+ty+i)*TT + r0 + tx] = __float2half_rn(t[tx][ty+i]);
}

// ---------------- fused rmsnorm + rope -> plain fp16 -----------------------
__global__ __launch_bounds__(256) void rmsnorm_rope_h(
    const float* __restrict__ in, const float* __restrict__ g,
    const float* __restrict__ cosp, const float* __restrict__ sinp,
    float scale, fp16* __restrict__ oh)
{
    __shared__ float s[DD];
    __shared__ float red[8];
    const int row = blockIdx.x;
    const int t = row & (TT - 1);
    const float* p = in + (size_t)row * DD;
    const int tid = threadIdx.x;

    float ss = 0.f;
    for (int c = tid; c < DD; c += 256) { float x = p[c]; s[c] = x; ss += x*x; }
    #pragma unroll
    for (int o = 16; o > 0; o >>= 1) ss += __shfl_xor_sync(0xffffffffu, ss, o);
    if ((tid & 31) == 0) red[tid >> 5] = ss;
    __syncthreads();
    float tot = red[0]+red[1]+red[2]+red[3]+red[4]+red[5]+red[6]+red[7];
    const float inv = rsqrtf(tot * (1.0f / (float)DD) + 1e-6f);

    for (int c = tid; c < DD; c += 256) {
        const int pidx = c & 127;
        const int base = c - pidx;
        float o;
        if (pidx < 64) {
            float x1 = s[c] * inv * g[c];
            float x2 = s[base + 64 + pidx] * inv * g[base + 64 + pidx];
            o = x1 * cosp[t*64 + pidx] - sinp[t*64 + pidx] * x2;
        } else {
            const int pp = pidx - 64;
            float x2 = s[c] * inv * g[c];
            float x1 = s[base + pp] * inv * g[base + pp];
            o = x2 * cosp[t*64 + pp] + sinp[t*64 + pp] * x1;
        }
        o *= scale;
        oh[(size_t)row*DD + c] = __float2half_rn(o);
    }
}

// ---------------------------------------------------------------------------
extern "C" void kernel_launch(void* const* d_in, const int* in_sizes, int n_in,
                              void* d_out, int out_size)
{
    const float* x    = (const float*)d_in[0];
    const float* cosp = (const float*)d_in[1];
    const float* sinp = (const float*)d_in[2];
    const float* w[5] = { (const float*)d_in[3], (const float*)d_in[5],
                          (const float*)d_in[7], (const float*)d_in[11],
                          (const float*)d_in[13] };
    const float* bq = (const float*)d_in[4];
    const float* bk = (const float*)d_in[6];
    const float* bv = (const float*)d_in[8];
    const float* gq = (const float*)d_in[9];
    const float* gk = (const float*)d_in[10];
    const float* bo = (const float*)d_in[12];
    const float* bg = (const float*)d_in[14];
    float* out = (float*)d_out;

    fp16 *xh, *wt, *qh, *kh, *vt, *ah, *oh;
    float *tmp, *of;
    cudaGetSymbolAddress((void**)&xh, g_xh);
    cudaGetSymbolAddress((void**)&wt, g_wt);
    cudaGetSymbolAddress((void**)&tmp, g_tmp);
    cudaGetSymbolAddress((void**)&qh, g_qh);
    cudaGetSymbolAddress((void**)&kh, g_kh);
    cudaGetSymbolAddress((void**)&vt, g_vt);
    cudaGetSymbolAddress((void**)&ah, g_ah);
    cudaGetSymbolAddress((void**)&of, g_of);
    cudaGetSymbolAddress((void**)&oh, g_oh);

    // gemm: dynamic smem = max(2 x 32KB stages, epilogue 128x132 fp32) + pad
    const int SMEMSZ  = 128*132*4 + 1024;         // 68608 -> 2 CTAs/SM
    const int SMEMF   = 32768 + 2*32768 + 1024;   // flash: Q 32KB + 2 x 32KB stages
    cudaFuncSetAttribute(gemm_h2, cudaFuncAttributeMaxDynamicSharedMemorySize, SMEMSZ);
    cudaFuncSetAttribute(flash_attn, cudaFuncAttributeMaxDynamicSharedMemorySize, SMEMF);

    dim3 blk(256), tb(32, 8);
    const long DDl = DD;

    // input + weight prep
    convert4h<<<(MROWS*DD/4 + 255)/256, blk>>>(x, xh, MROWS*DD/4);
    for (int i = 0; i < 5; i++)
        transpose_h<<<dim3(64,64,1), tb>>>(w[i], wt + (size_t)i*DD*DD, DD);

    dim3 gproj(DD/128, MROWS/128, 1);   // (16, 32) = 512 CTAs

    // Q  (single-pass; Q output plain fp16)
    gemm_h2<<<gproj, blk, SMEMSZ>>>(xh, DDl, wt, DDl,
        bq, nullptr, tmp, nullptr, DDl, DD, 0);
    rmsnorm_rope_h<<<MROWS, blk>>>(tmp, gq, cosp, sinp, 0.08838834764831845f, qh);
    // K  (single-pass; K output plain fp16)
    gemm_h2<<<gproj, blk, SMEMSZ>>>(xh, DDl, wt + (size_t)DD*DD, DDl,
        bk, nullptr, tmp, nullptr, DDl, DD, 0);
    rmsnorm_rope_h<<<MROWS, blk>>>(tmp, gk, cosp, sinp, 1.0f, kh);
    // V  (single-pass; + transpose to [b,h,d,t] plain fp16)
    gemm_h2<<<gproj, blk, SMEMSZ>>>(xh, DDl, wt + 2ULL*DD*DD, DDl,
        bv, nullptr, tmp, nullptr, DDl, DD, 0);
    transpose_v<<<dim3(4,64,NB), tb>>>(tmp, vt);

    // fused attention (scale folded into q) -> plain fp16 attn
    flash_attn<<<dim3(16, 32), blk, SMEMF>>>(qh, kh, vt, ah);

    // out proj — single-pass fp16 A (attn), fp32 + fp16-hi epilogue
    gemm_h2<<<gproj, blk, SMEMSZ>>>(ah, DDl, wt + 3ULL*DD*DD, DDl,
        bo, nullptr, of, oh, DDl, DD, 2);
    // gate — single-pass fp16 A (oh): out = of * sigmoid(oh @ wg + bg)
    gemm_h2<<<gproj, blk, SMEMSZ>>>(oh, DDl, wt + 4ULL*DD*DD, DDl,
        bg, of, out, nullptr, DDl, DD, 3);
}

// round 15
// speedup vs baseline: 8.1865x; 1.0210x over previous
#include <cuda_runtime.h>
#include <cuda_bf16.h>
#include <cuda_fp16.h>
#include <cstdint>
#include <math.h>

#define BB 2
#define TT 2048
#define DD 2048
#define HH 16
#define HD 128
#define MROWS (BB*TT)     // 4096
#define NB (BB*HH)        // 32

typedef __half fp16;

// ---------------- scratch (device globals; allocation-free rule) ----------
__device__ fp16  g_xh[(size_t)MROWS*DD];                         // x plain fp16
__device__ fp16  g_wt[5ULL*DD*DD];                               // transposed fp16 weights
__device__ float g_tmpq[(size_t)MROWS*DD];                       // fp32 q proj
__device__ float g_tmpk[(size_t)MROWS*DD];                       // fp32 k proj
__device__ float g_tmpv[(size_t)MROWS*DD];                       // fp32 v proj
__device__ fp16  g_qh[(size_t)MROWS*DD];                         // Q plain fp16
__device__ fp16  g_kh[(size_t)MROWS*DD];                         // K plain fp16
__device__ fp16  g_vt[(size_t)NB*HD*TT];                         // v^T [b,h,d,t] plain fp16
__device__ fp16  g_ah[(size_t)MROWS*DD];                         // attn plain fp16
__device__ float g_of[(size_t)MROWS*DD];
__device__ fp16  g_oh[(size_t)MROWS*DD];

// ---------------- PTX helpers (plain sm_80+ PTX only) ---------------------
__device__ __forceinline__ uint32_t smem_u32(const void* p) {
    uint32_t a;
    asm("{ .reg .u64 t; cvta.to.shared.u64 t, %1; cvt.u32.u64 %0, t; }" : "=r"(a) : "l"(p));
    return a;
}
__device__ __forceinline__ void cpa16(uint32_t s, const void* g) {
    asm volatile("cp.async.cg.shared.global [%0], [%1], 16;" :: "r"(s), "l"(g));
}
#define CP_COMMIT()  asm volatile("cp.async.commit_group;" ::: "memory")

__device__ __forceinline__ void ldsm4(uint32_t* r, uint32_t a) {
    asm volatile("ldmatrix.sync.aligned.m8n8.x4.shared.b16 {%0,%1,%2,%3}, [%4];"
        : "=r"(r[0]), "=r"(r[1]), "=r"(r[2]), "=r"(r[3]) : "r"(a));
}
__device__ __forceinline__ void mma16816h(float* c, const uint32_t* a, const uint32_t* b) {
    asm volatile("mma.sync.aligned.m16n8k16.row.col.f32.f16.f16.f32 "
        "{%0,%1,%2,%3}, {%4,%5,%6,%7}, {%8,%9}, {%0,%1,%2,%3};"
        : "+f"(c[0]), "+f"(c[1]), "+f"(c[2]), "+f"(c[3])
        : "r"(a[0]), "r"(a[1]), "r"(a[2]), "r"(a[3]), "r"(b[0]), "r"(b[1]));
}
__device__ __forceinline__ uint32_t sw_addr(uint32_t base, int row, int ch) {
    uint32_t off = (uint32_t)(row*128 + ch*16);
    return base + (off ^ ((off >> 3) & 0x70u));
}
__device__ __forceinline__ uint32_t pack_h(float a, float b) {
    __half2 H(__float2half_rn(a), __float2half_rn(b));
    return *(uint32_t*)&H;
}

// ============ 128x128x64 GEMM core pieces (fp16, 2 CTAs/SM) =================
#define STG_SZ 32768

__device__ __forceinline__ void ld_stage128(uint32_t sb,
    const fp16* A, long lda, const fp16* B, long ldb,
    int m0, int n0, int k0, int tid)
{
    #pragma unroll
    for (int t = 0; t < 8; t++) {
        int i = tid + t*256;
        if (i < 1024) {                       // A: 128 rows x 128B
            int r = i >> 3, ch = i & 7;
            uint32_t off = (uint32_t)(r*128 + ch*16);
            uint32_t sw = off ^ ((off >> 3) & 0x70u);
            cpa16(sb + sw, A + (size_t)(m0 + r)*lda + k0 + ch*8);
        } else {                              // B: 128 rows x 128B
            int j = i - 1024;
            int r = j >> 3, ch = j & 7;
            uint32_t off = (uint32_t)(r*128 + ch*16);
            uint32_t sw = off ^ ((off >> 3) & 0x70u);
            cpa16(sb + 16384 + sw, B + (size_t)(n0 + r)*ldb + k0 + ch*8);
        }
    }
    CP_COMMIT();
}

// mainloop: accumulate C(128x128) over K, from A(m0,:) x B(n0,:)^T
__device__ __forceinline__ void gemm_mainloop(uint32_t sb0,
    const fp16* A, long lda, const fp16* B, long ldb,
    int m0, int n0, int K, int tid, float c[2][8][4])
{
    const int lane = tid & 31, wid = tid >> 5;
    const int wm = wid >> 1, wn = wid & 1;
    const int g8 = lane & 7, q = lane >> 3;

    const int nch = K >> 6;
    ld_stage128(sb0, A, lda, B, ldb, m0, n0, 0, tid);

    for (int cc = 0; cc < nch; cc++) {
        const int s = cc & 1;
        const uint32_t sbs = sb0 + s*STG_SZ;
        if (cc + 1 < nch) {
            ld_stage128(sb0 + (s^1)*STG_SZ, A, lda, B, ldb, m0, n0, (cc+1)*64, tid);
            asm volatile("cp.async.wait_group 1;" ::: "memory");
        } else {
            asm volatile("cp.async.wait_group 0;" ::: "memory");
        }
        __syncthreads();

        #pragma unroll
        for (int k16 = 0; k16 < 4; k16++) {
            uint32_t bh[8][2];
            #pragma unroll
            for (int nj = 0; nj < 4; nj++) {
                int row = wn*64 + nj*16 + g8 + ((q >> 1) << 3);
                int ch  = k16*2 + (q & 1);
                uint32_t r4[4];
                ldsm4(r4, sw_addr(sbs + 16384, row, ch));
                bh[2*nj][0] = r4[0]; bh[2*nj][1] = r4[1];
                bh[2*nj+1][0] = r4[2]; bh[2*nj+1][1] = r4[3];
            }
            #pragma unroll
            for (int mi = 0; mi < 2; mi++) {
                int row = wm*32 + mi*16 + g8 + ((q & 1) << 3);
                int ch  = k16*2 + (q >> 1);
                uint32_t ah4[4];
                ldsm4(ah4, sw_addr(sbs, row, ch));
                #pragma unroll
                for (int ni = 0; ni < 8; ni++)
                    mma16816h(c[mi][ni], ah4, bh[ni]);
            }
        }
        __syncthreads();
    }
}

// epilogue stage 1: frags -> padded fp32 smem [128][132]
__device__ __forceinline__ void epi_to_smem(float* smemf, int tid, float c[2][8][4])
{
    const int lane = tid & 31, wid = tid >> 5;
    const int wm = wid >> 1, wn = wid & 1;
    const int gid = lane >> 2, tig = lane & 3;
    #pragma unroll
    for (int mi = 0; mi < 2; mi++)
        #pragma unroll
        for (int ni = 0; ni < 8; ni++) {
            int r0 = wm*32 + mi*16 + gid;
            int col = wn*64 + ni*8 + tig*2;
            *(float2*)&smemf[r0*132 + col]     = make_float2(c[mi][ni][0], c[mi][ni][1]);
            *(float2*)&smemf[(r0+8)*132 + col] = make_float2(c[mi][ni][2], c[mi][ni][3]);
        }
}

// ---------------- fused QKV projection GEMM --------------------------------
// grid (48, 32): blockIdx.x -> wsel = x>>4 (0=Q,1=K,2=V), n0 = (x&15)*128
__global__ __launch_bounds__(256, 2) void gemm_qkv(
    const fp16* __restrict__ A, const fp16* __restrict__ wt,
    const float* __restrict__ bq, const float* __restrict__ bk, const float* __restrict__ bv,
    float* __restrict__ cq, float* __restrict__ ck, float* __restrict__ cv)
{
    extern __shared__ __align__(16) uint8_t dyns[];
    const int tid = threadIdx.x;
    uint32_t raw = smem_u32(dyns);
    uint32_t sb0 = (raw + 1023u) & ~1023u;
    uint32_t pad = sb0 - raw;

    const int wsel = blockIdx.x >> 4;
    const int n0 = (blockIdx.x & 15) * 128;
    const int m0 = blockIdx.y * 128;
    const fp16* B = wt + (size_t)wsel*DD*DD;
    const float* bias = (wsel == 0) ? bq : (wsel == 1) ? bk : bv;
    float* Cf = (wsel == 0) ? cq : (wsel == 1) ? ck : cv;

    float c[2][8][4];
    #pragma unroll
    for (int i = 0; i < 2; i++)
        #pragma unroll
        for (int j = 0; j < 8; j++)
            #pragma unroll
            for (int e = 0; e < 4; e++) c[i][j][e] = 0.f;

    gemm_mainloop(sb0, A, DD, B, DD, m0, n0, DD, tid, c);

    float* smemf = (float*)(dyns + pad);
    epi_to_smem(smemf, tid, c);
    __syncthreads();

    for (int v = tid; v < 4096; v += 256) {
        const int row = v >> 5, c4 = (v & 31) << 2;
        float4 val = *(const float4*)&smemf[row*132 + c4];
        const int gc = n0 + c4;
        val.x += bias[gc]; val.y += bias[gc+1]; val.z += bias[gc+2]; val.w += bias[gc+3];
        *(float4*)&Cf[(size_t)(m0 + row)*DD + gc] = val;
    }
}

// ---------------- generic GEMM (out-proj / gate) ---------------------------
// epi: 2 = fp32 + fp16 hi, 3 = gate
__global__ __launch_bounds__(256, 2) void gemm_h2(
    const fp16* __restrict__ A, const fp16* __restrict__ B,
    const float* __restrict__ bias, const float* __restrict__ mul,
    float* __restrict__ Cf, fp16* __restrict__ Ch, int epi)
{
    extern __shared__ __align__(16) uint8_t dyns[];
    const int tid = threadIdx.x;
    uint32_t raw = smem_u32(dyns);
    uint32_t sb0 = (raw + 1023u) & ~1023u;
    uint32_t pad = sb0 - raw;

    const int m0 = blockIdx.y * 128, n0 = blockIdx.x * 128;

    float c[2][8][4];
    #pragma unroll
    for (int i = 0; i < 2; i++)
        #pragma unroll
        for (int j = 0; j < 8; j++)
            #pragma unroll
            for (int e = 0; e < 4; e++) c[i][j][e] = 0.f;

    gemm_mainloop(sb0, A, DD, B, DD, m0, n0, DD, tid, c);

    float* smemf = (float*)(dyns + pad);
    epi_to_smem(smemf, tid, c);
    __syncthreads();

    for (int v = tid; v < 4096; v += 256) {
        const int row = v >> 5, c4 = (v & 31) << 2;
        float4 val = *(const float4*)&smemf[row*132 + c4];
        const int gc = n0 + c4;
        const size_t go = (size_t)(m0 + row)*DD + gc;
        val.x += bias[gc]; val.y += bias[gc+1]; val.z += bias[gc+2]; val.w += bias[gc+3];
        if (epi == 2) {
            *(float4*)&Cf[go] = val;
            *(uint32_t*)&Ch[go]   = pack_h(val.x, val.y);
            *(uint32_t*)&Ch[go+2] = pack_h(val.z, val.w);
        } else {  // gate
            const float4 m = *(const float4*)&mul[go];
            float4 o;
            o.x = m.x / (1.0f + __expf(-val.x));
            o.y = m.y / (1.0f + __expf(-val.y));
            o.z = m.z / (1.0f + __expf(-val.z));
            o.w = m.w / (1.0f + __expf(-val.w));
            *(float4*)&Cf[go] = o;
        }
    }
}

// ---------------- flash attention KV stage loader (plain fp16) -------------
__device__ __forceinline__ void flash_ldkv(uint32_t stg, int kc0,
    const fp16* K, const fp16* V, int tid)
{
    #pragma unroll
    for (int t = 0; t < 8; t++) {
        int i = tid + t*256;
        if (i < 1024) {
            int p = i >> 9, j = i & 511;
            int r = j >> 3, ch = j & 7;
            uint32_t off = (uint32_t)(r*128 + ch*16);
            uint32_t sw = off ^ ((off >> 3) & 0x70u);
            const fp16* src = K + (size_t)(kc0 + r)*DD + p*64 + ch*8;
            cpa16(stg + p*8192 + sw, src);
        } else {
            int j = i - 1024;
            int r = j >> 3, ch = j & 7;
            uint32_t off = (uint32_t)(r*128 + ch*16);
            uint32_t sw = off ^ ((off >> 3) & 0x70u);
            const fp16* src = V + (size_t)r*TT + kc0 + ch*8;
            cpa16(stg + 16384 + sw, src);
        }
    }
    CP_COMMIT();
}

// ---------------- fused flash attention (fp16 single-pass) -----------------
__global__ __launch_bounds__(256, 1) void flash_attn(
    const fp16* __restrict__ qq, const fp16* __restrict__ kk,
    const fp16* __restrict__ vt, fp16* __restrict__ ah)
{
    extern __shared__ __align__(16) uint8_t dyns[];
    const int tid = threadIdx.x;
    uint32_t raw = smem_u32(dyns);
    uint32_t sb0 = (raw + 1023u) & ~1023u;
    uint32_t pad = sb0 - raw;

    const int qt = blockIdx.x;
    const int bh = blockIdx.y;
    const int b = bh >> 4, h = bh & 15;

    const fp16* Q = qq + ((size_t)(b*TT) + qt*128)*DD + h*HD;
    const fp16* K = kk + (size_t)(b*TT)*DD + h*HD;
    const fp16* V = vt + (size_t)bh*HD*TT;

    const int lane = tid & 31, wid = tid >> 5;
    const int g8 = lane & 7, q2 = lane >> 3;
    const int gid = lane >> 2, tig = lane & 3;

    #pragma unroll
    for (int t = 0; t < 8; t++) {
        int i = tid + t*256;
        int pd = i >> 10, jj = i & 1023;
        int r = jj >> 3, ch = jj & 7;
        uint32_t off = (uint32_t)(r*128 + ch*16);
        uint32_t sw = off ^ ((off >> 3) & 0x70u);
        cpa16(sb0 + pd*16384 + sw, Q + (size_t)r*DD + pd*64 + ch*8);
    }
    CP_COMMIT();
    flash_ldkv(sb0 + 32768, 0,  K, V, tid);
    flash_ldkv(sb0 + 65536, 64, K, V, tid);

    float c_o[16][4];
    #pragma unroll
    for (int i = 0; i < 16; i++)
        #pragma unroll
        for (int e = 0; e < 4; e++) c_o[i][e] = 0.f;
    float m0 = -1e30f, m1 = -1e30f, l0 = 0.f, l1 = 0.f;

    for (int t = 0; t < 32; t++) {
        if (t < 31) asm volatile("cp.async.wait_group 1;" ::: "memory");
        else        asm volatile("cp.async.wait_group 0;" ::: "memory");
        __syncthreads();
        const uint32_t stg = sb0 + 32768 + (t & 1)*32768;

        float c_s[8][4];
        #pragma unroll
        for (int i = 0; i < 8; i++)
            #pragma unroll
            for (int e = 0; e < 4; e++) c_s[i][e] = 0.f;

        #pragma unroll
        for (int k16 = 0; k16 < 8; k16++) {
            const int pd = k16 >> 2;
            uint32_t qa = sw_addr(sb0 + pd*16384, wid*16 + g8 + ((q2 & 1) << 3),
                                  (k16 & 3)*2 + (q2 >> 1));
            uint32_t qah[4];
            ldsm4(qah, qa);
            uint32_t kbh[8][2];
            #pragma unroll
            for (int nj = 0; nj < 4; nj++) {
                uint32_t ka = sw_addr(stg + pd*8192, nj*16 + g8 + ((q2 >> 1) << 3),
                                      (k16 & 3)*2 + (q2 & 1));
                uint32_t r4[4];
                ldsm4(r4, ka);
                kbh[2*nj][0] = r4[0]; kbh[2*nj][1] = r4[1];
                kbh[2*nj+1][0] = r4[2]; kbh[2*nj+1][1] = r4[3];
            }
            #pragma unroll
            for (int nj = 0; nj < 8; nj++)
                mma16816h(c_s[nj], qah, kbh[nj]);
        }

        float tm0 = -1e30f, tm1 = -1e30f;
        #pragma unroll
        for (int nj = 0; nj < 8; nj++) {
            tm0 = fmaxf(tm0, fmaxf(c_s[nj][0], c_s[nj][1]));
            tm1 = fmaxf(tm1, fmaxf(c_s[nj][2], c_s[nj][3]));
        }
        tm0 = fmaxf(tm0, __shfl_xor_sync(0xffffffffu, tm0, 1));
        tm0 = fmaxf(tm0, __shfl_xor_sync(0xffffffffu, tm0, 2));
        tm1 = fmaxf(tm1, __shfl_xor_sync(0xffffffffu, tm1, 1));
        tm1 = fmaxf(tm1, __shfl_xor_sync(0xffffffffu, tm1, 2));
        const float mn0 = fmaxf(m0, tm0), mn1 = fmaxf(m1, tm1);
        const float a0 = __expf(m0 - mn0), a1 = __expf(m1 - mn1);
        float rs0 = 0.f, rs1 = 0.f;
        #pragma unroll
        for (int nj = 0; nj < 8; nj++) {
            c_s[nj][0] = __expf(c_s[nj][0] - mn0);
            c_s[nj][1] = __expf(c_s[nj][1] - mn0);
            c_s[nj][2] = __expf(c_s[nj][2] - mn1);
            c_s[nj][3] = __expf(c_s[nj][3] - mn1);
            rs0 += c_s[nj][0] + c_s[nj][1];
            rs1 += c_s[nj][2] + c_s[nj][3];
        }
        rs0 += __shfl_xor_sync(0xffffffffu, rs0, 1);
        rs0 += __shfl_xor_sync(0xffffffffu, rs0, 2);
        rs1 += __shfl_xor_sync(0xffffffffu, rs1, 1);
        rs1 += __shfl_xor_sync(0xffffffffu, rs1, 2);
        l0 = l0*a0 + rs0;  l1 = l1*a1 + rs1;
        m0 = mn0;          m1 = mn1;
        #pragma unroll
        for (int nb = 0; nb < 16; nb++) {
            c_o[nb][0] *= a0; c_o[nb][1] *= a0;
            c_o[nb][2] *= a1; c_o[nb][3] *= a1;
        }

        #pragma unroll
        for (int kb = 0; kb < 4; kb++) {
            uint32_t pah[4];
            pah[0] = pack_h(c_s[2*kb][0],   c_s[2*kb][1]);
            pah[1] = pack_h(c_s[2*kb][2],   c_s[2*kb][3]);
            pah[2] = pack_h(c_s[2*kb+1][0], c_s[2*kb+1][1]);
            pah[3] = pack_h(c_s[2*kb+1][2], c_s[2*kb+1][3]);
            #pragma unroll
            for (int nj2 = 0; nj2 < 8; nj2++) {
                uint32_t va = sw_addr(stg + 16384, nj2*16 + g8 + ((q2 >> 1) << 3),
                                      kb*2 + (q2 & 1));
                uint32_t vh4[4];
                ldsm4(vh4, va);
                uint32_t b0[2] = {vh4[0], vh4[1]}, b1[2] = {vh4[2], vh4[3]};
                mma16816h(c_o[2*nj2],   pah, b0);
                mma16816h(c_o[2*nj2+1], pah, b1);
            }
        }

        __syncthreads();
        if (t + 2 < 32)
            flash_ldkv(sb0 + 32768 + (t & 1)*32768, (t+2)*64, K, V, tid);
    }

    float* smemf = (float*)(dyns + pad);
    {
        const float r0i = 1.0f / l0, r1i = 1.0f / l1;
        const int row0 = wid*16 + gid, row1 = row0 + 8;
        #pragma unroll
        for (int nb = 0; nb < 16; nb++) {
            const int col = nb*8 + tig*2;
            smemf[row0*132 + col]     = c_o[nb][0]*r0i;
            smemf[row0*132 + col + 1] = c_o[nb][1]*r0i;
            smemf[row1*132 + col]     = c_o[nb][2]*r1i;
            smemf[row1*132 + col + 1] = c_o[nb][3]*r1i;
        }
    }
    __syncthreads();
    for (int v = tid; v < 4096; v += 256) {
        const int row = v >> 5, c4 = (v & 31) << 2;
        float4 val = *(const float4*)&smemf[row*132 + c4];
        const size_t go = ((size_t)(b*TT) + qt*128 + row)*DD + h*HD + c4;
        *(uint32_t*)&ah[go]   = pack_h(val.x, val.y);
        *(uint32_t*)&ah[go+2] = pack_h(val.z, val.w);
    }
}

// ---------------- elementwise convert: fp32 -> fp16 ------------------------
__global__ __launch_bounds__(256) void convert4h(const float* __restrict__ in,
    fp16* __restrict__ oh, int n4)
{
    int i = blockIdx.x*256 + threadIdx.x;
    if (i >= n4) return;
    float4 v = ((const float4*)in)[i];
    ((uint32_t*)oh)[i*2]   = pack_h(v.x, v.y);
    ((uint32_t*)oh)[i*2+1] = pack_h(v.z, v.w);
}

// ---------------- 5 weight transposes in one launch (z = widx) -------------
__global__ void transpose_h5(
    const float* __restrict__ w0, const float* __restrict__ w1,
    const float* __restrict__ w2, const float* __restrict__ w3,
    const float* __restrict__ w4, fp16* __restrict__ out)
{
    __shared__ float t[32][33];
    const int z = blockIdx.z;
    const float* in = (z == 0) ? w0 : (z == 1) ? w1 : (z == 2) ? w2 : (z == 3) ? w3 : w4;
    fp16* po = out + (size_t)z*DD*DD;
    const int r0 = blockIdx.y*32, c0 = blockIdx.x*32;
    const int tx = threadIdx.x, ty = threadIdx.y;
    #pragma unroll
    for (int i = 0; i < 32; i += 8)
        t[ty+i][tx] = in[(size_t)(r0+ty+i)*DD + c0+tx];
    __syncthreads();
    #pragma unroll
    for (int i = 0; i < 32; i += 8)
        po[(size_t)(c0+ty+i)*DD + r0 + tx] = __float2half_rn(t[tx][ty+i]);
}

// ---------------- V transpose -> plain fp16 [b,h,d,t] -----------------------
__global__ void transpose_v(const float* __restrict__ in, fp16* __restrict__ out)
{
    __shared__ float t[32][33];
    const int z = blockIdx.z, zb = z >> 4, zh = z & 15;
    const float* pin = in + (size_t)zb*TT*DD + (size_t)zh*HD;
    fp16* pout = out + (size_t)z*HD*TT;
    const int r0 = blockIdx.y*32, c0 = blockIdx.x*32;
    const int tx = threadIdx.x, ty = threadIdx.y;
    #pragma unroll
    for (int i = 0; i < 32; i += 8)
        t[ty+i][tx] = pin[(size_t)(r0+ty+i)*DD + c0+tx];
    __syncthreads();
    #pragma unroll
    for (int i = 0; i < 32; i += 8)
        pout[(size_t)(c0+ty+i)*TT + r0 + tx] = __float2half_rn(t[tx][ty+i]);
}

// ---------------- fused rmsnorm + rope for Q and K in one launch ------------
__global__ __launch_bounds__(256) void rmsnorm_rope_qk(
    const float* __restrict__ inq, const float* __restrict__ ink,
    const float* __restrict__ gq, const float* __restrict__ gk,
    const float* __restrict__ cosp, const float* __restrict__ sinp,
    fp16* __restrict__ oq, fp16* __restrict__ ok)
{
    __shared__ float s[DD];
    __shared__ float red[8];
    const int isK = blockIdx.x >= MROWS;
    const int row = blockIdx.x - (isK ? MROWS : 0);
    const int t = row & (TT - 1);
    const float* p = (isK ? ink : inq) + (size_t)row * DD;
    const float* g = isK ? gk : gq;
    fp16* oh = (isK ? ok : oq) + (size_t)row * DD;
    const float scale = isK ? 1.0f : 0.08838834764831845f;
    const int tid = threadIdx.x;

    float ss = 0.f;
    for (int c = tid; c < DD; c += 256) { float x = p[c]; s[c] = x; ss += x*x; }
    #pragma unroll
    for (int o = 16; o > 0; o >>= 1) ss += __shfl_xor_sync(0xffffffffu, ss, o);
    if ((tid & 31) == 0) red[tid >> 5] = ss;
    __syncthreads();
    float tot = red[0]+red[1]+red[2]+red[3]+red[4]+red[5]+red[6]+red[7];
    const float inv = rsqrtf(tot * (1.0f / (float)DD) + 1e-6f);

    for (int c = tid; c < DD; c += 256) {
        const int pidx = c & 127;
        const int base = c - pidx;
        float o;
        if (pidx < 64) {
            float x1 = s[c] * inv * g[c];
            float x2 = s[base + 64 + pidx] * inv * g[base + 64 + pidx];
            o = x1 * cosp[t*64 + pidx] - sinp[t*64 + pidx] * x2;
        } else {
            const int pp = pidx - 64;
            float x2 = s[c] * inv * g[c];
            float x1 = s[base + pp] * inv * g[base + pp];
            o = x2 * cosp[t*64 + pp] + sinp[t*64 + pp] * x1;
        }
        o *= scale;
        oh[c] = __float2half_rn(o);
    }
}

// ---------------------------------------------------------------------------
extern "C" void kernel_launch(void* const* d_in, const int* in_sizes, int n_in,
                              void* d_out, int out_size)
{
    const float* x    = (const float*)d_in[0];
    const float* cosp = (const float*)d_in[1];
    const float* sinp = (const float*)d_in[2];
    const float* w0 = (const float*)d_in[3];
    const float* bq = (const float*)d_in[4];
    const float* w1 = (const float*)d_in[5];
    const float* bk = (const float*)d_in[6];
    const float* w2 = (const float*)d_in[7];
    const float* bv = (const float*)d_in[8];
    const float* gq = (const float*)d_in[9];
    const float* gk = (const float*)d_in[10];
    const float* w3 = (const float*)d_in[11];
    const float* bo = (const float*)d_in[12];
    const float* w4 = (const float*)d_in[13];
    const float* bg = (const float*)d_in[14];
    float* out = (float*)d_out;

    fp16 *xh, *wt, *qh, *kh, *vt, *ah, *oh;
    float *tmpq, *tmpk, *tmpv, *of;
    cudaGetSymbolAddress((void**)&xh, g_xh);
    cudaGetSymbolAddress((void**)&wt, g_wt);
    cudaGetSymbolAddress((void**)&tmpq, g_tmpq);
    cudaGetSymbolAddress((void**)&tmpk, g_tmpk);
    cudaGetSymbolAddress((void**)&tmpv, g_tmpv);
    cudaGetSymbolAddress((void**)&qh, g_qh);
    cudaGetSymbolAddress((void**)&kh, g_kh);
    cudaGetSymbolAddress((void**)&vt, g_vt);
    cudaGetSymbolAddress((void**)&ah, g_ah);
    cudaGetSymbolAddress((void**)&of, g_of);
    cudaGetSymbolAddress((void**)&oh, g_oh);

    const int SMEMSZ  = 128*132*4 + 1024;         // 68608 -> 2 CTAs/SM
    const int SMEMF   = 32768 + 2*32768 + 1024;
    cudaFuncSetAttribute(gemm_qkv, cudaFuncAttributeMaxDynamicSharedMemorySize, SMEMSZ);
    cudaFuncSetAttribute(gemm_h2, cudaFuncAttributeMaxDynamicSharedMemorySize, SMEMSZ);
    cudaFuncSetAttribute(flash_attn, cudaFuncAttributeMaxDynamicSharedMemorySize, SMEMF);

    dim3 blk(256), tb(32, 8);

    // input + weight prep
    convert4h<<<(MROWS*DD/4 + 255)/256, blk>>>(x, xh, MROWS*DD/4);
    transpose_h5<<<dim3(64,64,5), tb>>>(w0, w1, w2, w3, w4, wt);

    // fused QKV projection: one launch, 1536 CTAs
    gemm_qkv<<<dim3(48, MROWS/128), blk, SMEMSZ>>>(xh, wt, bq, bk, bv, tmpq, tmpk, tmpv);

    // rmsnorm+rope for Q and K in one launch; V transpose
    rmsnorm_rope_qk<<<2*MROWS, blk>>>(tmpq, tmpk, gq, gk, cosp, sinp, qh, kh);
    transpose_v<<<dim3(4,64,NB), tb>>>(tmpv, vt);

    // fused attention (scale folded into q) -> plain fp16 attn
    flash_attn<<<dim3(16, 32), blk, SMEMF>>>(qh, kh, vt, ah);

    // out proj — fp32 + fp16-hi epilogue
    gemm_h2<<<dim3(16, MROWS/128), blk, SMEMSZ>>>(ah, wt + 3ULL*DD*DD,
        bo, nullptr, of, oh, 2);
    // gate: out = of * sigmoid(oh @ wg + bg)
    gemm_h2<<<dim3(16, MROWS/128), blk, SMEMSZ>>>(oh, wt + 4ULL*DD*DD,
        bg, of, out, nullptr, 3);
}

// round 16
// speedup vs baseline: 8.6606x; 1.0579x over previous
#include <cuda_runtime.h>
#include <cuda_bf16.h>
#include <cuda_fp16.h>
#include <cstdint>
#include <math.h>

#define BB 2
#define TT 2048
#define DD 2048
#define HH 16
#define HD 128
#define MROWS (BB*TT)     // 4096
#define NB (BB*HH)        // 32

typedef __half fp16;

// ---------------- scratch (device globals; allocation-free rule) ----------
__device__ fp16  g_xh[(size_t)MROWS*DD];                         // x plain fp16
__device__ fp16  g_wt[5ULL*DD*DD];                               // transposed fp16 weights
__device__ fp16  g_tq[(size_t)MROWS*DD];                         // q proj (fp16, pre-norm)
__device__ fp16  g_tk[(size_t)MROWS*DD];                         // k proj (fp16, pre-norm)
__device__ fp16  g_qh[(size_t)MROWS*DD];                         // Q plain fp16
__device__ fp16  g_kh[(size_t)MROWS*DD];                         // K plain fp16
__device__ fp16  g_vt[(size_t)NB*HD*TT];                         // v^T [b,h,d,t] fp16
__device__ fp16  g_ah[(size_t)MROWS*DD];                         // attn plain fp16
__device__ float g_of[(size_t)MROWS*DD];
__device__ fp16  g_oh[(size_t)MROWS*DD];

// ---------------- PTX helpers (plain sm_80+ PTX only) ---------------------
__device__ __forceinline__ uint32_t smem_u32(const void* p) {
    uint32_t a;
    asm("{ .reg .u64 t; cvta.to.shared.u64 t, %1; cvt.u32.u64 %0, t; }" : "=r"(a) : "l"(p));
    return a;
}
__device__ __forceinline__ void cpa16(uint32_t s, const void* g) {
    asm volatile("cp.async.cg.shared.global [%0], [%1], 16;" :: "r"(s), "l"(g));
}
#define CP_COMMIT()  asm volatile("cp.async.commit_group;" ::: "memory")

__device__ __forceinline__ void ldsm4(uint32_t* r, uint32_t a) {
    asm volatile("ldmatrix.sync.aligned.m8n8.x4.shared.b16 {%0,%1,%2,%3}, [%4];"
        : "=r"(r[0]), "=r"(r[1]), "=r"(r[2]), "=r"(r[3]) : "r"(a));
}
__device__ __forceinline__ void mma16816h(float* c, const uint32_t* a, const uint32_t* b) {
    asm volatile("mma.sync.aligned.m16n8k16.row.col.f32.f16.f16.f32 "
        "{%0,%1,%2,%3}, {%4,%5,%6,%7}, {%8,%9}, {%0,%1,%2,%3};"
        : "+f"(c[0]), "+f"(c[1]), "+f"(c[2]), "+f"(c[3])
        : "r"(a[0]), "r"(a[1]), "r"(a[2]), "r"(a[3]), "r"(b[0]), "r"(b[1]));
}
__device__ __forceinline__ uint32_t sw_addr(uint32_t base, int row, int ch) {
    uint32_t off = (uint32_t)(row*128 + ch*16);
    return base + (off ^ ((off >> 3) & 0x70u));
}
__device__ __forceinline__ uint32_t pack_h(float a, float b) {
    __half2 H(__float2half_rn(a), __float2half_rn(b));
    return *(uint32_t*)&H;
}

// ============ 128x128x64 GEMM core pieces (fp16, 2 CTAs/SM) =================
#define STG_SZ 32768

__device__ __forceinline__ void ld_stage128(uint32_t sb,
    const fp16* A, long lda, const fp16* B, long ldb,
    int m0, int n0, int k0, int tid)
{
    #pragma unroll
    for (int t = 0; t < 8; t++) {
        int i = tid + t*256;
        if (i < 1024) {                       // A: 128 rows x 128B
            int r = i >> 3, ch = i & 7;
            uint32_t off = (uint32_t)(r*128 + ch*16);
            uint32_t sw = off ^ ((off >> 3) & 0x70u);
            cpa16(sb + sw, A + (size_t)(m0 + r)*lda + k0 + ch*8);
        } else {                              // B: 128 rows x 128B
            int j = i - 1024;
            int r = j >> 3, ch = j & 7;
            uint32_t off = (uint32_t)(r*128 + ch*16);
            uint32_t sw = off ^ ((off >> 3) & 0x70u);
            cpa16(sb + 16384 + sw, B + (size_t)(n0 + r)*ldb + k0 + ch*8);
        }
    }
    CP_COMMIT();
}

__device__ __forceinline__ void gemm_mainloop(uint32_t sb0,
    const fp16* A, long lda, const fp16* B, long ldb,
    int m0, int n0, int K, int tid, float c[2][8][4])
{
    const int lane = tid & 31, wid = tid >> 5;
    const int wm = wid >> 1, wn = wid & 1;
    const int g8 = lane & 7, q = lane >> 3;

    const int nch = K >> 6;
    ld_stage128(sb0, A, lda, B, ldb, m0, n0, 0, tid);

    for (int cc = 0; cc < nch; cc++) {
        const int s = cc & 1;
        const uint32_t sbs = sb0 + s*STG_SZ;
        if (cc + 1 < nch) {
            ld_stage128(sb0 + (s^1)*STG_SZ, A, lda, B, ldb, m0, n0, (cc+1)*64, tid);
            asm volatile("cp.async.wait_group 1;" ::: "memory");
        } else {
            asm volatile("cp.async.wait_group 0;" ::: "memory");
        }
        __syncthreads();

        #pragma unroll
        for (int k16 = 0; k16 < 4; k16++) {
            uint32_t bh[8][2];
            #pragma unroll
            for (int nj = 0; nj < 4; nj++) {
                int row = wn*64 + nj*16 + g8 + ((q >> 1) << 3);
                int ch  = k16*2 + (q & 1);
                uint32_t r4[4];
                ldsm4(r4, sw_addr(sbs + 16384, row, ch));
                bh[2*nj][0] = r4[0]; bh[2*nj][1] = r4[1];
                bh[2*nj+1][0] = r4[2]; bh[2*nj+1][1] = r4[3];
            }
            #pragma unroll
            for (int mi = 0; mi < 2; mi++) {
                int row = wm*32 + mi*16 + g8 + ((q & 1) << 3);
                int ch  = k16*2 + (q >> 1);
                uint32_t ah4[4];
                ldsm4(ah4, sw_addr(sbs, row, ch));
                #pragma unroll
                for (int ni = 0; ni < 8; ni++)
                    mma16816h(c[mi][ni], ah4, bh[ni]);
            }
        }
        __syncthreads();
    }
}

__device__ __forceinline__ void epi_to_smem(float* smemf, int tid, float c[2][8][4])
{
    const int lane = tid & 31, wid = tid >> 5;
    const int wm = wid >> 1, wn = wid & 1;
    const int gid = lane >> 2, tig = lane & 3;
    #pragma unroll
    for (int mi = 0; mi < 2; mi++)
        #pragma unroll
        for (int ni = 0; ni < 8; ni++) {
            int r0 = wm*32 + mi*16 + gid;
            int col = wn*64 + ni*8 + tig*2;
            *(float2*)&smemf[r0*132 + col]     = make_float2(c[mi][ni][0], c[mi][ni][1]);
            *(float2*)&smemf[(r0+8)*132 + col] = make_float2(c[mi][ni][2], c[mi][ni][3]);
        }
}

// ---------------- fused QKV projection GEMM --------------------------------
// grid (48, 32): wsel = x>>4 (0=Q,1=K,2=V), n0 = (x&15)*128
// Q/K: fp16 tmp out (+bias).  V: bias + TRANSPOSED fp16 write into vt.
__global__ __launch_bounds__(256, 2) void gemm_qkv(
    const fp16* __restrict__ A, const fp16* __restrict__ wt,
    const float* __restrict__ bq, const float* __restrict__ bk, const float* __restrict__ bv,
    fp16* __restrict__ cq, fp16* __restrict__ ck, fp16* __restrict__ vt)
{
    extern __shared__ __align__(16) uint8_t dyns[];
    const int tid = threadIdx.x;
    uint32_t raw = smem_u32(dyns);
    uint32_t sb0 = (raw + 1023u) & ~1023u;
    uint32_t pad = sb0 - raw;

    const int wsel = blockIdx.x >> 4;
    const int n0 = (blockIdx.x & 15) * 128;
    const int m0 = blockIdx.y * 128;
    const fp16* B = wt + (size_t)wsel*DD*DD;

    float c[2][8][4];
    #pragma unroll
    for (int i = 0; i < 2; i++)
        #pragma unroll
        for (int j = 0; j < 8; j++)
            #pragma unroll
            for (int e = 0; e < 4; e++) c[i][j][e] = 0.f;

    gemm_mainloop(sb0, A, DD, B, DD, m0, n0, DD, tid, c);

    float* smemf = (float*)(dyns + pad);
    epi_to_smem(smemf, tid, c);
    __syncthreads();

    if (wsel < 2) {
        const float* bias = wsel ? bk : bq;
        fp16* Cf = wsel ? ck : cq;
        for (int v = tid; v < 4096; v += 256) {
            const int row = v >> 5, c4 = (v & 31) << 2;
            float4 val = *(const float4*)&smemf[row*132 + c4];
            const int gc = n0 + c4;
            val.x += bias[gc]; val.y += bias[gc+1]; val.z += bias[gc+2]; val.w += bias[gc+3];
            const size_t go = (size_t)(m0 + row)*DD + gc;
            *(uint32_t*)&Cf[go]   = pack_h(val.x, val.y);
            *(uint32_t*)&Cf[go+2] = pack_h(val.z, val.w);
        }
    } else {
        // V: transposed write. h, b constant per CTA; d = col, t = m0 + row.
        const int bb = m0 >> 11;              // m0 / TT
        const int t0 = m0 & (TT - 1);
        const int h  = n0 >> 7;
        fp16* vbase = vt + ((size_t)(bb*HH + h))*HD*TT;
        // 8192 half2 elements: idx -> d = idx>>6, row2 = (idx&63)*2
        for (int idx = tid; idx < 8192; idx += 256) {
            const int d = idx >> 6, row2 = (idx & 63) << 1;
            const float bvd = bv[n0 + d];
            float v0 = smemf[row2*132 + d] + bvd;
            float v1 = smemf[(row2+1)*132 + d] + bvd;
            *(uint32_t*)&vbase[(size_t)d*TT + t0 + row2] = pack_h(v0, v1);
        }
    }
}

// ---------------- generic GEMM (out-proj / gate) ---------------------------
// epi: 2 = fp32 + fp16 hi, 3 = gate
__global__ __launch_bounds__(256, 2) void gemm_h2(
    const fp16* __restrict__ A, const fp16* __restrict__ B,
    const float* __restrict__ bias, const float* __restrict__ mul,
    float* __restrict__ Cf, fp16* __restrict__ Ch, int epi)
{
    extern __shared__ __align__(16) uint8_t dyns[];
    const int tid = threadIdx.x;
    uint32_t raw = smem_u32(dyns);
    uint32_t sb0 = (raw + 1023u) & ~1023u;
    uint32_t pad = sb0 - raw;

    const int m0 = blockIdx.y * 128, n0 = blockIdx.x * 128;

    float c[2][8][4];
    #pragma unroll
    for (int i = 0; i < 2; i++)
        #pragma unroll
        for (int j = 0; j < 8; j++)
            #pragma unroll
            for (int e = 0; e < 4; e++) c[i][j][e] = 0.f;

    gemm_mainloop(sb0, A, DD, B, DD, m0, n0, DD, tid, c);

    float* smemf = (float*)(dyns + pad);
    epi_to_smem(smemf, tid, c);
    __syncthreads();

    for (int v = tid; v < 4096; v += 256) {
        const int row = v >> 5, c4 = (v & 31) << 2;
        float4 val = *(const float4*)&smemf[row*132 + c4];
        const int gc = n0 + c4;
        const size_t go = (size_t)(m0 + row)*DD + gc;
        val.x += bias[gc]; val.y += bias[gc+1]; val.z += bias[gc+2]; val.w += bias[gc+3];
        if (epi == 2) {
            *(float4*)&Cf[go] = val;
            *(uint32_t*)&Ch[go]   = pack_h(val.x, val.y);
            *(uint32_t*)&Ch[go+2] = pack_h(val.z, val.w);
        } else {  // gate
            const float4 m = *(const float4*)&mul[go];
            float4 o;
            o.x = m.x / (1.0f + __expf(-val.x));
            o.y = m.y / (1.0f + __expf(-val.y));
            o.z = m.z / (1.0f + __expf(-val.z));
            o.w = m.w / (1.0f + __expf(-val.w));
            *(float4*)&Cf[go] = o;
        }
    }
}

// ---------------- flash attention KV stage loader (plain fp16) -------------
__device__ __forceinline__ void flash_ldkv(uint32_t stg, int kc0,
    const fp16* K, const fp16* V, int tid)
{
    #pragma unroll
    for (int t = 0; t < 8; t++) {
        int i = tid + t*256;
        if (i < 1024) {
            int p = i >> 9, j = i & 511;
            int r = j >> 3, ch = j & 7;
            uint32_t off = (uint32_t)(r*128 + ch*16);
            uint32_t sw = off ^ ((off >> 3) & 0x70u);
            const fp16* src = K + (size_t)(kc0 + r)*DD + p*64 + ch*8;
            cpa16(stg + p*8192 + sw, src);
        } else {
            int j = i - 1024;
            int r = j >> 3, ch = j & 7;
            uint32_t off = (uint32_t)(r*128 + ch*16);
            uint32_t sw = off ^ ((off >> 3) & 0x70u);
            const fp16* src = V + (size_t)r*TT + kc0 + ch*8;
            cpa16(stg + 16384 + sw, src);
        }
    }
    CP_COMMIT();
}

// ---------------- fused flash attention (fp16 single-pass) -----------------
__global__ __launch_bounds__(256, 1) void flash_attn(
    const fp16* __restrict__ qq, const fp16* __restrict__ kk,
    const fp16* __restrict__ vt, fp16* __restrict__ ah)
{
    extern __shared__ __align__(16) uint8_t dyns[];
    const int tid = threadIdx.x;
    uint32_t raw = smem_u32(dyns);
    uint32_t sb0 = (raw + 1023u) & ~1023u;
    uint32_t pad = sb0 - raw;

    const int qt = blockIdx.x;
    const int bh = blockIdx.y;
    const int b = bh >> 4, h = bh & 15;

    const fp16* Q = qq + ((size_t)(b*TT) + qt*128)*DD + h*HD;
    const fp16* K = kk + (size_t)(b*TT)*DD + h*HD;
    const fp16* V = vt + (size_t)bh*HD*TT;

    const int lane = tid & 31, wid = tid >> 5;
    const int g8 = lane & 7, q2 = lane >> 3;
    const int gid = lane >> 2, tig = lane & 3;

    #pragma unroll
    for (int t = 0; t < 8; t++) {
        int i = tid + t*256;
        int pd = i >> 10, jj = i & 1023;
        int r = jj >> 3, ch = jj & 7;
        uint32_t off = (uint32_t)(r*128 + ch*16);
        uint32_t sw = off ^ ((off >> 3) & 0x70u);
        cpa16(sb0 + pd*16384 + sw, Q + (size_t)r*DD + pd*64 + ch*8);
    }
    CP_COMMIT();
    flash_ldkv(sb0 + 32768, 0,  K, V, tid);
    flash_ldkv(sb0 + 65536, 64, K, V, tid);

    float c_o[16][4];
    #pragma unroll
    for (int i = 0; i < 16; i++)
        #pragma unroll
        for (int e = 0; e < 4; e++) c_o[i][e] = 0.f;
    float m0 = -1e30f, m1 = -1e30f, l0 = 0.f, l1 = 0.f;

    for (int t = 0; t < 32; t++) {
        if (t < 31) asm volatile("cp.async.wait_group 1;" ::: "memory");
        else        asm volatile("cp.async.wait_group 0;" ::: "memory");
        __syncthreads();
        const uint32_t stg = sb0 + 32768 + (t & 1)*32768;

        float c_s[8][4];
        #pragma unroll
        for (int i = 0; i < 8; i++)
            #pragma unroll
            for (int e = 0; e < 4; e++) c_s[i][e] = 0.f;

        #pragma unroll
        for (int k16 = 0; k16 < 8; k16++) {
            const int pd = k16 >> 2;
            uint32_t qa = sw_addr(sb0 + pd*16384, wid*16 + g8 + ((q2 & 1) << 3),
                                  (k16 & 3)*2 + (q2 >> 1));
            uint32_t qah[4];
            ldsm4(qah, qa);
            uint32_t kbh[8][2];
            #pragma unroll
            for (int nj = 0; nj < 4; nj++) {
                uint32_t ka = sw_addr(stg + pd*8192, nj*16 + g8 + ((q2 >> 1) << 3),
                                      (k16 & 3)*2 + (q2 & 1));
                uint32_t r4[4];
                ldsm4(r4, ka);
                kbh[2*nj][0] = r4[0]; kbh[2*nj][1] = r4[1];
                kbh[2*nj+1][0] = r4[2]; kbh[2*nj+1][1] = r4[3];
            }
            #pragma unroll
            for (int nj = 0; nj < 8; nj++)
                mma16816h(c_s[nj], qah, kbh[nj]);
        }

        float tm0 = -1e30f, tm1 = -1e30f;
        #pragma unroll
        for (int nj = 0; nj < 8; nj++) {
            tm0 = fmaxf(tm0, fmaxf(c_s[nj][0], c_s[nj][1]));
            tm1 = fmaxf(tm1, fmaxf(c_s[nj][2], c_s[nj][3]));
        }
        tm0 = fmaxf(tm0, __shfl_xor_sync(0xffffffffu, tm0, 1));
        tm0 = fmaxf(tm0, __shfl_xor_sync(0xffffffffu, tm0, 2));
        tm1 = fmaxf(tm1, __shfl_xor_sync(0xffffffffu, tm1, 1));
        tm1 = fmaxf(tm1, __shfl_xor_sync(0xffffffffu, tm1, 2));
        const float mn0 = fmaxf(m0, tm0), mn1 = fmaxf(m1, tm1);
        const float a0 = __expf(m0 - mn0), a1 = __expf(m1 - mn1);
        float rs0 = 0.f, rs1 = 0.f;
        #pragma unroll
        for (int nj = 0; nj < 8; nj++) {
            c_s[nj][0] = __expf(c_s[nj][0] - mn0);
            c_s[nj][1] = __expf(c_s[nj][1] - mn0);
            c_s[nj][2] = __expf(c_s[nj][2] - mn1);
            c_s[nj][3] = __expf(c_s[nj][3] - mn1);
            rs0 += c_s[nj][0] + c_s[nj][1];
            rs1 += c_s[nj][2] + c_s[nj][3];
        }
        rs0 += __shfl_xor_sync(0xffffffffu, rs0, 1);
        rs0 += __shfl_xor_sync(0xffffffffu, rs0, 2);
        rs1 += __shfl_xor_sync(0xffffffffu, rs1, 1);
        rs1 += __shfl_xor_sync(0xffffffffu, rs1, 2);
        l0 = l0*a0 + rs0;  l1 = l1*a1 + rs1;
        m0 = mn0;          m1 = mn1;
        #pragma unroll
        for (int nb = 0; nb < 16; nb++) {
            c_o[nb][0] *= a0; c_o[nb][1] *= a0;
            c_o[nb][2] *= a1; c_o[nb][3] *= a1;
        }

        #pragma unroll
        for (int kb = 0; kb < 4; kb++) {
            uint32_t pah[4];
            pah[0] = pack_h(c_s[2*kb][0],   c_s[2*kb][1]);
            pah[1] = pack_h(c_s[2*kb][2],   c_s[2*kb][3]);
            pah[2] = pack_h(c_s[2*kb+1][0], c_s[2*kb+1][1]);
            pah[3] = pack_h(c_s[2*kb+1][2], c_s[2*kb+1][3]);
            #pragma unroll
            for (int nj2 = 0; nj2 < 8; nj2++) {
                uint32_t va = sw_addr(stg + 16384, nj2*16 + g8 + ((q2 >> 1) << 3),
                                      kb*2 + (q2 & 1));
                uint32_t vh4[4];
                ldsm4(vh4, va);
                uint32_t b0[2] = {vh4[0], vh4[1]}, b1[2] = {vh4[2], vh4[3]};
                mma16816h(c_o[2*nj2],   pah, b0);
                mma16816h(c_o[2*nj2+1], pah, b1);
            }
        }

        __syncthreads();
        if (t + 2 < 32)
            flash_ldkv(sb0 + 32768 + (t & 1)*32768, (t+2)*64, K, V, tid);
    }

    float* smemf = (float*)(dyns + pad);
    {
        const float r0i = 1.0f / l0, r1i = 1.0f / l1;
        const int row0 = wid*16 + gid, row1 = row0 + 8;
        #pragma unroll
        for (int nb = 0; nb < 16; nb++) {
            const int col = nb*8 + tig*2;
            smemf[row0*132 + col]     = c_o[nb][0]*r0i;
            smemf[row0*132 + col + 1] = c_o[nb][1]*r0i;
            smemf[row1*132 + col]     = c_o[nb][2]*r1i;
            smemf[row1*132 + col + 1] = c_o[nb][3]*r1i;
        }
    }
    __syncthreads();
    for (int v = tid; v < 4096; v += 256) {
        const int row = v >> 5, c4 = (v & 31) << 2;
        float4 val = *(const float4*)&smemf[row*132 + c4];
        const size_t go = ((size_t)(b*TT) + qt*128 + row)*DD + h*HD + c4;
        *(uint32_t*)&ah[go]   = pack_h(val.x, val.y);
        *(uint32_t*)&ah[go+2] = pack_h(val.z, val.w);
    }
}

// ---------------- elementwise convert: fp32 -> fp16 ------------------------
__global__ __launch_bounds__(256) void convert4h(const float* __restrict__ in,
    fp16* __restrict__ oh, int n4)
{
    int i = blockIdx.x*256 + threadIdx.x;
    if (i >= n4) return;
    float4 v = ((const float4*)in)[i];
    ((uint32_t*)oh)[i*2]   = pack_h(v.x, v.y);
    ((uint32_t*)oh)[i*2+1] = pack_h(v.z, v.w);
}

// ---------------- 5 weight transposes in one launch ------------------------
__global__ void transpose_h5(
    const float* __restrict__ w0, const float* __restrict__ w1,
    const float* __restrict__ w2, const float* __restrict__ w3,
    const float* __restrict__ w4, fp16* __restrict__ out)
{
    __shared__ float t[32][33];
    const int z = blockIdx.z;
    const float* in = (z == 0) ? w0 : (z == 1) ? w1 : (z == 2) ? w2 : (z == 3) ? w3 : w4;
    fp16* po = out + (size_t)z*DD*DD;
    const int r0 = blockIdx.y*32, c0 = blockIdx.x*32;
    const int tx = threadIdx.x, ty = threadIdx.y;
    #pragma unroll
    for (int i = 0; i < 32; i += 8)
        t[ty+i][tx] = in[(size_t)(r0+ty+i)*DD + c0+tx];
    __syncthreads();
    #pragma unroll
    for (int i = 0; i < 32; i += 8)
        po[(size_t)(c0+ty+i)*DD + r0 + tx] = __float2half_rn(t[tx][ty+i]);
}

// ---------------- fused rmsnorm + rope (Q & K, fp16 in, pair-processed) -----
__global__ __launch_bounds__(256) void rmsnorm_rope_qk(
    const fp16* __restrict__ inq, const fp16* __restrict__ ink,
    const float* __restrict__ gq, const float* __restrict__ gk,
    const float* __restrict__ cosp, const float* __restrict__ sinp,
    fp16* __restrict__ oq, fp16* __restrict__ ok)
{
    __shared__ float s[DD];
    __shared__ float red[8];
    const int isK = blockIdx.x >= MROWS;
    const int row = blockIdx.x - (isK ? MROWS : 0);
    const int t = row & (TT - 1);
    const fp16* p = (isK ? ink : inq) + (size_t)row * DD;
    const float* g = isK ? gk : gq;
    fp16* oh = (isK ? ok : oq) + (size_t)row * DD;
    const float scale = isK ? 1.0f : 0.08838834764831845f;
    const int tid = threadIdx.x;

    float ss = 0.f;
    #pragma unroll
    for (int i = 0; i < 4; i++) {
        const int j = tid + i*256;              // half2 index, 1024 per row
        const __half2 h2 = ((const __half2*)p)[j];
        const float2 f2 = __half22float2(h2);
        s[2*j] = f2.x; s[2*j+1] = f2.y;
        ss += f2.x*f2.x + f2.y*f2.y;
    }
    #pragma unroll
    for (int o = 16; o > 0; o >>= 1) ss += __shfl_xor_sync(0xffffffffu, ss, o);
    if ((tid & 31) == 0) red[tid >> 5] = ss;
    __syncthreads();
    float tot = red[0]+red[1]+red[2]+red[3]+red[4]+red[5]+red[6]+red[7];
    const float inv = rsqrtf(tot * (1.0f / (float)DD) + 1e-6f) * scale;

    #pragma unroll
    for (int i = 0; i < 4; i++) {
        const int pi = tid + i*256;             // rotary-pair index, 1024 per row
        const int pidx = pi & 63;
        const int base = (pi >> 6) * 128;
        const float x1 = s[base + pidx]      * inv * g[base + pidx];
        const float x2 = s[base + 64 + pidx] * inv * g[base + 64 + pidx];
        const float cs = cosp[t*64 + pidx], sn = sinp[t*64 + pidx];
        oh[base + pidx]      = __float2half_rn(x1*cs - sn*x2);
        oh[base + 64 + pidx] = __float2half_rn(x2*cs + sn*x1);
    }
}

// ---------------------------------------------------------------------------
extern "C" void kernel_launch(void* const* d_in, const int* in_sizes, int n_in,
                              void* d_out, int out_size)
{
    const float* x    = (const float*)d_in[0];
    const float* cosp = (const float*)d_in[1];
    const float* sinp = (const float*)d_in[2];
    const float* w0 = (const float*)d_in[3];
    const float* bq = (const float*)d_in[4];
    const float* w1 = (const float*)d_in[5];
    const float* bk = (const float*)d_in[6];
    const float* w2 = (const float*)d_in[7];
    const float* bv = (const float*)d_in[8];
    const float* gq = (const float*)d_in[9];
    const float* gk = (const float*)d_in[10];
    const float* w3 = (const float*)d_in[11];
    const float* bo = (const float*)d_in[12];
    const float* w4 = (const float*)d_in[13];
    const float* bg = (const float*)d_in[14];
    float* out = (float*)d_out;

    fp16 *xh, *wt, *tq, *tk, *qh, *kh, *vt, *ah, *oh;
    float *of;
    cudaGetSymbolAddress((void**)&xh, g_xh);
    cudaGetSymbolAddress((void**)&wt, g_wt);
    cudaGetSymbolAddress((void**)&tq, g_tq);
    cudaGetSymbolAddress((void**)&tk, g_tk);
    cudaGetSymbolAddress((void**)&qh, g_qh);
    cudaGetSymbolAddress((void**)&kh, g_kh);
    cudaGetSymbolAddress((void**)&vt, g_vt);
    cudaGetSymbolAddress((void**)&ah, g_ah);
    cudaGetSymbolAddress((void**)&of, g_of);
    cudaGetSymbolAddress((void**)&oh, g_oh);

    const int SMEMSZ  = 128*132*4 + 1024;         // 68608 -> 2 CTAs/SM
    const int SMEMF   = 32768 + 2*32768 + 1024;
    cudaFuncSetAttribute(gemm_qkv, cudaFuncAttributeMaxDynamicSharedMemorySize, SMEMSZ);
    cudaFuncSetAttribute(gemm_h2, cudaFuncAttributeMaxDynamicSharedMemorySize, SMEMSZ);
    cudaFuncSetAttribute(flash_attn, cudaFuncAttributeMaxDynamicSharedMemorySize, SMEMF);

    dim3 blk(256), tb(32, 8);

    // input + weight prep
    convert4h<<<(MROWS*DD/4 + 255)/256, blk>>>(x, xh, MROWS*DD/4);
    transpose_h5<<<dim3(64,64,5), tb>>>(w0, w1, w2, w3, w4, wt);

    // fused QKV projection: fp16 tmp for Q/K, direct transposed fp16 V
    gemm_qkv<<<dim3(48, MROWS/128), blk, SMEMSZ>>>(xh, wt, bq, bk, bv, tq, tk, vt);

    // rmsnorm+rope for Q and K (fp16 in/out, pair-processed)
    rmsnorm_rope_qk<<<2*MROWS, blk>>>(tq, tk, gq, gk, cosp, sinp, qh, kh);

    // fused attention (scale folded into q) -> plain fp16 attn
    flash_attn<<<dim3(16, 32), blk, SMEMF>>>(qh, kh, vt, ah);

    // out proj — fp32 + fp16-hi epilogue
    gemm_h2<<<dim3(16, MROWS/128), blk, SMEMSZ>>>(ah, wt + 3ULL*DD*DD,
        bo, nullptr, of, oh, 2);
    // gate: out = of * sigmoid(oh @ wg + bg)
    gemm_h2<<<dim3(16, MROWS/128), blk, SMEMSZ>>>(oh, wt + 4ULL*DD*DD,
        bg, of, out, nullptr, 3);
}

// round 17
// speedup vs baseline: 8.7045x; 1.0051x over previous
#include <cuda_runtime.h>
#include <cuda_bf16.h>
#include <cuda_fp16.h>
#include <cstdint>
#include <math.h>

#define BB 2
#define TT 2048
#define DD 2048
#define HH 16
#define HD 128
#define MROWS (BB*TT)     // 4096
#define NB (BB*HH)        // 32

typedef __half fp16;

// ---------------- scratch (device globals; allocation-free rule) ----------
__device__ fp16  g_xh[(size_t)MROWS*DD];                         // x plain fp16
__device__ fp16  g_wt[5ULL*DD*DD];                               // transposed fp16 weights
__device__ fp16  g_tq[(size_t)MROWS*DD];                         // q proj (fp16, pre-norm)
__device__ fp16  g_tk[(size_t)MROWS*DD];                         // k proj (fp16, pre-norm)
__device__ fp16  g_qh[(size_t)MROWS*DD];                         // Q plain fp16
__device__ fp16  g_kh[(size_t)MROWS*DD];                         // K plain fp16
__device__ fp16  g_vt[(size_t)NB*HD*TT];                         // v^T [b,h,d,t] fp16
__device__ fp16  g_ah[(size_t)MROWS*DD];                         // attn plain fp16
__device__ float g_of[(size_t)MROWS*DD];
__device__ fp16  g_oh[(size_t)MROWS*DD];

// ---------------- PTX helpers (plain sm_80+ PTX only) ---------------------
__device__ __forceinline__ uint32_t smem_u32(const void* p) {
    uint32_t a;
    asm("{ .reg .u64 t; cvta.to.shared.u64 t, %1; cvt.u32.u64 %0, t; }" : "=r"(a) : "l"(p));
    return a;
}
__device__ __forceinline__ void cpa16(uint32_t s, const void* g) {
    asm volatile("cp.async.cg.shared.global [%0], [%1], 16;" :: "r"(s), "l"(g));
}
#define CP_COMMIT()  asm volatile("cp.async.commit_group;" ::: "memory")

__device__ __forceinline__ void ldsm4(uint32_t* r, uint32_t a) {
    asm volatile("ldmatrix.sync.aligned.m8n8.x4.shared.b16 {%0,%1,%2,%3}, [%4];"
        : "=r"(r[0]), "=r"(r[1]), "=r"(r[2]), "=r"(r[3]) : "r"(a));
}
__device__ __forceinline__ void mma16816h(float* c, const uint32_t* a, const uint32_t* b) {
    asm volatile("mma.sync.aligned.m16n8k16.row.col.f32.f16.f16.f32 "
        "{%0,%1,%2,%3}, {%4,%5,%6,%7}, {%8,%9}, {%0,%1,%2,%3};"
        : "+f"(c[0]), "+f"(c[1]), "+f"(c[2]), "+f"(c[3])
        : "r"(a[0]), "r"(a[1]), "r"(a[2]), "r"(a[3]), "r"(b[0]), "r"(b[1]));
}
__device__ __forceinline__ uint32_t sw_addr(uint32_t base, int row, int ch) {
    uint32_t off = (uint32_t)(row*128 + ch*16);
    return base + (off ^ ((off >> 3) & 0x70u));
}
__device__ __forceinline__ uint32_t pack_h(float a, float b) {
    __half2 H(__float2half_rn(a), __float2half_rn(b));
    return *(uint32_t*)&H;
}

// ============ 128x128x64 GEMM core (fp16, 3-stage, 2 CTAs/SM) ==============
#define STG_SZ 32768

__device__ __forceinline__ void ld_stage128(uint32_t sb,
    const fp16* A, long lda, const fp16* B, long ldb,
    int m0, int n0, int k0, int tid)
{
    #pragma unroll
    for (int t = 0; t < 8; t++) {
        int i = tid + t*256;
        if (i < 1024) {                       // A: 128 rows x 128B
            int r = i >> 3, ch = i & 7;
            uint32_t off = (uint32_t)(r*128 + ch*16);
            uint32_t sw = off ^ ((off >> 3) & 0x70u);
            cpa16(sb + sw, A + (size_t)(m0 + r)*lda + k0 + ch*8);
        } else {                              // B: 128 rows x 128B
            int j = i - 1024;
            int r = j >> 3, ch = j & 7;
            uint32_t off = (uint32_t)(r*128 + ch*16);
            uint32_t sw = off ^ ((off >> 3) & 0x70u);
            cpa16(sb + 16384 + sw, B + (size_t)(n0 + r)*ldb + k0 + ch*8);
        }
    }
    CP_COMMIT();
}

// 3-stage mainloop, single __syncthreads per chunk.
// Per iter: wait(group cc) -> sync -> issue cc+2 -> MMAs(stage cc%3).
__device__ __forceinline__ void gemm_mainloop(uint32_t sb0,
    const fp16* A, long lda, const fp16* B, long ldb,
    int m0, int n0, int K, int tid, float c[2][8][4])
{
    const int lane = tid & 31, wid = tid >> 5;
    const int wm = wid >> 1, wn = wid & 1;
    const int g8 = lane & 7, q = lane >> 3;

    const int nch = K >> 6;
    ld_stage128(sb0,          A, lda, B, ldb, m0, n0, 0,  tid);
    ld_stage128(sb0 + STG_SZ, A, lda, B, ldb, m0, n0, 64, tid);

    int s = 0;
    for (int cc = 0; cc < nch; cc++) {
        if (cc < nch - 1) asm volatile("cp.async.wait_group 1;" ::: "memory");
        else              asm volatile("cp.async.wait_group 0;" ::: "memory");
        __syncthreads();
        if (cc + 2 < nch) {
            int s2 = s + 2; if (s2 >= 3) s2 -= 3;
            ld_stage128(sb0 + s2*STG_SZ, A, lda, B, ldb, m0, n0, (cc+2)*64, tid);
        }
        const uint32_t sbs = sb0 + s*STG_SZ;

        #pragma unroll
        for (int k16 = 0; k16 < 4; k16++) {
            uint32_t bh[8][2];
            #pragma unroll
            for (int nj = 0; nj < 4; nj++) {
                int row = wn*64 + nj*16 + g8 + ((q >> 1) << 3);
                int ch  = k16*2 + (q & 1);
                uint32_t r4[4];
                ldsm4(r4, sw_addr(sbs + 16384, row, ch));
                bh[2*nj][0] = r4[0]; bh[2*nj][1] = r4[1];
                bh[2*nj+1][0] = r4[2]; bh[2*nj+1][1] = r4[3];
            }
            #pragma unroll
            for (int mi = 0; mi < 2; mi++) {
                int row = wm*32 + mi*16 + g8 + ((q & 1) << 3);
                int ch  = k16*2 + (q >> 1);
                uint32_t ah4[4];
                ldsm4(ah4, sw_addr(sbs, row, ch));
                #pragma unroll
                for (int ni = 0; ni < 8; ni++)
                    mma16816h(c[mi][ni], ah4, bh[ni]);
            }
        }
        if (++s >= 3) s -= 3;
    }
    __syncthreads();   // stage smem now safe for epilogue reuse
}

__device__ __forceinline__ void epi_to_smem(float* smemf, int tid, float c[2][8][4])
{
    const int lane = tid & 31, wid = tid >> 5;
    const int wm = wid >> 1, wn = wid & 1;
    const int gid = lane >> 2, tig = lane & 3;
    #pragma unroll
    for (int mi = 0; mi < 2; mi++)
        #pragma unroll
        for (int ni = 0; ni < 8; ni++) {
            int r0 = wm*32 + mi*16 + gid;
            int col = wn*64 + ni*8 + tig*2;
            *(float2*)&smemf[r0*132 + col]     = make_float2(c[mi][ni][0], c[mi][ni][1]);
            *(float2*)&smemf[(r0+8)*132 + col] = make_float2(c[mi][ni][2], c[mi][ni][3]);
        }
}

// ---------------- fused QKV projection GEMM --------------------------------
__global__ __launch_bounds__(256, 2) void gemm_qkv(
    const fp16* __restrict__ A, const fp16* __restrict__ wt,
    const float* __restrict__ bq, const float* __restrict__ bk, const float* __restrict__ bv,
    fp16* __restrict__ cq, fp16* __restrict__ ck, fp16* __restrict__ vt)
{
    extern __shared__ __align__(16) uint8_t dyns[];
    const int tid = threadIdx.x;
    uint32_t raw = smem_u32(dyns);
    uint32_t sb0 = (raw + 1023u) & ~1023u;
    uint32_t pad = sb0 - raw;

    const int wsel = blockIdx.x >> 4;
    const int n0 = (blockIdx.x & 15) * 128;
    const int m0 = blockIdx.y * 128;
    const fp16* B = wt + (size_t)wsel*DD*DD;

    float c[2][8][4];
    #pragma unroll
    for (int i = 0; i < 2; i++)
        #pragma unroll
        for (int j = 0; j < 8; j++)
            #pragma unroll
            for (int e = 0; e < 4; e++) c[i][j][e] = 0.f;

    gemm_mainloop(sb0, A, DD, B, DD, m0, n0, DD, tid, c);

    float* smemf = (float*)(dyns + pad);
    epi_to_smem(smemf, tid, c);
    __syncthreads();

    if (wsel < 2) {
        const float* bias = wsel ? bk : bq;
        fp16* Cf = wsel ? ck : cq;
        for (int v = tid; v < 4096; v += 256) {
            const int row = v >> 5, c4 = (v & 31) << 2;
            float4 val = *(const float4*)&smemf[row*132 + c4];
            const int gc = n0 + c4;
            val.x += bias[gc]; val.y += bias[gc+1]; val.z += bias[gc+2]; val.w += bias[gc+3];
            const size_t go = (size_t)(m0 + row)*DD + gc;
            *(uint32_t*)&Cf[go]   = pack_h(val.x, val.y);
            *(uint32_t*)&Cf[go+2] = pack_h(val.z, val.w);
        }
    } else {
        const int bb = m0 >> 11;
        const int t0 = m0 & (TT - 1);
        const int h  = n0 >> 7;
        fp16* vbase = vt + ((size_t)(bb*HH + h))*HD*TT;
        for (int idx = tid; idx < 8192; idx += 256) {
            const int d = idx >> 6, row2 = (idx & 63) << 1;
            const float bvd = bv[n0 + d];
            float v0 = smemf[row2*132 + d] + bvd;
            float v1 = smemf[(row2+1)*132 + d] + bvd;
            *(uint32_t*)&vbase[(size_t)d*TT + t0 + row2] = pack_h(v0, v1);
        }
    }
}

// ---------------- generic GEMM (out-proj / gate) ---------------------------
__global__ __launch_bounds__(256, 2) void gemm_h2(
    const fp16* __restrict__ A, const fp16* __restrict__ B,
    const float* __restrict__ bias, const float* __restrict__ mul,
    float* __restrict__ Cf, fp16* __restrict__ Ch, int epi)
{
    extern __shared__ __align__(16) uint8_t dyns[];
    const int tid = threadIdx.x;
    uint32_t raw = smem_u32(dyns);
    uint32_t sb0 = (raw + 1023u) & ~1023u;
    uint32_t pad = sb0 - raw;

    const int m0 = blockIdx.y * 128, n0 = blockIdx.x * 128;

    float c[2][8][4];
    #pragma unroll
    for (int i = 0; i < 2; i++)
        #pragma unroll
        for (int j = 0; j < 8; j++)
            #pragma unroll
            for (int e = 0; e < 4; e++) c[i][j][e] = 0.f;

    gemm_mainloop(sb0, A, DD, B, DD, m0, n0, DD, tid, c);

    float* smemf = (float*)(dyns + pad);
    epi_to_smem(smemf, tid, c);
    __syncthreads();

    for (int v = tid; v < 4096; v += 256) {
        const int row = v >> 5, c4 = (v & 31) << 2;
        float4 val = *(const float4*)&smemf[row*132 + c4];
        const int gc = n0 + c4;
        const size_t go = (size_t)(m0 + row)*DD + gc;
        val.x += bias[gc]; val.y += bias[gc+1]; val.z += bias[gc+2]; val.w += bias[gc+3];
        if (epi == 2) {
            *(float4*)&Cf[go] = val;
            *(uint32_t*)&Ch[go]   = pack_h(val.x, val.y);
            *(uint32_t*)&Ch[go+2] = pack_h(val.z, val.w);
        } else {  // gate
            const float4 m = *(const float4*)&mul[go];
            float4 o;
            o.x = m.x / (1.0f + __expf(-val.x));
            o.y = m.y / (1.0f + __expf(-val.y));
            o.z = m.z / (1.0f + __expf(-val.z));
            o.w = m.w / (1.0f + __expf(-val.w));
            *(float4*)&Cf[go] = o;
        }
    }
}

// ---------------- flash attention KV stage loader (plain fp16) -------------
__device__ __forceinline__ void flash_ldkv(uint32_t stg, int kc0,
    const fp16* K, const fp16* V, int tid)
{
    #pragma unroll
    for (int t = 0; t < 8; t++) {
        int i = tid + t*256;
        if (i < 1024) {
            int p = i >> 9, j = i & 511;
            int r = j >> 3, ch = j & 7;
            uint32_t off = (uint32_t)(r*128 + ch*16);
            uint32_t sw = off ^ ((off >> 3) & 0x70u);
            const fp16* src = K + (size_t)(kc0 + r)*DD + p*64 + ch*8;
            cpa16(stg + p*8192 + sw, src);
        } else {
            int j = i - 1024;
            int r = j >> 3, ch = j & 7;
            uint32_t off = (uint32_t)(r*128 + ch*16);
            uint32_t sw = off ^ ((off >> 3) & 0x70u);
            const fp16* src = V + (size_t)r*TT + kc0 + ch*8;
            cpa16(stg + 16384 + sw, src);
        }
    }
    CP_COMMIT();
}

// ---------------- fused flash attention (fp16, 3-stage KV) -----------------
__global__ __launch_bounds__(256, 1) void flash_attn(
    const fp16* __restrict__ qq, const fp16* __restrict__ kk,
    const fp16* __restrict__ vt, fp16* __restrict__ ah)
{
    extern __shared__ __align__(16) uint8_t dyns[];
    const int tid = threadIdx.x;
    uint32_t raw = smem_u32(dyns);
    uint32_t sb0 = (raw + 1023u) & ~1023u;
    uint32_t pad = sb0 - raw;

    const int qt = blockIdx.x;
    const int bh = blockIdx.y;
    const int b = bh >> 4, h = bh & 15;

    const fp16* Q = qq + ((size_t)(b*TT) + qt*128)*DD + h*HD;
    const fp16* K = kk + (size_t)(b*TT)*DD + h*HD;
    const fp16* V = vt + (size_t)bh*HD*TT;

    const int lane = tid & 31, wid = tid >> 5;
    const int g8 = lane & 7, q2 = lane >> 3;
    const int gid = lane >> 2, tig = lane & 3;

    // Q: 2 panels of 16KB at sb0..32KB  (its cp.asyncs fold into group 0)
    #pragma unroll
    for (int t = 0; t < 8; t++) {
        int i = tid + t*256;
        int pd = i >> 10, jj = i & 1023;
        int r = jj >> 3, ch = jj & 7;
        uint32_t off = (uint32_t)(r*128 + ch*16);
        uint32_t sw = off ^ ((off >> 3) & 0x70u);
        cpa16(sb0 + pd*16384 + sw, Q + (size_t)r*DD + pd*64 + ch*8);
    }
    const uint32_t kvb = sb0 + 32768;
    flash_ldkv(kvb,            0,  K, V, tid);   // group 0 (with Q)
    flash_ldkv(kvb + STG_SZ,   64, K, V, tid);   // group 1

    float c_o[16][4];
    #pragma unroll
    for (int i = 0; i < 16; i++)
        #pragma unroll
        for (int e = 0; e < 4; e++) c_o[i][e] = 0.f;
    float m0 = -1e30f, m1 = -1e30f, l0 = 0.f, l1 = 0.f;

    int s = 0;
    for (int t = 0; t < 32; t++) {
        if (t < 31) asm volatile("cp.async.wait_group 1;" ::: "memory");
        else        asm volatile("cp.async.wait_group 0;" ::: "memory");
        __syncthreads();
        if (t + 2 < 32) {
            int s2 = s + 2; if (s2 >= 3) s2 -= 3;
            flash_ldkv(kvb + s2*STG_SZ, (t+2)*64, K, V, tid);
        }
        const uint32_t stg = kvb + s*STG_SZ;

        // ---- S = Q @ K^T (128 x 64, single-pass) ----
        float c_s[8][4];
        #pragma unroll
        for (int i = 0; i < 8; i++)
            #pragma unroll
            for (int e = 0; e < 4; e++) c_s[i][e] = 0.f;

        #pragma unroll
        for (int k16 = 0; k16 < 8; k16++) {
            const int pd = k16 >> 2;
            uint32_t qa = sw_addr(sb0 + pd*16384, wid*16 + g8 + ((q2 & 1) << 3),
                                  (k16 & 3)*2 + (q2 >> 1));
            uint32_t qah[4];
            ldsm4(qah, qa);
            uint32_t kbh[8][2];
            #pragma unroll
            for (int nj = 0; nj < 4; nj++) {
                uint32_t ka = sw_addr(stg + pd*8192, nj*16 + g8 + ((q2 >> 1) << 3),
                                      (k16 & 3)*2 + (q2 & 1));
                uint32_t r4[4];
                ldsm4(r4, ka);
                kbh[2*nj][0] = r4[0]; kbh[2*nj][1] = r4[1];
                kbh[2*nj+1][0] = r4[2]; kbh[2*nj+1][1] = r4[3];
            }
            #pragma unroll
            for (int nj = 0; nj < 8; nj++)
                mma16816h(c_s[nj], qah, kbh[nj]);
        }

        // ---- online softmax ----
        float tm0 = -1e30f, tm1 = -1e30f;
        #pragma unroll
        for (int nj = 0; nj < 8; nj++) {
            tm0 = fmaxf(tm0, fmaxf(c_s[nj][0], c_s[nj][1]));
            tm1 = fmaxf(tm1, fmaxf(c_s[nj][2], c_s[nj][3]));
        }
        tm0 = fmaxf(tm0, __shfl_xor_sync(0xffffffffu, tm0, 1));
        tm0 = fmaxf(tm0, __shfl_xor_sync(0xffffffffu, tm0, 2));
        tm1 = fmaxf(tm1, __shfl_xor_sync(0xffffffffu, tm1, 1));
        tm1 = fmaxf(tm1, __shfl_xor_sync(0xffffffffu, tm1, 2));
        const float mn0 = fmaxf(m0, tm0), mn1 = fmaxf(m1, tm1);
        const float a0 = __expf(m0 - mn0), a1 = __expf(m1 - mn1);
        float rs0 = 0.f, rs1 = 0.f;
        #pragma unroll
        for (int nj = 0; nj < 8; nj++) {
            c_s[nj][0] = __expf(c_s[nj][0] - mn0);
            c_s[nj][1] = __expf(c_s[nj][1] - mn0);
            c_s[nj][2] = __expf(c_s[nj][2] - mn1);
            c_s[nj][3] = __expf(c_s[nj][3] - mn1);
            rs0 += c_s[nj][0] + c_s[nj][1];
            rs1 += c_s[nj][2] + c_s[nj][3];
        }
        rs0 += __shfl_xor_sync(0xffffffffu, rs0, 1);
        rs0 += __shfl_xor_sync(0xffffffffu, rs0, 2);
        rs1 += __shfl_xor_sync(0xffffffffu, rs1, 1);
        rs1 += __shfl_xor_sync(0xffffffffu, rs1, 2);
        l0 = l0*a0 + rs0;  l1 = l1*a1 + rs1;
        m0 = mn0;          m1 = mn1;
        #pragma unroll
        for (int nb = 0; nb < 16; nb++) {
            c_o[nb][0] *= a0; c_o[nb][1] *= a0;
            c_o[nb][2] *= a1; c_o[nb][3] *= a1;
        }

        // ---- O += P @ V ----
        #pragma unroll
        for (int kb = 0; kb < 4; kb++) {
            uint32_t pah[4];
            pah[0] = pack_h(c_s[2*kb][0],   c_s[2*kb][1]);
            pah[1] = pack_h(c_s[2*kb][2],   c_s[2*kb][3]);
            pah[2] = pack_h(c_s[2*kb+1][0], c_s[2*kb+1][1]);
            pah[3] = pack_h(c_s[2*kb+1][2], c_s[2*kb+1][3]);
            #pragma unroll
            for (int nj2 = 0; nj2 < 8; nj2++) {
                uint32_t va = sw_addr(stg + 16384, nj2*16 + g8 + ((q2 >> 1) << 3),
                                      kb*2 + (q2 & 1));
                uint32_t vh4[4];
                ldsm4(vh4, va);
                uint32_t b0[2] = {vh4[0], vh4[1]}, b1[2] = {vh4[2], vh4[3]};
                mma16816h(c_o[2*nj2],   pah, b0);
                mma16816h(c_o[2*nj2+1], pah, b1);
            }
        }
        if (++s >= 3) s -= 3;
    }
    __syncthreads();   // all warps done with stage smem before epilogue reuse

    float* smemf = (float*)(dyns + pad);
    {
        const float r0i = 1.0f / l0, r1i = 1.0f / l1;
        const int row0 = wid*16 + gid, row1 = row0 + 8;
        #pragma unroll
        for (int nb = 0; nb < 16; nb++) {
            const int col = nb*8 + tig*2;
            smemf[row0*132 + col]     = c_o[nb][0]*r0i;
            smemf[row0*132 + col + 1] = c_o[nb][1]*r0i;
            smemf[row1*132 + col]     = c_o[nb][2]*r1i;
            smemf[row1*132 + col + 1] = c_o[nb][3]*r1i;
        }
    }
    __syncthreads();
    for (int v = tid; v < 4096; v += 256) {
        const int row = v >> 5, c4 = (v & 31) << 2;
        float4 val = *(const float4*)&smemf[row*132 + c4];
        const size_t go = ((size_t)(b*TT) + qt*128 + row)*DD + h*HD + c4;
        *(uint32_t*)&ah[go]   = pack_h(val.x, val.y);
        *(uint32_t*)&ah[go+2] = pack_h(val.z, val.w);
    }
}

// ---------------- elementwise convert: fp32 -> fp16 ------------------------
__global__ __launch_bounds__(256) void convert4h(const float* __restrict__ in,
    fp16* __restrict__ oh, int n4)
{
    int i = blockIdx.x*256 + threadIdx.x;
    if (i >= n4) return;
    float4 v = ((const float4*)in)[i];
    ((uint32_t*)oh)[i*2]   = pack_h(v.x, v.y);
    ((uint32_t*)oh)[i*2+1] = pack_h(v.z, v.w);
}

// ---------------- 5 weight transposes in one launch ------------------------
__global__ void transpose_h5(
    const float* __restrict__ w0, const float* __restrict__ w1,
    const float* __restrict__ w2, const float* __restrict__ w3,
    const float* __restrict__ w4, fp16* __restrict__ out)
{
    __shared__ float t[32][33];
    const int z = blockIdx.z;
    const float* in = (z == 0) ? w0 : (z == 1) ? w1 : (z == 2) ? w2 : (z == 3) ? w3 : w4;
    fp16* po = out + (size_t)z*DD*DD;
    const int r0 = blockIdx.y*32, c0 = blockIdx.x*32;
    const int tx = threadIdx.x, ty = threadIdx.y;
    #pragma unroll
    for (int i = 0; i < 32; i += 8)
        t[ty+i][tx] = in[(size_t)(r0+ty+i)*DD + c0+tx];
    __syncthreads();
    #pragma unroll
    for (int i = 0; i < 32; i += 8)
        po[(size_t)(c0+ty+i)*DD + r0 + tx] = __float2half_rn(t[tx][ty+i]);
}

// ---------------- fused rmsnorm + rope (Q & K, fp16 in, pair-processed) -----
__global__ __launch_bounds__(256) void rmsnorm_rope_qk(
    const fp16* __restrict__ inq, const fp16* __restrict__ ink,
    const float* __restrict__ gq, const float* __restrict__ gk,
    const float* __restrict__ cosp, const float* __restrict__ sinp,
    fp16* __restrict__ oq, fp16* __restrict__ ok)
{
    __shared__ float s[DD];
    __shared__ float red[8];
    const int isK = blockIdx.x >= MROWS;
    const int row = blockIdx.x - (isK ? MROWS : 0);
    const int t = row & (TT - 1);
    const fp16* p = (isK ? ink : inq) + (size_t)row * DD;
    const float* g = isK ? gk : gq;
    fp16* oh = (isK ? ok : oq) + (size_t)row * DD;
    const float scale = isK ? 1.0f : 0.08838834764831845f;
    const int tid = threadIdx.x;

    float ss = 0.f;
    #pragma unroll
    for (int i = 0; i < 4; i++) {
        const int j = tid + i*256;
        const __half2 h2 = ((const __half2*)p)[j];
        const float2 f2 = __half22float2(h2);
        s[2*j] = f2.x; s[2*j+1] = f2.y;
        ss += f2.x*f2.x + f2.y*f2.y;
    }
    #pragma unroll
    for (int o = 16; o > 0; o >>= 1) ss += __shfl_xor_sync(0xffffffffu, ss, o);
    if ((tid & 31) == 0) red[tid >> 5] = ss;
    __syncthreads();
    float tot = red[0]+red[1]+red[2]+red[3]+red[4]+red[5]+red[6]+red[7];
    const float inv = rsqrtf(tot * (1.0f / (float)DD) + 1e-6f) * scale;

    #pragma unroll
    for (int i = 0; i < 4; i++) {
        const int pi = tid + i*256;
        const int pidx = pi & 63;
        const int base = (pi >> 6) * 128;
        const float x1 = s[base + pidx]      * inv * g[base + pidx];
        const float x2 = s[base + 64 + pidx] * inv * g[base + 64 + pidx];
        const float cs = cosp[t*64 + pidx], sn = sinp[t*64 + pidx];
        oh[base + pidx]      = __float2half_rn(x1*cs - sn*x2);
        oh[base + 64 + pidx] = __float2half_rn(x2*cs + sn*x1);
    }
}

// ---------------------------------------------------------------------------
extern "C" void kernel_launch(void* const* d_in, const int* in_sizes, int n_in,
                              void* d_out, int out_size)
{
    const float* x    = (const float*)d_in[0];
    const float* cosp = (const float*)d_in[1];
    const float* sinp = (const float*)d_in[2];
    const float* w0 = (const float*)d_in[3];
    const float* bq = (const float*)d_in[4];
    const float* w1 = (const float*)d_in[5];
    const float* bk = (const float*)d_in[6];
    const float* w2 = (const float*)d_in[7];
    const float* bv = (const float*)d_in[8];
    const float* gq = (const float*)d_in[9];
    const float* gk = (const float*)d_in[10];
    const float* w3 = (const float*)d_in[11];
    const float* bo = (const float*)d_in[12];
    const float* w4 = (const float*)d_in[13];
    const float* bg = (const float*)d_in[14];
    float* out = (float*)d_out;

    fp16 *xh, *wt, *tq, *tk, *qh, *kh, *vt, *ah, *oh;
    float *of;
    cudaGetSymbolAddress((void**)&xh, g_xh);
    cudaGetSymbolAddress((void**)&wt, g_wt);
    cudaGetSymbolAddress((void**)&tq, g_tq);
    cudaGetSymbolAddress((void**)&tk, g_tk);
    cudaGetSymbolAddress((void**)&qh, g_qh);
    cudaGetSymbolAddress((void**)&kh, g_kh);
    cudaGetSymbolAddress((void**)&vt, g_vt);
    cudaGetSymbolAddress((void**)&ah, g_ah);
    cudaGetSymbolAddress((void**)&of, g_of);
    cudaGetSymbolAddress((void**)&oh, g_oh);

    // gemm: dyn smem = max(3 x 32KB stages, epilogue 128x132 fp32) + pad
    const int SMEMSZ  = 3*STG_SZ + 1024;          // 99328 -> 2 CTAs/SM
    const int SMEMF   = 32768 + 3*STG_SZ + 1024;  // flash: Q 32KB + 3 stages
    cudaFuncSetAttribute(gemm_qkv, cudaFuncAttributeMaxDynamicSharedMemorySize, SMEMSZ);
    cudaFuncSetAttribute(gemm_h2, cudaFuncAttributeMaxDynamicSharedMemorySize, SMEMSZ);
    cudaFuncSetAttribute(flash_attn, cudaFuncAttributeMaxDynamicSharedMemorySize, SMEMF);

    dim3 blk(256), tb(32, 8);

    // input + weight prep
    convert4h<<<(MROWS*DD/4 + 255)/256, blk>>>(x, xh, MROWS*DD/4);
    transpose_h5<<<dim3(64,64,5), tb>>>(w0, w1, w2, w3, w4, wt);

    // fused QKV projection: fp16 tmp for Q/K, direct transposed fp16 V
    gemm_qkv<<<dim3(48, MROWS/128), blk, SMEMSZ>>>(xh, wt, bq, bk, bv, tq, tk, vt);

    // rmsnorm+rope for Q and K (fp16 in/out, pair-processed)
    rmsnorm_rope_qk<<<2*MROWS, blk>>>(tq, tk, gq, gk, cosp, sinp, qh, kh);

    // fused attention (scale folded into q) -> plain fp16 attn
    flash_attn<<<dim3(16, 32), blk, SMEMF>>>(qh, kh, vt, ah);

    // out proj — fp32 + fp16-hi epilogue
    gemm_h2<<<dim3(16, MROWS/128), blk, SMEMSZ>>>(ah, wt + 3ULL*DD*DD,
        bo, nullptr, of, oh, 2);
    // gate: out = of * sigmoid(oh @ wg + bg)
    gemm_h2<<<dim3(16, MROWS/128), blk, SMEMSZ>>>(oh, wt + 4ULL*DD*DD,
        bg, of, out, nullptr, 3);
}